// round 1
// baseline (speedup 1.0000x reference)
#include <cuda_runtime.h>
#include <cstddef>

// Problem constants (fixed shapes from setup_inputs)
#define BATCH 2
#define SEQ   2048
#define CDIM  1024
#define NHEAD 16
#define HDIM  64
#define MROWS (BATCH * SEQ)          // 4096
#define QKVC  (3 * CDIM)             // 3072

// Scratch (allocation-free rule: __device__ globals)
__device__ float g_qkv [ (size_t)MROWS * QKVC ];   // 48 MB
__device__ float g_attn[ (size_t)MROWS * CDIM ];   // 16 MB

// ---------------------------------------------------------------------------
// SGEMM: C[M,N] = A[M,K] @ B[K,N] + bias[N]   (all row-major, fp32)
// 128x128 block tile, 8x8 thread tile, BK=8, double-buffered smem.
// ---------------------------------------------------------------------------
__global__ __launch_bounds__(256) void sgemm_bias_kernel(
    const float* __restrict__ A, const float* __restrict__ B,
    const float* __restrict__ bias, float* __restrict__ C,
    int M, int N, int K)
{
    const int BM = 128, BN = 128, BK = 8;
    __shared__ float As[2][BK][BM];
    __shared__ float Bs[2][BK][BN];

    const int tid = threadIdx.x;
    const int tx = tid & 15;          // 0..15 -> N direction
    const int ty = tid >> 4;          // 0..15 -> M direction
    const int row0 = blockIdx.y * BM;
    const int col0 = blockIdx.x * BN;

    // Global load mapping
    const int aRow = tid >> 1;              // 0..127
    const int aCol = (tid & 1) << 2;        // 0 or 4
    const int bRow = tid >> 5;              // 0..7
    const int bCol = (tid & 31) << 2;       // 0..124

    const float* Aptr = A + (size_t)(row0 + aRow) * K + aCol;
    const float* Bptr = B + (size_t)bRow * N + col0 + bCol;

    float4 aReg = *(const float4*)Aptr;
    float4 bReg = *(const float4*)Bptr;

    float acc[8][8];
    #pragma unroll
    for (int i = 0; i < 8; ++i)
        #pragma unroll
        for (int j = 0; j < 8; ++j) acc[i][j] = 0.f;

    const int nIters = K / BK;
    int buf = 0;
    for (int it = 0; it < nIters; ++it) {
        // commit prefetched regs to smem
        As[buf][aCol + 0][aRow] = aReg.x;
        As[buf][aCol + 1][aRow] = aReg.y;
        As[buf][aCol + 2][aRow] = aReg.z;
        As[buf][aCol + 3][aRow] = aReg.w;
        *(float4*)&Bs[buf][bRow][bCol] = bReg;
        __syncthreads();

        if (it + 1 < nIters) {
            aReg = *(const float4*)(Aptr + (it + 1) * BK);
            bReg = *(const float4*)(Bptr + (size_t)(it + 1) * BK * N);
        }

        #pragma unroll
        for (int k = 0; k < BK; ++k) {
            float a[8], b[8];
            *(float4*)&a[0] = *(const float4*)&As[buf][k][ty * 8];
            *(float4*)&a[4] = *(const float4*)&As[buf][k][ty * 8 + 4];
            *(float4*)&b[0] = *(const float4*)&Bs[buf][k][tx * 8];
            *(float4*)&b[4] = *(const float4*)&Bs[buf][k][tx * 8 + 4];
            #pragma unroll
            for (int i = 0; i < 8; ++i)
                #pragma unroll
                for (int j = 0; j < 8; ++j)
                    acc[i][j] += a[i] * b[j];
        }
        buf ^= 1;
    }

    // epilogue: add bias, store
    float bj[8];
    #pragma unroll
    for (int j = 0; j < 8; ++j) bj[j] = bias[col0 + tx * 8 + j];

    #pragma unroll
    for (int i = 0; i < 8; ++i) {
        const size_t row = (size_t)(row0 + ty * 8 + i);
        float* cp = C + row * N + col0 + tx * 8;
        #pragma unroll
        for (int j = 0; j < 8; j += 4) {
            float4 o;
            o.x = acc[i][j + 0] + bj[j + 0];
            o.y = acc[i][j + 1] + bj[j + 1];
            o.z = acc[i][j + 2] + bj[j + 2];
            o.w = acc[i][j + 3] + bj[j + 3];
            *(float4*)(cp + j) = o;
        }
    }
}

// ---------------------------------------------------------------------------
// RoPE: in-place on q (offset 0) and k (offset CDIM) of each qkv row.
// One thread per (row m, head h, d in [0,32)).
// ---------------------------------------------------------------------------
__global__ void rope_kernel(float* __restrict__ qkv)
{
    const int total = MROWS * NHEAD * 32;
    int idx = blockIdx.x * blockDim.x + threadIdx.x;
    if (idx >= total) return;
    const int d = idx & 31;
    const int h = (idx >> 5) & (NHEAD - 1);
    const int m = idx >> 9;                  // 0..4095
    const int t = m & (SEQ - 1);

    // inv_freq = 10000^{-d/32};  log2(10000) = 13.287712379549449
    const float inv_freq = exp2f((float)d * (-13.2877123795494493f / 32.0f));
    const float ang = (float)t * inv_freq;
    float s, c;
    sincosf(ang, &s, &c);

    float* base = qkv + (size_t)m * QKVC + h * HDIM + d;
    const float q1 = base[0],  q2 = base[32];
    base[0]  = q1 * c - q2 * s;
    base[32] = q2 * c + q1 * s;

    float* kb = base + CDIM;
    const float k1 = kb[0], k2 = kb[32];
    kb[0]  = k1 * c - k2 * s;
    kb[32] = k2 * c + k1 * s;
}

// ---------------------------------------------------------------------------
// Attention: flash-style online softmax.
// grid = (SEQ/128, BATCH*NHEAD), block = 128 threads, 1 query per thread.
// q row + 64-wide accumulator in registers; K/V tiles (64 keys) in smem,
// read as warp-broadcast LDS.128.
// ---------------------------------------------------------------------------
#define AT_BM 128
#define AT_BN 64

__global__ __launch_bounds__(AT_BM) void attn_kernel(
    const float* __restrict__ qkv, float* __restrict__ out)
{
    const int bh = blockIdx.y;
    const int b  = bh >> 4;
    const int h  = bh & 15;
    const int q0 = blockIdx.x * AT_BM;
    const int tid = threadIdx.x;

    __shared__ float sK[AT_BN][HDIM];
    __shared__ float sV[AT_BN][HDIM];

    // load this thread's query row into registers
    float q[HDIM];
    {
        const float* qptr = qkv + (size_t)(b * SEQ + q0 + tid) * QKVC + h * HDIM;
        #pragma unroll
        for (int d = 0; d < HDIM; d += 4) {
            float4 v = *(const float4*)(qptr + d);
            q[d] = v.x; q[d + 1] = v.y; q[d + 2] = v.z; q[d + 3] = v.w;
        }
    }

    float acc[HDIM];
    #pragma unroll
    for (int d = 0; d < HDIM; ++d) acc[d] = 0.f;
    float mrun = -1e30f, lrun = 0.f;
    const float scale = 0.125f;   // 1/sqrt(64)

    for (int k0 = 0; k0 < SEQ; k0 += AT_BN) {
        __syncthreads();
        // cooperative load of K and V tiles (coalesced float4)
        #pragma unroll
        for (int e = tid; e < AT_BN * (HDIM / 4); e += AT_BM) {
            const int r  = e >> 4;
            const int d4 = (e & 15) << 2;
            const size_t base = (size_t)(b * SEQ + k0 + r) * QKVC + h * HDIM + d4;
            *(float4*)&sK[r][d4] = *(const float4*)(qkv + base + CDIM);
            *(float4*)&sV[r][d4] = *(const float4*)(qkv + base + 2 * CDIM);
        }
        __syncthreads();

        for (int kn = 0; kn < AT_BN; kn += 4) {
            // 4 independent score chains for ILP
            float s0 = 0.f, s1 = 0.f, s2 = 0.f, s3 = 0.f;
            #pragma unroll
            for (int d = 0; d < HDIM; d += 4) {
                float4 k0v = *(const float4*)&sK[kn + 0][d];
                float4 k1v = *(const float4*)&sK[kn + 1][d];
                float4 k2v = *(const float4*)&sK[kn + 2][d];
                float4 k3v = *(const float4*)&sK[kn + 3][d];
                s0 += q[d]*k0v.x + q[d+1]*k0v.y + q[d+2]*k0v.z + q[d+3]*k0v.w;
                s1 += q[d]*k1v.x + q[d+1]*k1v.y + q[d+2]*k1v.z + q[d+3]*k1v.w;
                s2 += q[d]*k2v.x + q[d+1]*k2v.y + q[d+2]*k2v.z + q[d+3]*k2v.w;
                s3 += q[d]*k3v.x + q[d+1]*k3v.y + q[d+2]*k3v.z + q[d+3]*k3v.w;
            }
            s0 *= scale; s1 *= scale; s2 *= scale; s3 *= scale;

            const float mn = fmaxf(fmaxf(s0, s1), fmaxf(s2, s3));
            if (mn > mrun) {                 // rare rescale
                const float corr = __expf(mrun - mn);
                lrun *= corr;
                #pragma unroll
                for (int d = 0; d < HDIM; ++d) acc[d] *= corr;
                mrun = mn;
            }
            const float p0 = __expf(s0 - mrun);
            const float p1 = __expf(s1 - mrun);
            const float p2 = __expf(s2 - mrun);
            const float p3 = __expf(s3 - mrun);
            lrun += (p0 + p1) + (p2 + p3);

            #pragma unroll
            for (int d = 0; d < HDIM; d += 4) {
                float4 v0 = *(const float4*)&sV[kn + 0][d];
                float4 v1 = *(const float4*)&sV[kn + 1][d];
                float4 v2 = *(const float4*)&sV[kn + 2][d];
                float4 v3 = *(const float4*)&sV[kn + 3][d];
                acc[d+0] += p0*v0.x + p1*v1.x + p2*v2.x + p3*v3.x;
                acc[d+1] += p0*v0.y + p1*v1.y + p2*v2.y + p3*v3.y;
                acc[d+2] += p0*v0.z + p1*v1.z + p2*v2.z + p3*v3.z;
                acc[d+3] += p0*v0.w + p1*v1.w + p2*v2.w + p3*v3.w;
            }
        }
    }

    const float inv = 1.0f / lrun;
    float* op = out + (size_t)(b * SEQ + q0 + tid) * CDIM + h * HDIM;
    #pragma unroll
    for (int d = 0; d < HDIM; d += 4) {
        float4 o;
        o.x = acc[d+0] * inv; o.y = acc[d+1] * inv;
        o.z = acc[d+2] * inv; o.w = acc[d+3] * inv;
        *(float4*)(op + d) = o;
    }
}

// ---------------------------------------------------------------------------
// Launch
// ---------------------------------------------------------------------------
extern "C" void kernel_launch(void* const* d_in, const int* in_sizes, int n_in,
                              void* d_out, int out_size)
{
    const float* x    = (const float*)d_in[0];
    const float* Wqkv = (const float*)d_in[1];
    const float* bqkv = (const float*)d_in[2];
    const float* Wout = (const float*)d_in[3];
    const float* bout = (const float*)d_in[4];
    float* out = (float*)d_out;

    float *qkv = nullptr, *attn = nullptr;
    cudaGetSymbolAddress((void**)&qkv,  g_qkv);
    cudaGetSymbolAddress((void**)&attn, g_attn);

    // 1) qkv = x @ Wqkv + bqkv
    sgemm_bias_kernel<<<dim3(QKVC / 128, MROWS / 128), 256>>>(
        x, Wqkv, bqkv, qkv, MROWS, QKVC, CDIM);

    // 2) RoPE in-place on q, k
    {
        const int total = MROWS * NHEAD * 32;
        rope_kernel<<<(total + 255) / 256, 256>>>(qkv);
    }

    // 3) attention
    attn_kernel<<<dim3(SEQ / AT_BM, BATCH * NHEAD), AT_BM>>>(qkv, attn);

    // 4) out = attn @ Wout + bout
    sgemm_bias_kernel<<<dim3(CDIM / 128, MROWS / 128), 256>>>(
        attn, Wout, bout, out, MROWS, CDIM, CDIM);
}

// round 3
// speedup vs baseline: 2.3362x; 2.3362x over previous
#include <cuda_runtime.h>
#include <cuda_fp16.h>
#include <cstdint>
#include <cstddef>

// Problem constants (fixed shapes from setup_inputs)
#define BATCH 2
#define SEQ   2048
#define CDIM  1024
#define NHEAD 16
#define HDIM  64
#define MROWS (BATCH * SEQ)          // 4096
#define QKVC  (3 * CDIM)             // 3072

// Scratch (allocation-free rule: __device__ globals)
__device__ float g_qkv [ (size_t)MROWS * QKVC ];   // 48 MB
__device__ float g_attn[ (size_t)MROWS * CDIM ];   // 16 MB
__device__ __half g_qb[(size_t)MROWS * CDIM];      // 8 MB, layout [b][h][t][d]
__device__ __half g_kb[(size_t)MROWS * CDIM];
__device__ __half g_vb[(size_t)MROWS * CDIM];

// ---------------------------------------------------------------------------
// SGEMM: C[M,N] = A[M,K] @ B[K,N] + bias[N]   (row-major fp32) -- unchanged R0
// ---------------------------------------------------------------------------
__global__ __launch_bounds__(256) void sgemm_bias_kernel(
    const float* __restrict__ A, const float* __restrict__ B,
    const float* __restrict__ bias, float* __restrict__ C,
    int M, int N, int K)
{
    const int BM = 128, BN = 128, BK = 8;
    __shared__ float As[2][BK][BM];
    __shared__ float Bs[2][BK][BN];

    const int tid = threadIdx.x;
    const int tx = tid & 15;
    const int ty = tid >> 4;
    const int row0 = blockIdx.y * BM;
    const int col0 = blockIdx.x * BN;

    const int aRow = tid >> 1;
    const int aCol = (tid & 1) << 2;
    const int bRow = tid >> 5;
    const int bCol = (tid & 31) << 2;

    const float* Aptr = A + (size_t)(row0 + aRow) * K + aCol;
    const float* Bptr = B + (size_t)bRow * N + col0 + bCol;

    float4 aReg = *(const float4*)Aptr;
    float4 bReg = *(const float4*)Bptr;

    float acc[8][8];
    #pragma unroll
    for (int i = 0; i < 8; ++i)
        #pragma unroll
        for (int j = 0; j < 8; ++j) acc[i][j] = 0.f;

    const int nIters = K / BK;
    int buf = 0;
    for (int it = 0; it < nIters; ++it) {
        As[buf][aCol + 0][aRow] = aReg.x;
        As[buf][aCol + 1][aRow] = aReg.y;
        As[buf][aCol + 2][aRow] = aReg.z;
        As[buf][aCol + 3][aRow] = aReg.w;
        *(float4*)&Bs[buf][bRow][bCol] = bReg;
        __syncthreads();

        if (it + 1 < nIters) {
            aReg = *(const float4*)(Aptr + (it + 1) * BK);
            bReg = *(const float4*)(Bptr + (size_t)(it + 1) * BK * N);
        }

        #pragma unroll
        for (int k = 0; k < BK; ++k) {
            float a[8], b[8];
            *(float4*)&a[0] = *(const float4*)&As[buf][k][ty * 8];
            *(float4*)&a[4] = *(const float4*)&As[buf][k][ty * 8 + 4];
            *(float4*)&b[0] = *(const float4*)&Bs[buf][k][tx * 8];
            *(float4*)&b[4] = *(const float4*)&Bs[buf][k][tx * 8 + 4];
            #pragma unroll
            for (int i = 0; i < 8; ++i)
                #pragma unroll
                for (int j = 0; j < 8; ++j)
                    acc[i][j] += a[i] * b[j];
        }
        buf ^= 1;
    }

    float bj[8];
    #pragma unroll
    for (int j = 0; j < 8; ++j) bj[j] = bias[col0 + tx * 8 + j];

    #pragma unroll
    for (int i = 0; i < 8; ++i) {
        const size_t row = (size_t)(row0 + ty * 8 + i);
        float* cp = C + row * N + col0 + tx * 8;
        #pragma unroll
        for (int j = 0; j < 8; j += 4) {
            float4 o;
            o.x = acc[i][j + 0] + bj[j + 0];
            o.y = acc[i][j + 1] + bj[j + 1];
            o.z = acc[i][j + 2] + bj[j + 2];
            o.w = acc[i][j + 3] + bj[j + 3];
            *(float4*)(cp + j) = o;
        }
    }
}

// ---------------------------------------------------------------------------
// RoPE + cast to fp16, scatter into [b][h][t][d] layout.
// Q additionally scaled by 1/sqrt(D) * log2(e) so softmax can use exp2.
// ---------------------------------------------------------------------------
__global__ void rope_cast_kernel(const float* __restrict__ qkv,
                                 __half* __restrict__ qb,
                                 __half* __restrict__ kb,
                                 __half* __restrict__ vb)
{
    const int total = MROWS * NHEAD * 32;
    int idx = blockIdx.x * blockDim.x + threadIdx.x;
    if (idx >= total) return;
    const int d = idx & 31;
    const int h = (idx >> 5) & (NHEAD - 1);
    const int m = idx >> 9;                  // 0..4095
    const int t = m & (SEQ - 1);
    const int b = m >> 11;

    const float inv_freq = exp2f((float)d * (-13.2877123795494493f / 32.0f));
    const float ang = (float)t * inv_freq;
    float s, c;
    sincosf(ang, &s, &c);

    const float QS = 0.125f * 1.4426950408889634f;  // 1/sqrt(64) * log2(e)

    const float* base = qkv + (size_t)m * QKVC + h * HDIM + d;
    const float q1 = base[0], q2 = base[32];
    const float k1 = base[CDIM], k2 = base[CDIM + 32];
    const float v1 = base[2 * CDIM], v2 = base[2 * CDIM + 32];

    const size_t ob = ((size_t)(b * NHEAD + h) * SEQ + t) * HDIM + d;
    qb[ob]      = __float2half((q1 * c - q2 * s) * QS);
    qb[ob + 32] = __float2half((q2 * c + q1 * s) * QS);
    kb[ob]      = __float2half(k1 * c - k2 * s);
    kb[ob + 32] = __float2half(k2 * c + k1 * s);
    vb[ob]      = __float2half(v1);
    vb[ob + 32] = __float2half(v2);
}

// ---------------------------------------------------------------------------
// fp16 flash attention with mma.sync (m16n8k16) + ldmatrix + cp.async
// ---------------------------------------------------------------------------
__device__ __forceinline__ uint32_t sw_off(int row, int col) {
    return (uint32_t)(row * 64 + ((((col >> 3) ^ (row & 7)) << 3) | (col & 7)));
}
__device__ __forceinline__ void ldm_x4(uint32_t& r0, uint32_t& r1,
                                       uint32_t& r2, uint32_t& r3, uint32_t a) {
    asm volatile("ldmatrix.sync.aligned.m8n8.x4.shared.b16 {%0,%1,%2,%3}, [%4];"
                 : "=r"(r0), "=r"(r1), "=r"(r2), "=r"(r3) : "r"(a));
}
__device__ __forceinline__ void ldm_x4_t(uint32_t& r0, uint32_t& r1,
                                         uint32_t& r2, uint32_t& r3, uint32_t a) {
    asm volatile("ldmatrix.sync.aligned.m8n8.x4.trans.shared.b16 {%0,%1,%2,%3}, [%4];"
                 : "=r"(r0), "=r"(r1), "=r"(r2), "=r"(r3) : "r"(a));
}
__device__ __forceinline__ void mma16816(float* c, const uint32_t* a,
                                         uint32_t b0, uint32_t b1) {
    asm volatile(
        "mma.sync.aligned.m16n8k16.row.col.f32.f16.f16.f32 "
        "{%0,%1,%2,%3}, {%4,%5,%6,%7}, {%8,%9}, {%0,%1,%2,%3};"
        : "+f"(c[0]), "+f"(c[1]), "+f"(c[2]), "+f"(c[3])
        : "r"(a[0]), "r"(a[1]), "r"(a[2]), "r"(a[3]), "r"(b0), "r"(b1));
}
__device__ __forceinline__ float ex2f(float x) {
    float r;
    asm("ex2.approx.ftz.f32 %0, %1;" : "=f"(r) : "f"(x));
    return r;
}
__device__ __forceinline__ void cp16(uint32_t dst, const void* src) {
    asm volatile("cp.async.cg.shared.global [%0], [%1], 16;" :: "r"(dst), "l"(src));
}

#define FA_BM 128
#define FA_BN 64
#define FA_TILES (SEQ / FA_BN)   // 32

__global__ __launch_bounds__(256) void fa_kernel(
    const __half* __restrict__ Q, const __half* __restrict__ K,
    const __half* __restrict__ V, float* __restrict__ out)
{
    const int bh = blockIdx.y;
    const int b  = bh >> 4;
    const int h  = bh & 15;
    const int q0 = blockIdx.x * FA_BM;
    const int tid  = threadIdx.x;
    const int lane = tid & 31;
    const int wid  = tid >> 5;

    __shared__ __half sQ[FA_BM * HDIM];        // 16 KB
    __shared__ __half sK[2][FA_BN * HDIM];     // 16 KB
    __shared__ __half sV[2][FA_BN * HDIM];     // 16 KB

    const __half* qg = Q + ((size_t)bh * SEQ + q0) * HDIM;
    const __half* kg = K + (size_t)bh * SEQ * HDIM;
    const __half* vg = V + (size_t)bh * SEQ * HDIM;

    const uint32_t sQb  = (uint32_t)__cvta_generic_to_shared(sQ);
    const uint32_t sKb0 = (uint32_t)__cvta_generic_to_shared(sK[0]);
    const uint32_t sKb1 = (uint32_t)__cvta_generic_to_shared(sK[1]);
    const uint32_t sVb0 = (uint32_t)__cvta_generic_to_shared(sV[0]);
    const uint32_t sVb1 = (uint32_t)__cvta_generic_to_shared(sV[1]);

    // stage Q tile into smem (swizzled)
    #pragma unroll
    for (int e = tid; e < FA_BM * 8; e += 256) {
        const int row = e >> 3, ch = e & 7;
        *(uint4*)&sQ[sw_off(row, ch * 8)] = *(const uint4*)(qg + row * 64 + ch * 8);
    }

    // prologue: async-load K/V tiles 0 and 1
    #pragma unroll
    for (int pt = 0; pt < 2; ++pt) {
        const __half* kt = kg + pt * FA_BN * HDIM;
        const __half* vt = vg + pt * FA_BN * HDIM;
        const uint32_t kb = pt ? sKb1 : sKb0;
        const uint32_t vb = pt ? sVb1 : sVb0;
        #pragma unroll
        for (int e = tid; e < FA_BN * 8; e += 256) {
            const int row = e >> 3, ch = e & 7;
            const uint32_t so = 2 * sw_off(row, ch * 8);
            cp16(kb + so, kt + row * 64 + ch * 8);
            cp16(vb + so, vt + row * 64 + ch * 8);
        }
        asm volatile("cp.async.commit_group;" ::: "memory");
    }

    __syncthreads();

    // load Q fragments (A frags for 4 k-chunks of 16 d each)
    uint32_t aq[4][4];
    {
        const int qr = wid * 16 + (lane & 15);
        const int qc = (lane >> 4) * 8;
        #pragma unroll
        for (int c4 = 0; c4 < 4; ++c4)
            ldm_x4(aq[c4][0], aq[c4][1], aq[c4][2], aq[c4][3],
                   sQb + 2 * sw_off(qr, c4 * 16 + qc));
    }

    float o[8][4];
    #pragma unroll
    for (int j = 0; j < 8; ++j)
        #pragma unroll
        for (int r = 0; r < 4; ++r) o[j][r] = 0.f;
    float m0 = -1e30f, m1 = -1e30f, l0 = 0.f, l1 = 0.f;

    const int lrow = lane & 15;
    const int lcol8 = (lane >> 4) * 8;

    for (int t = 0; t < FA_TILES; ++t) {
        if (t < FA_TILES - 1)
            asm volatile("cp.async.wait_group 1;" ::: "memory");
        else
            asm volatile("cp.async.wait_group 0;" ::: "memory");
        __syncthreads();

        const uint32_t kb = (t & 1) ? sKb1 : sKb0;
        const uint32_t vb = (t & 1) ? sVb1 : sVb0;

        // S = Q @ K^T (log2-domain scores; scale folded into Q)
        float c[8][4];
        #pragma unroll
        for (int j = 0; j < 8; ++j)
            #pragma unroll
            for (int r = 0; r < 4; ++r) c[j][r] = 0.f;

        #pragma unroll
        for (int n16 = 0; n16 < 4; ++n16) {
            #pragma unroll
            for (int dc = 0; dc < 4; ++dc) {
                uint32_t r0, r1, r2, r3;
                ldm_x4(r0, r1, r2, r3,
                       kb + 2 * sw_off(n16 * 16 + lrow, dc * 16 + lcol8));
                mma16816(c[2 * n16 + 0], aq[dc], r0, r2);
                mma16816(c[2 * n16 + 1], aq[dc], r1, r3);
            }
        }

        // online softmax (rows g = lane/4 and g+8 of this warp)
        float t0 = -1e30f, t1 = -1e30f;
        #pragma unroll
        for (int j = 0; j < 8; ++j) {
            t0 = fmaxf(t0, fmaxf(c[j][0], c[j][1]));
            t1 = fmaxf(t1, fmaxf(c[j][2], c[j][3]));
        }
        t0 = fmaxf(t0, __shfl_xor_sync(0xffffffffu, t0, 1));
        t0 = fmaxf(t0, __shfl_xor_sync(0xffffffffu, t0, 2));
        t1 = fmaxf(t1, __shfl_xor_sync(0xffffffffu, t1, 1));
        t1 = fmaxf(t1, __shfl_xor_sync(0xffffffffu, t1, 2));

        const float m0n = fmaxf(m0, t0);
        const float m1n = fmaxf(m1, t1);
        const float a0 = ex2f(m0 - m0n);
        const float a1 = ex2f(m1 - m1n);
        m0 = m0n; m1 = m1n;

        float s0 = 0.f, s1 = 0.f;
        uint32_t ap[4][4];
        #pragma unroll
        for (int j = 0; j < 8; ++j) {
            const float p0 = ex2f(c[j][0] - m0);
            const float p1 = ex2f(c[j][1] - m0);
            const float p2 = ex2f(c[j][2] - m1);
            const float p3 = ex2f(c[j][3] - m1);
            s0 += p0 + p1;
            s1 += p2 + p3;
            const int kc = j >> 1, hi = (j & 1) << 1;
            __half2 u = __floats2half2_rn(p0, p1);
            __half2 w = __floats2half2_rn(p2, p3);
            ap[kc][hi + 0] = *(uint32_t*)&u;
            ap[kc][hi + 1] = *(uint32_t*)&w;
        }
        s0 += __shfl_xor_sync(0xffffffffu, s0, 1);
        s0 += __shfl_xor_sync(0xffffffffu, s0, 2);
        s1 += __shfl_xor_sync(0xffffffffu, s1, 1);
        s1 += __shfl_xor_sync(0xffffffffu, s1, 2);
        l0 = l0 * a0 + s0;
        l1 = l1 * a1 + s1;

        #pragma unroll
        for (int j = 0; j < 8; ++j) {
            o[j][0] *= a0; o[j][1] *= a0;
            o[j][2] *= a1; o[j][3] *= a1;
        }

        // O += P @ V
        #pragma unroll
        for (int kc = 0; kc < 4; ++kc) {
            #pragma unroll
            for (int dc = 0; dc < 4; ++dc) {
                uint32_t r0, r1, r2, r3;
                ldm_x4_t(r0, r1, r2, r3,
                         vb + 2 * sw_off(kc * 16 + lrow, dc * 16 + lcol8));
                mma16816(o[2 * dc + 0], ap[kc], r0, r1);
                mma16816(o[2 * dc + 1], ap[kc], r2, r3);
            }
        }

        __syncthreads();

        // issue tile t+2 into the buffer we just consumed
        if (t + 2 < FA_TILES) {
            const __half* kt = kg + (t + 2) * FA_BN * HDIM;
            const __half* vt = vg + (t + 2) * FA_BN * HDIM;
            const uint32_t kbn = (t & 1) ? sKb1 : sKb0;
            const uint32_t vbn = (t & 1) ? sVb1 : sVb0;
            #pragma unroll
            for (int e = tid; e < FA_BN * 8; e += 256) {
                const int row = e >> 3, ch = e & 7;
                const uint32_t so = 2 * sw_off(row, ch * 8);
                cp16(kbn + so, kt + row * 64 + ch * 8);
                cp16(vbn + so, vt + row * 64 + ch * 8);
            }
        }
        asm volatile("cp.async.commit_group;" ::: "memory");
    }

    // epilogue: normalize + store fp32
    const float inv0 = 1.0f / l0;
    const float inv1 = 1.0f / l1;
    const int g = lane >> 2;
    const int cq = (lane & 3) * 2;
    const int row0 = q0 + wid * 16 + g;
    const int row1 = row0 + 8;
    float* ob0 = out + ((size_t)(b * SEQ + row0)) * CDIM + h * HDIM + cq;
    float* ob1 = out + ((size_t)(b * SEQ + row1)) * CDIM + h * HDIM + cq;
    #pragma unroll
    for (int j = 0; j < 8; ++j) {
        *(float2*)(ob0 + j * 8) = make_float2(o[j][0] * inv0, o[j][1] * inv0);
        *(float2*)(ob1 + j * 8) = make_float2(o[j][2] * inv1, o[j][3] * inv1);
    }
}

// ---------------------------------------------------------------------------
// Launch
// ---------------------------------------------------------------------------
extern "C" void kernel_launch(void* const* d_in, const int* in_sizes, int n_in,
                              void* d_out, int out_size)
{
    const float* x    = (const float*)d_in[0];
    const float* Wqkv = (const float*)d_in[1];
    const float* bqkv = (const float*)d_in[2];
    const float* Wout = (const float*)d_in[3];
    const float* bout = (const float*)d_in[4];
    float* out = (float*)d_out;

    float *qkv = nullptr, *attn = nullptr;
    __half *qb = nullptr, *kb = nullptr, *vb = nullptr;
    cudaGetSymbolAddress((void**)&qkv,  g_qkv);
    cudaGetSymbolAddress((void**)&attn, g_attn);
    cudaGetSymbolAddress((void**)&qb, g_qb);
    cudaGetSymbolAddress((void**)&kb, g_kb);
    cudaGetSymbolAddress((void**)&vb, g_vb);

    // 1) qkv = x @ Wqkv + bqkv
    sgemm_bias_kernel<<<dim3(QKVC / 128, MROWS / 128), 256>>>(
        x, Wqkv, bqkv, qkv, MROWS, QKVC, CDIM);

    // 2) RoPE + fp16 cast + [b,h,t,d] relayout
    {
        const int total = MROWS * NHEAD * 32;
        rope_cast_kernel<<<(total + 255) / 256, 256>>>(qkv, qb, kb, vb);
    }

    // 3) tensor-core flash attention
    fa_kernel<<<dim3(SEQ / FA_BM, BATCH * NHEAD), 256>>>(qb, kb, vb, attn);

    // 4) out = attn @ Wout + bout
    sgemm_bias_kernel<<<dim3(CDIM / 128, MROWS / 128), 256>>>(
        attn, Wout, bout, out, MROWS, CDIM, CDIM);
}

// round 4
// speedup vs baseline: 4.7014x; 2.0124x over previous
#include <cuda_runtime.h>
#include <cuda_fp16.h>
#include <cuda_bf16.h>
#include <cstdint>
#include <cstddef>

// Problem constants (fixed shapes from setup_inputs)
#define BATCH 2
#define SEQ   2048
#define CDIM  1024
#define NHEAD 16
#define HDIM  64
#define MROWS (BATCH * SEQ)          // 4096
#define QKVC  (3 * CDIM)             // 3072
#define K3    (3 * CDIM)             // stacked-K width = 3072

// Scratch (allocation-free rule: __device__ globals)
__device__ float g_qkv [ (size_t)MROWS * QKVC ];            // 48 MB
__device__ float g_attn[ (size_t)MROWS * CDIM ];            // 16 MB
__device__ __half g_qb[(size_t)MROWS * CDIM];               // 8 MB [b][h][t][d]
__device__ __half g_kb[(size_t)MROWS * CDIM];
__device__ __half g_vb[(size_t)MROWS * CDIM];
__device__ __nv_bfloat16 g_Asp[(size_t)MROWS * K3];         // 24 MB [M][3K] split activations
__device__ __nv_bfloat16 g_B1 [(size_t)QKVC * K3];          // 18 MB [N=3072][3K] split Wqkv^T
__device__ __nv_bfloat16 g_B2 [(size_t)CDIM * K3];          //  6 MB [N=1024][3K] split Wout^T

// ---------------------------------------------------------------------------
// Common PTX helpers
// ---------------------------------------------------------------------------
__device__ __forceinline__ uint32_t sw_off(int row, int col) {
    // XOR swizzle on 16B chunks within a 64-elt (128B) 16-bit row
    return (uint32_t)(row * 64 + ((((col >> 3) ^ (row & 7)) << 3) | (col & 7)));
}
__device__ __forceinline__ void ldm_x4(uint32_t& r0, uint32_t& r1,
                                       uint32_t& r2, uint32_t& r3, uint32_t a) {
    asm volatile("ldmatrix.sync.aligned.m8n8.x4.shared.b16 {%0,%1,%2,%3}, [%4];"
                 : "=r"(r0), "=r"(r1), "=r"(r2), "=r"(r3) : "r"(a));
}
__device__ __forceinline__ void ldm_x4_t(uint32_t& r0, uint32_t& r1,
                                         uint32_t& r2, uint32_t& r3, uint32_t a) {
    asm volatile("ldmatrix.sync.aligned.m8n8.x4.trans.shared.b16 {%0,%1,%2,%3}, [%4];"
                 : "=r"(r0), "=r"(r1), "=r"(r2), "=r"(r3) : "r"(a));
}
__device__ __forceinline__ void mma16816_f16(float* c, const uint32_t* a,
                                             uint32_t b0, uint32_t b1) {
    asm volatile(
        "mma.sync.aligned.m16n8k16.row.col.f32.f16.f16.f32 "
        "{%0,%1,%2,%3}, {%4,%5,%6,%7}, {%8,%9}, {%0,%1,%2,%3};"
        : "+f"(c[0]), "+f"(c[1]), "+f"(c[2]), "+f"(c[3])
        : "r"(a[0]), "r"(a[1]), "r"(a[2]), "r"(a[3]), "r"(b0), "r"(b1));
}
__device__ __forceinline__ void mma16816_bf16(float* c, const uint32_t* a,
                                              uint32_t b0, uint32_t b1) {
    asm volatile(
        "mma.sync.aligned.m16n8k16.row.col.f32.bf16.bf16.f32 "
        "{%0,%1,%2,%3}, {%4,%5,%6,%7}, {%8,%9}, {%0,%1,%2,%3};"
        : "+f"(c[0]), "+f"(c[1]), "+f"(c[2]), "+f"(c[3])
        : "r"(a[0]), "r"(a[1]), "r"(a[2]), "r"(a[3]), "r"(b0), "r"(b1));
}
__device__ __forceinline__ float ex2f(float x) {
    float r;
    asm("ex2.approx.ftz.f32 %0, %1;" : "=f"(r) : "f"(x));
    return r;
}
__device__ __forceinline__ void cp16(uint32_t dst, const void* src) {
    asm volatile("cp.async.cg.shared.global [%0], [%1], 16;" :: "r"(dst), "l"(src));
}

// ---------------------------------------------------------------------------
// Split activations: in [M][Kin] fp32 -> out [M][3*Kin] bf16 = [hi | hi | lo]
// ---------------------------------------------------------------------------
__global__ void split_act_kernel(const float* __restrict__ in,
                                 __nv_bfloat16* __restrict__ out, int Kin)
{
    const int total = MROWS * (CDIM / 2);
    int idx = blockIdx.x * blockDim.x + threadIdx.x;
    if (idx >= total) return;
    const int row = idx / (Kin / 2);
    const int c2  = idx % (Kin / 2);
    const float2 v = *(const float2*)(in + (size_t)row * Kin + c2 * 2);
    __nv_bfloat16 h0 = __float2bfloat16(v.x);
    __nv_bfloat16 h1 = __float2bfloat16(v.y);
    __nv_bfloat16 l0 = __float2bfloat16(v.x - __bfloat162float(h0));
    __nv_bfloat16 l1 = __float2bfloat16(v.y - __bfloat162float(h1));
    __nv_bfloat162 hh; hh.x = h0; hh.y = h1;
    __nv_bfloat162 ll; ll.x = l0; ll.y = l1;
    __nv_bfloat16* o = out + (size_t)row * (3 * Kin);
    *(__nv_bfloat162*)(o + c2 * 2)            = hh;
    *(__nv_bfloat162*)(o + Kin + c2 * 2)      = hh;
    *(__nv_bfloat162*)(o + 2 * Kin + c2 * 2)  = ll;
}

// ---------------------------------------------------------------------------
// Transpose + split weights: W [K][N] fp32 -> Bt [N][3K] bf16 = [hi | lo | hi]
// (pairs with activation stacking [hi | hi | lo])
// ---------------------------------------------------------------------------
__global__ void wsplit_kernel(const float* __restrict__ W,
                              __nv_bfloat16* __restrict__ Bt, int K, int N)
{
    __shared__ float s[32][33];
    const int k0 = blockIdx.y * 32, n0 = blockIdx.x * 32;
    const int tx = threadIdx.x, ty = threadIdx.y;   // (32, 8)
    #pragma unroll
    for (int i = 0; i < 4; ++i)
        s[ty + i * 8][tx] = W[(size_t)(k0 + ty + i * 8) * N + n0 + tx];
    __syncthreads();
    #pragma unroll
    for (int i = 0; i < 4; ++i) {
        const int n = n0 + ty + i * 8, k = k0 + tx;
        const float v = s[tx][ty + i * 8];
        __nv_bfloat16 h = __float2bfloat16(v);
        __nv_bfloat16 l = __float2bfloat16(v - __bfloat162float(h));
        __nv_bfloat16* o = Bt + (size_t)n * (3 * K);
        o[k] = h; o[K + k] = l; o[2 * K + k] = h;
    }
}

// ---------------------------------------------------------------------------
// Tensor-core GEMM: C[M][N] = A[M][K] @ Bt[N][K]^T + bias  (bf16 in, fp32 out)
// 128x128x64 tiles, cp.async double-buffer, 8 warps (2M x 4N), warp 64x32.
// Dynamic smem: 64 KB.
// ---------------------------------------------------------------------------
#define GM_BK 64

extern __shared__ __nv_bfloat16 smem_dyn[];

__global__ __launch_bounds__(256) void hgemm_bias_kernel(
    const __nv_bfloat16* __restrict__ A,   // [M][K]
    const __nv_bfloat16* __restrict__ Bt,  // [N][K]
    const float* __restrict__ bias, float* __restrict__ C,
    int M, int N, int K)
{
    const int tid = threadIdx.x, lane = tid & 31, wid = tid >> 5;
    const int m0 = blockIdx.y * 128, n0 = blockIdx.x * 128;
    const int wm = (wid >> 2) * 64, wn = (wid & 3) * 32;
    const int lrow = lane & 15, lcol8 = (lane >> 4) * 8;

    const uint32_t sAb = (uint32_t)__cvta_generic_to_shared(smem_dyn);
    const uint32_t sBb = sAb + 2 * 16384;   // after the two A buffers

    const __nv_bfloat16* Ag = A  + (size_t)m0 * K;
    const __nv_bfloat16* Bg = Bt + (size_t)n0 * K;

    // tile loader: 128 rows x 64 cols bf16, 16B chunks, swizzled
    auto loadTile = [&](int it, int buf) {
        const __nv_bfloat16* ag = Ag + it * GM_BK;
        const __nv_bfloat16* bg = Bg + it * GM_BK;
        const uint32_t sa = sAb + buf * 16384;
        const uint32_t sb = sBb + buf * 16384;
        #pragma unroll
        for (int e = tid; e < 1024; e += 256) {
            const int row = e >> 3, ch = e & 7;
            const uint32_t so = 2 * sw_off(row, ch * 8);
            cp16(sa + so, ag + (size_t)row * K + ch * 8);
            cp16(sb + so, bg + (size_t)row * K + ch * 8);
        }
        asm volatile("cp.async.commit_group;" ::: "memory");
    };

    float acc[4][4][4];
    #pragma unroll
    for (int mt = 0; mt < 4; ++mt)
        #pragma unroll
        for (int nb = 0; nb < 4; ++nb)
            #pragma unroll
            for (int r = 0; r < 4; ++r) acc[mt][nb][r] = 0.f;

    const int kIters = K / GM_BK;
    loadTile(0, 0);
    loadTile(1, 1);

    for (int it = 0; it < kIters; ++it) {
        if (it < kIters - 1)
            asm volatile("cp.async.wait_group 1;" ::: "memory");
        else
            asm volatile("cp.async.wait_group 0;" ::: "memory");
        __syncthreads();

        const int buf = it & 1;
        const uint32_t sa = sAb + buf * 16384;
        const uint32_t sb = sBb + buf * 16384;

        #pragma unroll
        for (int k16 = 0; k16 < 4; ++k16) {
            uint32_t af[4][4];
            #pragma unroll
            for (int mt = 0; mt < 4; ++mt)
                ldm_x4(af[mt][0], af[mt][1], af[mt][2], af[mt][3],
                       sa + 2 * sw_off(wm + mt * 16 + lrow, k16 * 16 + lcol8));
            uint32_t bfr[4][2];
            #pragma unroll
            for (int nt = 0; nt < 2; ++nt) {
                uint32_t r0, r1, r2, r3;
                ldm_x4(r0, r1, r2, r3,
                       sb + 2 * sw_off(wn + nt * 16 + lrow, k16 * 16 + lcol8));
                bfr[2 * nt][0] = r0; bfr[2 * nt][1] = r2;
                bfr[2 * nt + 1][0] = r1; bfr[2 * nt + 1][1] = r3;
            }
            #pragma unroll
            for (int mt = 0; mt < 4; ++mt)
                #pragma unroll
                for (int nb = 0; nb < 4; ++nb)
                    mma16816_bf16(acc[mt][nb], af[mt], bfr[nb][0], bfr[nb][1]);
        }

        __syncthreads();
        if (it + 2 < kIters)
            loadTile(it + 2, buf);
        else
            asm volatile("cp.async.commit_group;" ::: "memory");
    }

    // epilogue: bias + store fp32
    #pragma unroll
    for (int mt = 0; mt < 4; ++mt) {
        const int r0 = m0 + wm + mt * 16 + (lane >> 2);
        #pragma unroll
        for (int nb = 0; nb < 4; ++nb) {
            const int cidx = n0 + wn + nb * 8 + (lane & 3) * 2;
            const float b0 = bias[cidx], b1 = bias[cidx + 1];
            *(float2*)(C + (size_t)r0 * N + cidx) =
                make_float2(acc[mt][nb][0] + b0, acc[mt][nb][1] + b1);
            *(float2*)(C + (size_t)(r0 + 8) * N + cidx) =
                make_float2(acc[mt][nb][2] + b0, acc[mt][nb][3] + b1);
        }
    }
}

// ---------------------------------------------------------------------------
// RoPE + cast to fp16, scatter into [b][h][t][d] layout (unchanged R3).
// ---------------------------------------------------------------------------
__global__ void rope_cast_kernel(const float* __restrict__ qkv,
                                 __half* __restrict__ qb,
                                 __half* __restrict__ kb,
                                 __half* __restrict__ vb)
{
    const int total = MROWS * NHEAD * 32;
    int idx = blockIdx.x * blockDim.x + threadIdx.x;
    if (idx >= total) return;
    const int d = idx & 31;
    const int h = (idx >> 5) & (NHEAD - 1);
    const int m = idx >> 9;
    const int t = m & (SEQ - 1);
    const int b = m >> 11;

    const float inv_freq = exp2f((float)d * (-13.2877123795494493f / 32.0f));
    const float ang = (float)t * inv_freq;
    float s, c;
    sincosf(ang, &s, &c);

    const float QS = 0.125f * 1.4426950408889634f;  // 1/sqrt(64) * log2(e)

    const float* base = qkv + (size_t)m * QKVC + h * HDIM + d;
    const float q1 = base[0], q2 = base[32];
    const float k1 = base[CDIM], k2 = base[CDIM + 32];
    const float v1 = base[2 * CDIM], v2 = base[2 * CDIM + 32];

    const size_t ob = ((size_t)(b * NHEAD + h) * SEQ + t) * HDIM + d;
    qb[ob]      = __float2half((q1 * c - q2 * s) * QS);
    qb[ob + 32] = __float2half((q2 * c + q1 * s) * QS);
    kb[ob]      = __float2half(k1 * c - k2 * s);
    kb[ob + 32] = __float2half(k2 * c + k1 * s);
    vb[ob]      = __float2half(v1);
    vb[ob + 32] = __float2half(v2);
}

// ---------------------------------------------------------------------------
// fp16 flash attention (unchanged R3, passing at rel_err 4e-4)
// ---------------------------------------------------------------------------
#define FA_BM 128
#define FA_BN 64
#define FA_TILES (SEQ / FA_BN)   // 32

__global__ __launch_bounds__(256) void fa_kernel(
    const __half* __restrict__ Q, const __half* __restrict__ K,
    const __half* __restrict__ V, float* __restrict__ out)
{
    const int bh = blockIdx.y;
    const int b  = bh >> 4;
    const int h  = bh & 15;
    const int q0 = blockIdx.x * FA_BM;
    const int tid  = threadIdx.x;
    const int lane = tid & 31;
    const int wid  = tid >> 5;

    __shared__ __half sQ[FA_BM * HDIM];
    __shared__ __half sK[2][FA_BN * HDIM];
    __shared__ __half sV[2][FA_BN * HDIM];

    const __half* qg = Q + ((size_t)bh * SEQ + q0) * HDIM;
    const __half* kg = K + (size_t)bh * SEQ * HDIM;
    const __half* vg = V + (size_t)bh * SEQ * HDIM;

    const uint32_t sQb  = (uint32_t)__cvta_generic_to_shared(sQ);
    const uint32_t sKb0 = (uint32_t)__cvta_generic_to_shared(sK[0]);
    const uint32_t sKb1 = (uint32_t)__cvta_generic_to_shared(sK[1]);
    const uint32_t sVb0 = (uint32_t)__cvta_generic_to_shared(sV[0]);
    const uint32_t sVb1 = (uint32_t)__cvta_generic_to_shared(sV[1]);

    #pragma unroll
    for (int e = tid; e < FA_BM * 8; e += 256) {
        const int row = e >> 3, ch = e & 7;
        *(uint4*)&sQ[sw_off(row, ch * 8)] = *(const uint4*)(qg + row * 64 + ch * 8);
    }

    #pragma unroll
    for (int pt = 0; pt < 2; ++pt) {
        const __half* kt = kg + pt * FA_BN * HDIM;
        const __half* vt = vg + pt * FA_BN * HDIM;
        const uint32_t kb = pt ? sKb1 : sKb0;
        const uint32_t vb = pt ? sVb1 : sVb0;
        #pragma unroll
        for (int e = tid; e < FA_BN * 8; e += 256) {
            const int row = e >> 3, ch = e & 7;
            const uint32_t so = 2 * sw_off(row, ch * 8);
            cp16(kb + so, kt + row * 64 + ch * 8);
            cp16(vb + so, vt + row * 64 + ch * 8);
        }
        asm volatile("cp.async.commit_group;" ::: "memory");
    }

    __syncthreads();

    uint32_t aq[4][4];
    {
        const int qr = wid * 16 + (lane & 15);
        const int qc = (lane >> 4) * 8;
        #pragma unroll
        for (int c4 = 0; c4 < 4; ++c4)
            ldm_x4(aq[c4][0], aq[c4][1], aq[c4][2], aq[c4][3],
                   sQb + 2 * sw_off(qr, c4 * 16 + qc));
    }

    float o[8][4];
    #pragma unroll
    for (int j = 0; j < 8; ++j)
        #pragma unroll
        for (int r = 0; r < 4; ++r) o[j][r] = 0.f;
    float m0 = -1e30f, m1 = -1e30f, l0 = 0.f, l1 = 0.f;

    const int lrow = lane & 15;
    const int lcol8 = (lane >> 4) * 8;

    for (int t = 0; t < FA_TILES; ++t) {
        if (t < FA_TILES - 1)
            asm volatile("cp.async.wait_group 1;" ::: "memory");
        else
            asm volatile("cp.async.wait_group 0;" ::: "memory");
        __syncthreads();

        const uint32_t kb = (t & 1) ? sKb1 : sKb0;
        const uint32_t vb = (t & 1) ? sVb1 : sVb0;

        float c[8][4];
        #pragma unroll
        for (int j = 0; j < 8; ++j)
            #pragma unroll
            for (int r = 0; r < 4; ++r) c[j][r] = 0.f;

        #pragma unroll
        for (int n16 = 0; n16 < 4; ++n16) {
            #pragma unroll
            for (int dc = 0; dc < 4; ++dc) {
                uint32_t r0, r1, r2, r3;
                ldm_x4(r0, r1, r2, r3,
                       kb + 2 * sw_off(n16 * 16 + lrow, dc * 16 + lcol8));
                mma16816_f16(c[2 * n16 + 0], aq[dc], r0, r2);
                mma16816_f16(c[2 * n16 + 1], aq[dc], r1, r3);
            }
        }

        float t0 = -1e30f, t1 = -1e30f;
        #pragma unroll
        for (int j = 0; j < 8; ++j) {
            t0 = fmaxf(t0, fmaxf(c[j][0], c[j][1]));
            t1 = fmaxf(t1, fmaxf(c[j][2], c[j][3]));
        }
        t0 = fmaxf(t0, __shfl_xor_sync(0xffffffffu, t0, 1));
        t0 = fmaxf(t0, __shfl_xor_sync(0xffffffffu, t0, 2));
        t1 = fmaxf(t1, __shfl_xor_sync(0xffffffffu, t1, 1));
        t1 = fmaxf(t1, __shfl_xor_sync(0xffffffffu, t1, 2));

        const float m0n = fmaxf(m0, t0);
        const float m1n = fmaxf(m1, t1);
        const float a0 = ex2f(m0 - m0n);
        const float a1 = ex2f(m1 - m1n);
        m0 = m0n; m1 = m1n;

        float s0 = 0.f, s1 = 0.f;
        uint32_t ap[4][4];
        #pragma unroll
        for (int j = 0; j < 8; ++j) {
            const float p0 = ex2f(c[j][0] - m0);
            const float p1 = ex2f(c[j][1] - m0);
            const float p2 = ex2f(c[j][2] - m1);
            const float p3 = ex2f(c[j][3] - m1);
            s0 += p0 + p1;
            s1 += p2 + p3;
            const int kc = j >> 1, hi = (j & 1) << 1;
            __half2 u = __floats2half2_rn(p0, p1);
            __half2 w = __floats2half2_rn(p2, p3);
            ap[kc][hi + 0] = *(uint32_t*)&u;
            ap[kc][hi + 1] = *(uint32_t*)&w;
        }
        s0 += __shfl_xor_sync(0xffffffffu, s0, 1);
        s0 += __shfl_xor_sync(0xffffffffu, s0, 2);
        s1 += __shfl_xor_sync(0xffffffffu, s1, 1);
        s1 += __shfl_xor_sync(0xffffffffu, s1, 2);
        l0 = l0 * a0 + s0;
        l1 = l1 * a1 + s1;

        #pragma unroll
        for (int j = 0; j < 8; ++j) {
            o[j][0] *= a0; o[j][1] *= a0;
            o[j][2] *= a1; o[j][3] *= a1;
        }

        #pragma unroll
        for (int kc = 0; kc < 4; ++kc) {
            #pragma unroll
            for (int dc = 0; dc < 4; ++dc) {
                uint32_t r0, r1, r2, r3;
                ldm_x4_t(r0, r1, r2, r3,
                         vb + 2 * sw_off(kc * 16 + lrow, dc * 16 + lcol8));
                mma16816_f16(o[2 * dc + 0], ap[kc], r0, r1);
                mma16816_f16(o[2 * dc + 1], ap[kc], r2, r3);
            }
        }

        __syncthreads();

        if (t + 2 < FA_TILES) {
            const __half* kt = kg + (t + 2) * FA_BN * HDIM;
            const __half* vt = vg + (t + 2) * FA_BN * HDIM;
            const uint32_t kbn = (t & 1) ? sKb1 : sKb0;
            const uint32_t vbn = (t & 1) ? sVb1 : sVb0;
            #pragma unroll
            for (int e = tid; e < FA_BN * 8; e += 256) {
                const int row = e >> 3, ch = e & 7;
                const uint32_t so = 2 * sw_off(row, ch * 8);
                cp16(kbn + so, kt + row * 64 + ch * 8);
                cp16(vbn + so, vt + row * 64 + ch * 8);
            }
        }
        asm volatile("cp.async.commit_group;" ::: "memory");
    }

    const float inv0 = 1.0f / l0;
    const float inv1 = 1.0f / l1;
    const int g = lane >> 2;
    const int cq = (lane & 3) * 2;
    const int row0 = q0 + wid * 16 + g;
    const int row1 = row0 + 8;
    float* ob0 = out + ((size_t)(b * SEQ + row0)) * CDIM + h * HDIM + cq;
    float* ob1 = out + ((size_t)(b * SEQ + row1)) * CDIM + h * HDIM + cq;
    #pragma unroll
    for (int j = 0; j < 8; ++j) {
        *(float2*)(ob0 + j * 8) = make_float2(o[j][0] * inv0, o[j][1] * inv0);
        *(float2*)(ob1 + j * 8) = make_float2(o[j][2] * inv1, o[j][3] * inv1);
    }
}

// ---------------------------------------------------------------------------
// Launch
// ---------------------------------------------------------------------------
extern "C" void kernel_launch(void* const* d_in, const int* in_sizes, int n_in,
                              void* d_out, int out_size)
{
    const float* x    = (const float*)d_in[0];
    const float* Wqkv = (const float*)d_in[1];
    const float* bqkv = (const float*)d_in[2];
    const float* Wout = (const float*)d_in[3];
    const float* bout = (const float*)d_in[4];
    float* out = (float*)d_out;

    float *qkv = nullptr, *attn = nullptr;
    __half *qb = nullptr, *kb = nullptr, *vb = nullptr;
    __nv_bfloat16 *Asp = nullptr, *B1 = nullptr, *B2 = nullptr;
    cudaGetSymbolAddress((void**)&qkv,  g_qkv);
    cudaGetSymbolAddress((void**)&attn, g_attn);
    cudaGetSymbolAddress((void**)&qb, g_qb);
    cudaGetSymbolAddress((void**)&kb, g_kb);
    cudaGetSymbolAddress((void**)&vb, g_vb);
    cudaGetSymbolAddress((void**)&Asp, g_Asp);
    cudaGetSymbolAddress((void**)&B1,  g_B1);
    cudaGetSymbolAddress((void**)&B2,  g_B2);

    // opt-in to 64 KB dynamic smem for the GEMM (idempotent, capture-safe)
    cudaFuncSetAttribute(hgemm_bias_kernel,
                         cudaFuncAttributeMaxDynamicSharedMemorySize, 65536);

    const int splitBlocks = (MROWS * (CDIM / 2) + 255) / 256;

    // 1) split x -> Asp [4096][3072]; split+transpose Wqkv -> B1 [3072][3072]
    split_act_kernel<<<splitBlocks, 256>>>(x, Asp, CDIM);
    wsplit_kernel<<<dim3(QKVC / 32, CDIM / 32), dim3(32, 8)>>>(Wqkv, B1, CDIM, QKVC);

    // 2) qkv = x @ Wqkv + bqkv   (tensor-core split GEMM, K=3072)
    hgemm_bias_kernel<<<dim3(QKVC / 128, MROWS / 128), 256, 65536>>>(
        Asp, B1, bqkv, qkv, MROWS, QKVC, K3);

    // 3) RoPE + fp16 cast + [b,h,t,d] relayout
    {
        const int total = MROWS * NHEAD * 32;
        rope_cast_kernel<<<(total + 255) / 256, 256>>>(qkv, qb, kb, vb);
    }

    // 4) tensor-core flash attention
    fa_kernel<<<dim3(SEQ / FA_BM, BATCH * NHEAD), 256>>>(qb, kb, vb, attn);

    // 5) split attn -> Asp (reuse); split+transpose Wout -> B2 [1024][3072]
    split_act_kernel<<<splitBlocks, 256>>>(attn, Asp, CDIM);
    wsplit_kernel<<<dim3(CDIM / 32, CDIM / 32), dim3(32, 8)>>>(Wout, B2, CDIM, CDIM);

    // 6) out = attn @ Wout + bout   (tensor-core split GEMM)
    hgemm_bias_kernel<<<dim3(CDIM / 128, MROWS / 128), 256, 65536>>>(
        Asp, B2, bout, out, MROWS, CDIM, K3);
}

// round 6
// speedup vs baseline: 6.1302x; 1.3039x over previous
#include <cuda_runtime.h>
#include <cuda_fp16.h>
#include <cstdint>
#include <cstddef>

// Problem constants (fixed shapes from setup_inputs)
#define BATCH 2
#define SEQ   2048
#define CDIM  1024
#define NHEAD 16
#define HDIM  64
#define MROWS (BATCH * SEQ)          // 4096
#define QKVC  (3 * CDIM)             // 3072
#define KA    (2 * CDIM)             // stacked-K width (hi|lo) = 2048

// Scratch (allocation-free rule: __device__ globals)
__device__ float  g_qkv [ (size_t)MROWS * QKVC ];    // 48 MB
__device__ __half g_qb[(size_t)MROWS * CDIM];        // 8 MB [b][h][t][d]
__device__ __half g_kb[(size_t)MROWS * CDIM];
__device__ __half g_vb[(size_t)MROWS * CDIM];
__device__ __half g_Asp[(size_t)MROWS * KA];         // 16 MB [M][2K] split activations
__device__ __half g_W1 [(size_t)QKVC * CDIM];        //  6 MB [N=3072][K=1024] Wqkv^T fp16
__device__ __half g_W2 [(size_t)CDIM * CDIM];        //  2 MB [N=1024][K=1024] Wout^T fp16

// ---------------------------------------------------------------------------
// Common PTX helpers
// ---------------------------------------------------------------------------
__device__ __forceinline__ uint32_t sw_off(int row, int col) {
    // XOR swizzle on 16B chunks within a 64-elt (128B) 16-bit row
    return (uint32_t)(row * 64 + ((((col >> 3) ^ (row & 7)) << 3) | (col & 7)));
}
__device__ __forceinline__ void ldm_x4(uint32_t& r0, uint32_t& r1,
                                       uint32_t& r2, uint32_t& r3, uint32_t a) {
    asm volatile("ldmatrix.sync.aligned.m8n8.x4.shared.b16 {%0,%1,%2,%3}, [%4];"
                 : "=r"(r0), "=r"(r1), "=r"(r2), "=r"(r3) : "r"(a));
}
__device__ __forceinline__ void ldm_x4_t(uint32_t& r0, uint32_t& r1,
                                         uint32_t& r2, uint32_t& r3, uint32_t a) {
    asm volatile("ldmatrix.sync.aligned.m8n8.x4.trans.shared.b16 {%0,%1,%2,%3}, [%4];"
                 : "=r"(r0), "=r"(r1), "=r"(r2), "=r"(r3) : "r"(a));
}
__device__ __forceinline__ void mma16816_f16(float* c, const uint32_t* a,
                                             uint32_t b0, uint32_t b1) {
    asm volatile(
        "mma.sync.aligned.m16n8k16.row.col.f32.f16.f16.f32 "
        "{%0,%1,%2,%3}, {%4,%5,%6,%7}, {%8,%9}, {%0,%1,%2,%3};"
        : "+f"(c[0]), "+f"(c[1]), "+f"(c[2]), "+f"(c[3])
        : "r"(a[0]), "r"(a[1]), "r"(a[2]), "r"(a[3]), "r"(b0), "r"(b1));
}
__device__ __forceinline__ float ex2f(float x) {
    float r;
    asm("ex2.approx.ftz.f32 %0, %1;" : "=f"(r) : "f"(x));
    return r;
}
__device__ __forceinline__ void cp16(uint32_t dst, const void* src) {
    asm volatile("cp.async.cg.shared.global [%0], [%1], 16;" :: "r"(dst), "l"(src));
}

// ---------------------------------------------------------------------------
// Split activations: in [M][Kin] fp32 -> out [M][2*Kin] fp16 = [hi | lo]
// ---------------------------------------------------------------------------
__global__ void split_act_kernel(const float* __restrict__ in,
                                 __half* __restrict__ out)
{
    const int total = MROWS * (CDIM / 2);
    int idx = blockIdx.x * blockDim.x + threadIdx.x;
    if (idx >= total) return;
    const int row = idx / (CDIM / 2);
    const int c2  = idx % (CDIM / 2);
    const float2 v = *(const float2*)(in + (size_t)row * CDIM + c2 * 2);
    const __half h0 = __float2half_rn(v.x);
    const __half h1 = __float2half_rn(v.y);
    const __half l0 = __float2half_rn(v.x - __half2float(h0));
    const __half l1 = __float2half_rn(v.y - __half2float(h1));
    __half2 hh; hh.x = h0; hh.y = h1;
    __half2 ll; ll.x = l0; ll.y = l1;
    __half* o = out + (size_t)row * KA;
    *(__half2*)(o + c2 * 2)        = hh;
    *(__half2*)(o + CDIM + c2 * 2) = ll;
}

// ---------------------------------------------------------------------------
// Transpose weights: W [K][N] fp32 -> Wt [N][K] fp16 (single rounding)
// ---------------------------------------------------------------------------
__global__ void wtrans_kernel(const float* __restrict__ W,
                              __half* __restrict__ Wt, int K, int N)
{
    __shared__ float s[32][33];
    const int k0 = blockIdx.y * 32, n0 = blockIdx.x * 32;
    const int tx = threadIdx.x, ty = threadIdx.y;   // (32, 8)
    #pragma unroll
    for (int i = 0; i < 4; ++i)
        s[ty + i * 8][tx] = W[(size_t)(k0 + ty + i * 8) * N + n0 + tx];
    __syncthreads();
    #pragma unroll
    for (int i = 0; i < 4; ++i) {
        const int n = n0 + ty + i * 8, k = k0 + tx;
        Wt[(size_t)n * K + k] = __float2half_rn(s[tx][ty + i * 8]);
    }
}

// ---------------------------------------------------------------------------
// Tensor-core GEMM (fp16 in, fp32 out): C[M][N] = A[M][Ka] @ BtileWrap + bias
// A is [M][Ka] with Ka = 2*Kb (hi|lo stack); B is [N][Kb], tile index wraps
// (bMask) so the lo half of A re-reads the same B. 128x128x64 tiles,
// cp.async double-buffer, 8 warps (2M x 4N), warp 64x32. Dyn smem: 64 KB.
// ---------------------------------------------------------------------------
#define GM_BK 64

extern __shared__ __half smem_dyn[];

__global__ __launch_bounds__(256) void hgemm_bias_kernel(
    const __half* __restrict__ A,   // [M][Ka]
    const __half* __restrict__ Bt,  // [N][Kb]
    const float* __restrict__ bias, float* __restrict__ C,
    int M, int N, int Ka, int Kb, int bMask)
{
    const int tid = threadIdx.x, lane = tid & 31, wid = tid >> 5;
    const int m0 = blockIdx.y * 128, n0 = blockIdx.x * 128;
    const int wm = (wid >> 2) * 64, wn = (wid & 3) * 32;
    const int lrow = lane & 15, lcol8 = (lane >> 4) * 8;

    const uint32_t sAb = (uint32_t)__cvta_generic_to_shared(smem_dyn);
    const uint32_t sBb = sAb + 2 * 16384;   // after the two A buffers

    const __half* Ag = A  + (size_t)m0 * Ka;
    const __half* Bg = Bt + (size_t)n0 * Kb;

    // tile loader: 128 rows x 64 cols fp16, 16B chunks, swizzled
    auto loadTile = [&](int it, int buf) {
        const __half* ag = Ag + it * GM_BK;
        const __half* bg = Bg + (it & bMask) * GM_BK;
        const uint32_t sa = sAb + buf * 16384;
        const uint32_t sb = sBb + buf * 16384;
        #pragma unroll
        for (int e = tid; e < 1024; e += 256) {
            const int row = e >> 3, ch = e & 7;
            const uint32_t so = 2 * sw_off(row, ch * 8);
            cp16(sa + so, ag + (size_t)row * Ka + ch * 8);
            cp16(sb + so, bg + (size_t)row * Kb + ch * 8);
        }
        asm volatile("cp.async.commit_group;" ::: "memory");
    };

    float acc[4][4][4];
    #pragma unroll
    for (int mt = 0; mt < 4; ++mt)
        #pragma unroll
        for (int nb = 0; nb < 4; ++nb)
            #pragma unroll
            for (int r = 0; r < 4; ++r) acc[mt][nb][r] = 0.f;

    const int kIters = Ka / GM_BK;
    loadTile(0, 0);
    loadTile(1, 1);

    for (int it = 0; it < kIters; ++it) {
        if (it < kIters - 1)
            asm volatile("cp.async.wait_group 1;" ::: "memory");
        else
            asm volatile("cp.async.wait_group 0;" ::: "memory");
        __syncthreads();

        const int buf = it & 1;
        const uint32_t sa = sAb + buf * 16384;
        const uint32_t sb = sBb + buf * 16384;

        #pragma unroll
        for (int k16 = 0; k16 < 4; ++k16) {
            uint32_t af[4][4];
            #pragma unroll
            for (int mt = 0; mt < 4; ++mt)
                ldm_x4(af[mt][0], af[mt][1], af[mt][2], af[mt][3],
                       sa + 2 * sw_off(wm + mt * 16 + lrow, k16 * 16 + lcol8));
            uint32_t bfr[4][2];
            #pragma unroll
            for (int nt = 0; nt < 2; ++nt) {
                uint32_t r0, r1, r2, r3;
                ldm_x4(r0, r1, r2, r3,
                       sb + 2 * sw_off(wn + nt * 16 + lrow, k16 * 16 + lcol8));
                bfr[2 * nt][0] = r0; bfr[2 * nt][1] = r2;
                bfr[2 * nt + 1][0] = r1; bfr[2 * nt + 1][1] = r3;
            }
            #pragma unroll
            for (int mt = 0; mt < 4; ++mt)
                #pragma unroll
                for (int nb = 0; nb < 4; ++nb)
                    mma16816_f16(acc[mt][nb], af[mt], bfr[nb][0], bfr[nb][1]);
        }

        __syncthreads();
        if (it + 2 < kIters)
            loadTile(it + 2, buf);
        else
            asm volatile("cp.async.commit_group;" ::: "memory");
    }

    // epilogue: bias + store fp32
    #pragma unroll
    for (int mt = 0; mt < 4; ++mt) {
        const int r0 = m0 + wm + mt * 16 + (lane >> 2);
        #pragma unroll
        for (int nb = 0; nb < 4; ++nb) {
            const int cidx = n0 + wn + nb * 8 + (lane & 3) * 2;
            const float b0 = bias[cidx], b1 = bias[cidx + 1];
            *(float2*)(C + (size_t)r0 * N + cidx) =
                make_float2(acc[mt][nb][0] + b0, acc[mt][nb][1] + b1);
            *(float2*)(C + (size_t)(r0 + 8) * N + cidx) =
                make_float2(acc[mt][nb][2] + b0, acc[mt][nb][3] + b1);
        }
    }
}

// ---------------------------------------------------------------------------
// RoPE + cast to fp16, scatter into [b][h][t][d] layout (unchanged).
// ---------------------------------------------------------------------------
__global__ void rope_cast_kernel(const float* __restrict__ qkv,
                                 __half* __restrict__ qb,
                                 __half* __restrict__ kb,
                                 __half* __restrict__ vb)
{
    const int total = MROWS * NHEAD * 32;
    int idx = blockIdx.x * blockDim.x + threadIdx.x;
    if (idx >= total) return;
    const int d = idx & 31;
    const int h = (idx >> 5) & (NHEAD - 1);
    const int m = idx >> 9;
    const int t = m & (SEQ - 1);
    const int b = m >> 11;

    const float inv_freq = exp2f((float)d * (-13.2877123795494493f / 32.0f));
    const float ang = (float)t * inv_freq;
    float s, c;
    sincosf(ang, &s, &c);

    const float QS = 0.125f * 1.4426950408889634f;  // 1/sqrt(64) * log2(e)

    const float* base = qkv + (size_t)m * QKVC + h * HDIM + d;
    const float q1 = base[0], q2 = base[32];
    const float k1 = base[CDIM], k2 = base[CDIM + 32];
    const float v1 = base[2 * CDIM], v2 = base[2 * CDIM + 32];

    const size_t ob = ((size_t)(b * NHEAD + h) * SEQ + t) * HDIM + d;
    qb[ob]      = __float2half((q1 * c - q2 * s) * QS);
    qb[ob + 32] = __float2half((q2 * c + q1 * s) * QS);
    kb[ob]      = __float2half(k1 * c - k2 * s);
    kb[ob + 32] = __float2half(k2 * c + k1 * s);
    vb[ob]      = __float2half(v1);
    vb[ob + 32] = __float2half(v2);
}

// ---------------------------------------------------------------------------
// fp16 flash attention. Epilogue now writes the hi/lo split activation
// directly into Asp [M][2K] (fuses the out-proj split_act kernel).
// ---------------------------------------------------------------------------
#define FA_BM 128
#define FA_BN 64
#define FA_TILES (SEQ / FA_BN)   // 32

__global__ __launch_bounds__(256) void fa_kernel(
    const __half* __restrict__ Q, const __half* __restrict__ K,
    const __half* __restrict__ V, __half* __restrict__ Asp)
{
    const int bh = blockIdx.y;
    const int b  = bh >> 4;
    const int h  = bh & 15;
    const int q0 = blockIdx.x * FA_BM;
    const int tid  = threadIdx.x;
    const int lane = tid & 31;
    const int wid  = tid >> 5;

    __shared__ __half sQ[FA_BM * HDIM];
    __shared__ __half sK[2][FA_BN * HDIM];
    __shared__ __half sV[2][FA_BN * HDIM];

    const __half* qg = Q + ((size_t)bh * SEQ + q0) * HDIM;
    const __half* kg = K + (size_t)bh * SEQ * HDIM;
    const __half* vg = V + (size_t)bh * SEQ * HDIM;

    const uint32_t sQb  = (uint32_t)__cvta_generic_to_shared(sQ);
    const uint32_t sKb0 = (uint32_t)__cvta_generic_to_shared(sK[0]);
    const uint32_t sKb1 = (uint32_t)__cvta_generic_to_shared(sK[1]);
    const uint32_t sVb0 = (uint32_t)__cvta_generic_to_shared(sV[0]);
    const uint32_t sVb1 = (uint32_t)__cvta_generic_to_shared(sV[1]);

    #pragma unroll
    for (int e = tid; e < FA_BM * 8; e += 256) {
        const int row = e >> 3, ch = e & 7;
        *(uint4*)&sQ[sw_off(row, ch * 8)] = *(const uint4*)(qg + row * 64 + ch * 8);
    }

    #pragma unroll
    for (int pt = 0; pt < 2; ++pt) {
        const __half* kt = kg + pt * FA_BN * HDIM;
        const __half* vt = vg + pt * FA_BN * HDIM;
        const uint32_t kb = pt ? sKb1 : sKb0;
        const uint32_t vb = pt ? sVb1 : sVb0;
        #pragma unroll
        for (int e = tid; e < FA_BN * 8; e += 256) {
            const int row = e >> 3, ch = e & 7;
            const uint32_t so = 2 * sw_off(row, ch * 8);
            cp16(kb + so, kt + row * 64 + ch * 8);
            cp16(vb + so, vt + row * 64 + ch * 8);
        }
        asm volatile("cp.async.commit_group;" ::: "memory");
    }

    __syncthreads();

    uint32_t aq[4][4];
    {
        const int qr = wid * 16 + (lane & 15);
        const int qc = (lane >> 4) * 8;
        #pragma unroll
        for (int c4 = 0; c4 < 4; ++c4)
            ldm_x4(aq[c4][0], aq[c4][1], aq[c4][2], aq[c4][3],
                   sQb + 2 * sw_off(qr, c4 * 16 + qc));
    }

    float o[8][4];
    #pragma unroll
    for (int j = 0; j < 8; ++j)
        #pragma unroll
        for (int r = 0; r < 4; ++r) o[j][r] = 0.f;
    float m0 = -1e30f, m1 = -1e30f, l0 = 0.f, l1 = 0.f;

    const int lrow = lane & 15;
    const int lcol8 = (lane >> 4) * 8;

    for (int t = 0; t < FA_TILES; ++t) {
        if (t < FA_TILES - 1)
            asm volatile("cp.async.wait_group 1;" ::: "memory");
        else
            asm volatile("cp.async.wait_group 0;" ::: "memory");
        __syncthreads();

        const uint32_t kb = (t & 1) ? sKb1 : sKb0;
        const uint32_t vb = (t & 1) ? sVb1 : sVb0;

        float c[8][4];
        #pragma unroll
        for (int j = 0; j < 8; ++j)
            #pragma unroll
            for (int r = 0; r < 4; ++r) c[j][r] = 0.f;

        #pragma unroll
        for (int n16 = 0; n16 < 4; ++n16) {
            #pragma unroll
            for (int dc = 0; dc < 4; ++dc) {
                uint32_t r0, r1, r2, r3;
                ldm_x4(r0, r1, r2, r3,
                       kb + 2 * sw_off(n16 * 16 + lrow, dc * 16 + lcol8));
                mma16816_f16(c[2 * n16 + 0], aq[dc], r0, r2);
                mma16816_f16(c[2 * n16 + 1], aq[dc], r1, r3);
            }
        }

        float t0 = -1e30f, t1 = -1e30f;
        #pragma unroll
        for (int j = 0; j < 8; ++j) {
            t0 = fmaxf(t0, fmaxf(c[j][0], c[j][1]));
            t1 = fmaxf(t1, fmaxf(c[j][2], c[j][3]));
        }
        t0 = fmaxf(t0, __shfl_xor_sync(0xffffffffu, t0, 1));
        t0 = fmaxf(t0, __shfl_xor_sync(0xffffffffu, t0, 2));
        t1 = fmaxf(t1, __shfl_xor_sync(0xffffffffu, t1, 1));
        t1 = fmaxf(t1, __shfl_xor_sync(0xffffffffu, t1, 2));

        const float m0n = fmaxf(m0, t0);
        const float m1n = fmaxf(m1, t1);
        const float a0 = ex2f(m0 - m0n);
        const float a1 = ex2f(m1 - m1n);
        m0 = m0n; m1 = m1n;

        float s0 = 0.f, s1 = 0.f;
        uint32_t ap[4][4];
        #pragma unroll
        for (int j = 0; j < 8; ++j) {
            const float p0 = ex2f(c[j][0] - m0);
            const float p1 = ex2f(c[j][1] - m0);
            const float p2 = ex2f(c[j][2] - m1);
            const float p3 = ex2f(c[j][3] - m1);
            s0 += p0 + p1;
            s1 += p2 + p3;
            const int kc = j >> 1, hi = (j & 1) << 1;
            __half2 u = __floats2half2_rn(p0, p1);
            __half2 w = __floats2half2_rn(p2, p3);
            ap[kc][hi + 0] = *(uint32_t*)&u;
            ap[kc][hi + 1] = *(uint32_t*)&w;
        }
        s0 += __shfl_xor_sync(0xffffffffu, s0, 1);
        s0 += __shfl_xor_sync(0xffffffffu, s0, 2);
        s1 += __shfl_xor_sync(0xffffffffu, s1, 1);
        s1 += __shfl_xor_sync(0xffffffffu, s1, 2);
        l0 = l0 * a0 + s0;
        l1 = l1 * a1 + s1;

        #pragma unroll
        for (int j = 0; j < 8; ++j) {
            o[j][0] *= a0; o[j][1] *= a0;
            o[j][2] *= a1; o[j][3] *= a1;
        }

        #pragma unroll
        for (int kc = 0; kc < 4; ++kc) {
            #pragma unroll
            for (int dc = 0; dc < 4; ++dc) {
                uint32_t r0, r1, r2, r3;
                ldm_x4_t(r0, r1, r2, r3,
                         vb + 2 * sw_off(kc * 16 + lrow, dc * 16 + lcol8));
                mma16816_f16(o[2 * dc + 0], ap[kc], r0, r1);
                mma16816_f16(o[2 * dc + 1], ap[kc], r2, r3);
            }
        }

        __syncthreads();

        if (t + 2 < FA_TILES) {
            const __half* kt = kg + (t + 2) * FA_BN * HDIM;
            const __half* vt = vg + (t + 2) * FA_BN * HDIM;
            const uint32_t kbn = (t & 1) ? sKb1 : sKb0;
            const uint32_t vbn = (t & 1) ? sVb1 : sVb0;
            #pragma unroll
            for (int e = tid; e < FA_BN * 8; e += 256) {
                const int row = e >> 3, ch = e & 7;
                const uint32_t so = 2 * sw_off(row, ch * 8);
                cp16(kbn + so, kt + row * 64 + ch * 8);
                cp16(vbn + so, vt + row * 64 + ch * 8);
            }
        }
        asm volatile("cp.async.commit_group;" ::: "memory");
    }

    // epilogue: normalize + hi/lo fp16 split, write into Asp [M][2K]
    const float inv0 = 1.0f / l0;
    const float inv1 = 1.0f / l1;
    const int g = lane >> 2;
    const int cq = (lane & 3) * 2;
    const int row0 = q0 + wid * 16 + g;
    const int row1 = row0 + 8;
    __half* ab0 = Asp + (size_t)(b * SEQ + row0) * KA + h * HDIM + cq;
    __half* ab1 = Asp + (size_t)(b * SEQ + row1) * KA + h * HDIM + cq;
    #pragma unroll
    for (int j = 0; j < 8; ++j) {
        const float v00 = o[j][0] * inv0, v01 = o[j][1] * inv0;
        const float v10 = o[j][2] * inv1, v11 = o[j][3] * inv1;
        const __half h00 = __float2half_rn(v00), h01 = __float2half_rn(v01);
        const __half h10 = __float2half_rn(v10), h11 = __float2half_rn(v11);
        __half2 hh0; hh0.x = h00; hh0.y = h01;
        __half2 hh1; hh1.x = h10; hh1.y = h11;
        __half2 ll0; ll0.x = __float2half_rn(v00 - __half2float(h00));
                     ll0.y = __float2half_rn(v01 - __half2float(h01));
        __half2 ll1; ll1.x = __float2half_rn(v10 - __half2float(h10));
                     ll1.y = __float2half_rn(v11 - __half2float(h11));
        *(__half2*)(ab0 + j * 8)        = hh0;
        *(__half2*)(ab0 + CDIM + j * 8) = ll0;
        *(__half2*)(ab1 + j * 8)        = hh1;
        *(__half2*)(ab1 + CDIM + j * 8) = ll1;
    }
}

// ---------------------------------------------------------------------------
// Launch
// ---------------------------------------------------------------------------
extern "C" void kernel_launch(void* const* d_in, const int* in_sizes, int n_in,
                              void* d_out, int out_size)
{
    const float* x    = (const float*)d_in[0];
    const float* Wqkv = (const float*)d_in[1];
    const float* bqkv = (const float*)d_in[2];
    const float* Wout = (const float*)d_in[3];
    const float* bout = (const float*)d_in[4];
    float* out = (float*)d_out;

    float *qkv = nullptr;
    __half *qb = nullptr, *kb = nullptr, *vb = nullptr;
    __half *Asp = nullptr, *W1 = nullptr, *W2 = nullptr;
    cudaGetSymbolAddress((void**)&qkv,  g_qkv);
    cudaGetSymbolAddress((void**)&qb, g_qb);
    cudaGetSymbolAddress((void**)&kb, g_kb);
    cudaGetSymbolAddress((void**)&vb, g_vb);
    cudaGetSymbolAddress((void**)&Asp, g_Asp);
    cudaGetSymbolAddress((void**)&W1,  g_W1);
    cudaGetSymbolAddress((void**)&W2,  g_W2);

    cudaFuncSetAttribute(hgemm_bias_kernel,
                         cudaFuncAttributeMaxDynamicSharedMemorySize, 65536);

    const int splitBlocks = (MROWS * (CDIM / 2) + 255) / 256;

    // 1) split x -> Asp [4096][2048] (hi|lo); transpose Wqkv -> W1 [3072][1024]
    split_act_kernel<<<splitBlocks, 256>>>(x, Asp);
    wtrans_kernel<<<dim3(QKVC / 32, CDIM / 32), dim3(32, 8)>>>(Wqkv, W1, CDIM, QKVC);

    // 2) qkv = x @ Wqkv + bqkv   (fp16 2-term split GEMM, Ka=2048, B wraps)
    hgemm_bias_kernel<<<dim3(QKVC / 128, MROWS / 128), 256, 65536>>>(
        Asp, W1, bqkv, qkv, MROWS, QKVC, KA, CDIM, (CDIM / GM_BK) - 1);

    // 3) RoPE + fp16 cast + [b,h,t,d] relayout
    {
        const int total = MROWS * NHEAD * 32;
        rope_cast_kernel<<<(total + 255) / 256, 256>>>(qkv, qb, kb, vb);
    }

    // 4) flash attention; epilogue writes split activations into Asp (reused)
    fa_kernel<<<dim3(SEQ / FA_BM, BATCH * NHEAD), 256>>>(qb, kb, vb, Asp);

    // 5) transpose Wout -> W2 [1024][1024]
    wtrans_kernel<<<dim3(CDIM / 32, CDIM / 32), dim3(32, 8)>>>(Wout, W2, CDIM, CDIM);

    // 6) out = attn @ Wout + bout   (fp16 2-term split GEMM)
    hgemm_bias_kernel<<<dim3(CDIM / 128, MROWS / 128), 256, 65536>>>(
        Asp, W2, bout, out, MROWS, CDIM, KA, CDIM, (CDIM / GM_BK) - 1);
}

// round 7
// speedup vs baseline: 7.7554x; 1.2651x over previous
#include <cuda_runtime.h>
#include <cuda_fp16.h>
#include <cstdint>
#include <cstddef>

// Problem constants (fixed shapes from setup_inputs)
#define BATCH 2
#define SEQ   2048
#define CDIM  1024
#define NHEAD 16
#define HDIM  64
#define MROWS (BATCH * SEQ)          // 4096
#define QKVC  (3 * CDIM)             // 3072
#define KA    (2 * CDIM)             // out-proj stacked-K width (hi|lo) = 2048

// Scratch (allocation-free rule: __device__ globals)
__device__ float  g_qkv [ (size_t)MROWS * QKVC ];    // 48 MB
__device__ __half g_x16 [ (size_t)MROWS * CDIM ];    //  8 MB fp16 cast of x
__device__ __half g_qb[(size_t)MROWS * CDIM];        //  8 MB [b][h][t][d]
__device__ __half g_kb[(size_t)MROWS * CDIM];
__device__ __half g_vb[(size_t)MROWS * CDIM];
__device__ __half g_Asp[(size_t)MROWS * KA];         // 16 MB [M][2K] split attn output
__device__ __half g_W1 [(size_t)QKVC * CDIM];        //  6 MB [N=3072][K=1024] Wqkv^T fp16
__device__ __half g_W2 [(size_t)CDIM * CDIM];        //  2 MB [N=1024][K=1024] Wout^T fp16

// ---------------------------------------------------------------------------
// Common PTX helpers
// ---------------------------------------------------------------------------
__device__ __forceinline__ uint32_t sw_off(int row, int col) {
    // XOR swizzle on 16B chunks within a 64-elt (128B) 16-bit row
    return (uint32_t)(row * 64 + ((((col >> 3) ^ (row & 7)) << 3) | (col & 7)));
}
__device__ __forceinline__ void ldm_x4(uint32_t& r0, uint32_t& r1,
                                       uint32_t& r2, uint32_t& r3, uint32_t a) {
    asm volatile("ldmatrix.sync.aligned.m8n8.x4.shared.b16 {%0,%1,%2,%3}, [%4];"
                 : "=r"(r0), "=r"(r1), "=r"(r2), "=r"(r3) : "r"(a));
}
__device__ __forceinline__ void ldm_x4_t(uint32_t& r0, uint32_t& r1,
                                         uint32_t& r2, uint32_t& r3, uint32_t a) {
    asm volatile("ldmatrix.sync.aligned.m8n8.x4.trans.shared.b16 {%0,%1,%2,%3}, [%4];"
                 : "=r"(r0), "=r"(r1), "=r"(r2), "=r"(r3) : "r"(a));
}
__device__ __forceinline__ void mma16816_f16(float* c, const uint32_t* a,
                                             uint32_t b0, uint32_t b1) {
    asm volatile(
        "mma.sync.aligned.m16n8k16.row.col.f32.f16.f16.f32 "
        "{%0,%1,%2,%3}, {%4,%5,%6,%7}, {%8,%9}, {%0,%1,%2,%3};"
        : "+f"(c[0]), "+f"(c[1]), "+f"(c[2]), "+f"(c[3])
        : "r"(a[0]), "r"(a[1]), "r"(a[2]), "r"(a[3]), "r"(b0), "r"(b1));
}
__device__ __forceinline__ float ex2f(float x) {
    float r;
    asm("ex2.approx.ftz.f32 %0, %1;" : "=f"(r) : "f"(x));
    return r;
}
__device__ __forceinline__ void cp16(uint32_t dst, const void* src) {
    asm volatile("cp.async.cg.shared.global [%0], [%1], 16;" :: "r"(dst), "l"(src));
}

// ---------------------------------------------------------------------------
// Cast activations: in [M][CDIM] fp32 -> out [M][CDIM] fp16
// ---------------------------------------------------------------------------
__global__ void cast_act_kernel(const float* __restrict__ in,
                                __half* __restrict__ out)
{
    const int total = MROWS * (CDIM / 2);
    int idx = blockIdx.x * blockDim.x + threadIdx.x;
    if (idx >= total) return;
    const float2 v = *(const float2*)(in + (size_t)idx * 2);
    __half2 hh;
    hh.x = __float2half_rn(v.x);
    hh.y = __float2half_rn(v.y);
    *(__half2*)(out + (size_t)idx * 2) = hh;
}

// ---------------------------------------------------------------------------
// Transpose weights: W [K][N] fp32 -> Wt [N][K] fp16 (single rounding)
// ---------------------------------------------------------------------------
__global__ void wtrans_kernel(const float* __restrict__ W,
                              __half* __restrict__ Wt, int K, int N)
{
    __shared__ float s[32][33];
    const int k0 = blockIdx.y * 32, n0 = blockIdx.x * 32;
    const int tx = threadIdx.x, ty = threadIdx.y;   // (32, 8)
    #pragma unroll
    for (int i = 0; i < 4; ++i)
        s[ty + i * 8][tx] = W[(size_t)(k0 + ty + i * 8) * N + n0 + tx];
    __syncthreads();
    #pragma unroll
    for (int i = 0; i < 4; ++i) {
        const int n = n0 + ty + i * 8, k = k0 + tx;
        Wt[(size_t)n * K + k] = __float2half_rn(s[tx][ty + i * 8]);
    }
}

// ---------------------------------------------------------------------------
// Tensor-core GEMM (fp16 in, fp32 out): C[M][N] = A[M][Ka] @ BtileWrap + bias
// A is [M][Ka]; B is [N][Kb], Kb <= Ka, B tile index wraps (bMask) so a hi|lo
// stacked A re-reads the same B. 128x128x64 tiles, cp.async double-buffer,
// 8 warps (2M x 4N), warp 64x32. Dyn smem: 64 KB.
// ---------------------------------------------------------------------------
#define GM_BK 64

extern __shared__ __half smem_dyn[];

__global__ __launch_bounds__(256) void hgemm_bias_kernel(
    const __half* __restrict__ A,   // [M][Ka]
    const __half* __restrict__ Bt,  // [N][Kb]
    const float* __restrict__ bias, float* __restrict__ C,
    int M, int N, int Ka, int Kb, int bMask)
{
    const int tid = threadIdx.x, lane = tid & 31, wid = tid >> 5;
    const int m0 = blockIdx.y * 128, n0 = blockIdx.x * 128;
    const int wm = (wid >> 2) * 64, wn = (wid & 3) * 32;
    const int lrow = lane & 15, lcol8 = (lane >> 4) * 8;

    const uint32_t sAb = (uint32_t)__cvta_generic_to_shared(smem_dyn);
    const uint32_t sBb = sAb + 2 * 16384;   // after the two A buffers

    const __half* Ag = A  + (size_t)m0 * Ka;
    const __half* Bg = Bt + (size_t)n0 * Kb;

    // tile loader: 128 rows x 64 cols fp16, 16B chunks, swizzled
    auto loadTile = [&](int it, int buf) {
        const __half* ag = Ag + it * GM_BK;
        const __half* bg = Bg + (it & bMask) * GM_BK;
        const uint32_t sa = sAb + buf * 16384;
        const uint32_t sb = sBb + buf * 16384;
        #pragma unroll
        for (int e = tid; e < 1024; e += 256) {
            const int row = e >> 3, ch = e & 7;
            const uint32_t so = 2 * sw_off(row, ch * 8);
            cp16(sa + so, ag + (size_t)row * Ka + ch * 8);
            cp16(sb + so, bg + (size_t)row * Kb + ch * 8);
        }
        asm volatile("cp.async.commit_group;" ::: "memory");
    };

    float acc[4][4][4];
    #pragma unroll
    for (int mt = 0; mt < 4; ++mt)
        #pragma unroll
        for (int nb = 0; nb < 4; ++nb)
            #pragma unroll
            for (int r = 0; r < 4; ++r) acc[mt][nb][r] = 0.f;

    const int kIters = Ka / GM_BK;
    loadTile(0, 0);
    loadTile(1, 1);

    for (int it = 0; it < kIters; ++it) {
        if (it < kIters - 1)
            asm volatile("cp.async.wait_group 1;" ::: "memory");
        else
            asm volatile("cp.async.wait_group 0;" ::: "memory");
        __syncthreads();

        const int buf = it & 1;
        const uint32_t sa = sAb + buf * 16384;
        const uint32_t sb = sBb + buf * 16384;

        #pragma unroll
        for (int k16 = 0; k16 < 4; ++k16) {
            uint32_t af[4][4];
            #pragma unroll
            for (int mt = 0; mt < 4; ++mt)
                ldm_x4(af[mt][0], af[mt][1], af[mt][2], af[mt][3],
                       sa + 2 * sw_off(wm + mt * 16 + lrow, k16 * 16 + lcol8));
            uint32_t bfr[4][2];
            #pragma unroll
            for (int nt = 0; nt < 2; ++nt) {
                uint32_t r0, r1, r2, r3;
                ldm_x4(r0, r1, r2, r3,
                       sb + 2 * sw_off(wn + nt * 16 + lrow, k16 * 16 + lcol8));
                bfr[2 * nt][0] = r0; bfr[2 * nt][1] = r2;
                bfr[2 * nt + 1][0] = r1; bfr[2 * nt + 1][1] = r3;
            }
            #pragma unroll
            for (int mt = 0; mt < 4; ++mt)
                #pragma unroll
                for (int nb = 0; nb < 4; ++nb)
                    mma16816_f16(acc[mt][nb], af[mt], bfr[nb][0], bfr[nb][1]);
        }

        __syncthreads();
        if (it + 2 < kIters)
            loadTile(it + 2, buf);
        else
            asm volatile("cp.async.commit_group;" ::: "memory");
    }

    // epilogue: bias + store fp32
    #pragma unroll
    for (int mt = 0; mt < 4; ++mt) {
        const int r0 = m0 + wm + mt * 16 + (lane >> 2);
        #pragma unroll
        for (int nb = 0; nb < 4; ++nb) {
            const int cidx = n0 + wn + nb * 8 + (lane & 3) * 2;
            const float b0 = bias[cidx], b1 = bias[cidx + 1];
            *(float2*)(C + (size_t)r0 * N + cidx) =
                make_float2(acc[mt][nb][0] + b0, acc[mt][nb][1] + b1);
            *(float2*)(C + (size_t)(r0 + 8) * N + cidx) =
                make_float2(acc[mt][nb][2] + b0, acc[mt][nb][3] + b1);
        }
    }
}

// ---------------------------------------------------------------------------
// RoPE + cast to fp16, scatter into [b][h][t][d] layout (unchanged).
// ---------------------------------------------------------------------------
__global__ void rope_cast_kernel(const float* __restrict__ qkv,
                                 __half* __restrict__ qb,
                                 __half* __restrict__ kb,
                                 __half* __restrict__ vb)
{
    const int total = MROWS * NHEAD * 32;
    int idx = blockIdx.x * blockDim.x + threadIdx.x;
    if (idx >= total) return;
    const int d = idx & 31;
    const int h = (idx >> 5) & (NHEAD - 1);
    const int m = idx >> 9;
    const int t = m & (SEQ - 1);
    const int b = m >> 11;

    const float inv_freq = exp2f((float)d * (-13.2877123795494493f / 32.0f));
    const float ang = (float)t * inv_freq;
    float s, c;
    sincosf(ang, &s, &c);

    const float QS = 0.125f * 1.4426950408889634f;  // 1/sqrt(64) * log2(e)

    const float* base = qkv + (size_t)m * QKVC + h * HDIM + d;
    const float q1 = base[0], q2 = base[32];
    const float k1 = base[CDIM], k2 = base[CDIM + 32];
    const float v1 = base[2 * CDIM], v2 = base[2 * CDIM + 32];

    const size_t ob = ((size_t)(b * NHEAD + h) * SEQ + t) * HDIM + d;
    qb[ob]      = __float2half((q1 * c - q2 * s) * QS);
    qb[ob + 32] = __float2half((q2 * c + q1 * s) * QS);
    kb[ob]      = __float2half(k1 * c - k2 * s);
    kb[ob + 32] = __float2half(k2 * c + k1 * s);
    vb[ob]      = __float2half(v1);
    vb[ob + 32] = __float2half(v2);
}

// ---------------------------------------------------------------------------
// fp16 flash attention. Epilogue writes the hi/lo split activation directly
// into Asp [M][2K] for the 2-term out-projection GEMM.
// ---------------------------------------------------------------------------
#define FA_BM 128
#define FA_BN 64
#define FA_TILES (SEQ / FA_BN)   // 32

__global__ __launch_bounds__(256) void fa_kernel(
    const __half* __restrict__ Q, const __half* __restrict__ K,
    const __half* __restrict__ V, __half* __restrict__ Asp)
{
    const int bh = blockIdx.y;
    const int b  = bh >> 4;
    const int h  = bh & 15;
    const int q0 = blockIdx.x * FA_BM;
    const int tid  = threadIdx.x;
    const int lane = tid & 31;
    const int wid  = tid >> 5;

    __shared__ __half sQ[FA_BM * HDIM];
    __shared__ __half sK[2][FA_BN * HDIM];
    __shared__ __half sV[2][FA_BN * HDIM];

    const __half* qg = Q + ((size_t)bh * SEQ + q0) * HDIM;
    const __half* kg = K + (size_t)bh * SEQ * HDIM;
    const __half* vg = V + (size_t)bh * SEQ * HDIM;

    const uint32_t sQb  = (uint32_t)__cvta_generic_to_shared(sQ);
    const uint32_t sKb0 = (uint32_t)__cvta_generic_to_shared(sK[0]);
    const uint32_t sKb1 = (uint32_t)__cvta_generic_to_shared(sK[1]);
    const uint32_t sVb0 = (uint32_t)__cvta_generic_to_shared(sV[0]);
    const uint32_t sVb1 = (uint32_t)__cvta_generic_to_shared(sV[1]);

    #pragma unroll
    for (int e = tid; e < FA_BM * 8; e += 256) {
        const int row = e >> 3, ch = e & 7;
        *(uint4*)&sQ[sw_off(row, ch * 8)] = *(const uint4*)(qg + row * 64 + ch * 8);
    }

    #pragma unroll
    for (int pt = 0; pt < 2; ++pt) {
        const __half* kt = kg + pt * FA_BN * HDIM;
        const __half* vt = vg + pt * FA_BN * HDIM;
        const uint32_t kb = pt ? sKb1 : sKb0;
        const uint32_t vb = pt ? sVb1 : sVb0;
        #pragma unroll
        for (int e = tid; e < FA_BN * 8; e += 256) {
            const int row = e >> 3, ch = e & 7;
            const uint32_t so = 2 * sw_off(row, ch * 8);
            cp16(kb + so, kt + row * 64 + ch * 8);
            cp16(vb + so, vt + row * 64 + ch * 8);
        }
        asm volatile("cp.async.commit_group;" ::: "memory");
    }

    __syncthreads();

    uint32_t aq[4][4];
    {
        const int qr = wid * 16 + (lane & 15);
        const int qc = (lane >> 4) * 8;
        #pragma unroll
        for (int c4 = 0; c4 < 4; ++c4)
            ldm_x4(aq[c4][0], aq[c4][1], aq[c4][2], aq[c4][3],
                   sQb + 2 * sw_off(qr, c4 * 16 + qc));
    }

    float o[8][4];
    #pragma unroll
    for (int j = 0; j < 8; ++j)
        #pragma unroll
        for (int r = 0; r < 4; ++r) o[j][r] = 0.f;
    float m0 = -1e30f, m1 = -1e30f, l0 = 0.f, l1 = 0.f;

    const int lrow = lane & 15;
    const int lcol8 = (lane >> 4) * 8;

    for (int t = 0; t < FA_TILES; ++t) {
        if (t < FA_TILES - 1)
            asm volatile("cp.async.wait_group 1;" ::: "memory");
        else
            asm volatile("cp.async.wait_group 0;" ::: "memory");
        __syncthreads();

        const uint32_t kb = (t & 1) ? sKb1 : sKb0;
        const uint32_t vb = (t & 1) ? sVb1 : sVb0;

        float c[8][4];
        #pragma unroll
        for (int j = 0; j < 8; ++j)
            #pragma unroll
            for (int r = 0; r < 4; ++r) c[j][r] = 0.f;

        #pragma unroll
        for (int n16 = 0; n16 < 4; ++n16) {
            #pragma unroll
            for (int dc = 0; dc < 4; ++dc) {
                uint32_t r0, r1, r2, r3;
                ldm_x4(r0, r1, r2, r3,
                       kb + 2 * sw_off(n16 * 16 + lrow, dc * 16 + lcol8));
                mma16816_f16(c[2 * n16 + 0], aq[dc], r0, r2);
                mma16816_f16(c[2 * n16 + 1], aq[dc], r1, r3);
            }
        }

        float t0 = -1e30f, t1 = -1e30f;
        #pragma unroll
        for (int j = 0; j < 8; ++j) {
            t0 = fmaxf(t0, fmaxf(c[j][0], c[j][1]));
            t1 = fmaxf(t1, fmaxf(c[j][2], c[j][3]));
        }
        t0 = fmaxf(t0, __shfl_xor_sync(0xffffffffu, t0, 1));
        t0 = fmaxf(t0, __shfl_xor_sync(0xffffffffu, t0, 2));
        t1 = fmaxf(t1, __shfl_xor_sync(0xffffffffu, t1, 1));
        t1 = fmaxf(t1, __shfl_xor_sync(0xffffffffu, t1, 2));

        const float m0n = fmaxf(m0, t0);
        const float m1n = fmaxf(m1, t1);
        const float a0 = ex2f(m0 - m0n);
        const float a1 = ex2f(m1 - m1n);
        m0 = m0n; m1 = m1n;

        float s0 = 0.f, s1 = 0.f;
        uint32_t ap[4][4];
        #pragma unroll
        for (int j = 0; j < 8; ++j) {
            const float p0 = ex2f(c[j][0] - m0);
            const float p1 = ex2f(c[j][1] - m0);
            const float p2 = ex2f(c[j][2] - m1);
            const float p3 = ex2f(c[j][3] - m1);
            s0 += p0 + p1;
            s1 += p2 + p3;
            const int kc = j >> 1, hi = (j & 1) << 1;
            __half2 u = __floats2half2_rn(p0, p1);
            __half2 w = __floats2half2_rn(p2, p3);
            ap[kc][hi + 0] = *(uint32_t*)&u;
            ap[kc][hi + 1] = *(uint32_t*)&w;
        }
        s0 += __shfl_xor_sync(0xffffffffu, s0, 1);
        s0 += __shfl_xor_sync(0xffffffffu, s0, 2);
        s1 += __shfl_xor_sync(0xffffffffu, s1, 1);
        s1 += __shfl_xor_sync(0xffffffffu, s1, 2);
        l0 = l0 * a0 + s0;
        l1 = l1 * a1 + s1;

        #pragma unroll
        for (int j = 0; j < 8; ++j) {
            o[j][0] *= a0; o[j][1] *= a0;
            o[j][2] *= a1; o[j][3] *= a1;
        }

        #pragma unroll
        for (int kc = 0; kc < 4; ++kc) {
            #pragma unroll
            for (int dc = 0; dc < 4; ++dc) {
                uint32_t r0, r1, r2, r3;
                ldm_x4_t(r0, r1, r2, r3,
                         vb + 2 * sw_off(kc * 16 + lrow, dc * 16 + lcol8));
                mma16816_f16(o[2 * dc + 0], ap[kc], r0, r1);
                mma16816_f16(o[2 * dc + 1], ap[kc], r2, r3);
            }
        }

        __syncthreads();

        if (t + 2 < FA_TILES) {
            const __half* kt = kg + (t + 2) * FA_BN * HDIM;
            const __half* vt = vg + (t + 2) * FA_BN * HDIM;
            const uint32_t kbn = (t & 1) ? sKb1 : sKb0;
            const uint32_t vbn = (t & 1) ? sVb1 : sVb0;
            #pragma unroll
            for (int e = tid; e < FA_BN * 8; e += 256) {
                const int row = e >> 3, ch = e & 7;
                const uint32_t so = 2 * sw_off(row, ch * 8);
                cp16(kbn + so, kt + row * 64 + ch * 8);
                cp16(vbn + so, vt + row * 64 + ch * 8);
            }
        }
        asm volatile("cp.async.commit_group;" ::: "memory");
    }

    // epilogue: normalize + hi/lo fp16 split, write into Asp [M][2K]
    const float inv0 = 1.0f / l0;
    const float inv1 = 1.0f / l1;
    const int g = lane >> 2;
    const int cq = (lane & 3) * 2;
    const int row0 = q0 + wid * 16 + g;
    const int row1 = row0 + 8;
    __half* ab0 = Asp + (size_t)(b * SEQ + row0) * KA + h * HDIM + cq;
    __half* ab1 = Asp + (size_t)(b * SEQ + row1) * KA + h * HDIM + cq;
    #pragma unroll
    for (int j = 0; j < 8; ++j) {
        const float v00 = o[j][0] * inv0, v01 = o[j][1] * inv0;
        const float v10 = o[j][2] * inv1, v11 = o[j][3] * inv1;
        const __half h00 = __float2half_rn(v00), h01 = __float2half_rn(v01);
        const __half h10 = __float2half_rn(v10), h11 = __float2half_rn(v11);
        __half2 hh0; hh0.x = h00; hh0.y = h01;
        __half2 hh1; hh1.x = h10; hh1.y = h11;
        __half2 ll0; ll0.x = __float2half_rn(v00 - __half2float(h00));
                     ll0.y = __float2half_rn(v01 - __half2float(h01));
        __half2 ll1; ll1.x = __float2half_rn(v10 - __half2float(h10));
                     ll1.y = __float2half_rn(v11 - __half2float(h11));
        *(__half2*)(ab0 + j * 8)        = hh0;
        *(__half2*)(ab0 + CDIM + j * 8) = ll0;
        *(__half2*)(ab1 + j * 8)        = hh1;
        *(__half2*)(ab1 + CDIM + j * 8) = ll1;
    }
}

// ---------------------------------------------------------------------------
// Launch
// ---------------------------------------------------------------------------
extern "C" void kernel_launch(void* const* d_in, const int* in_sizes, int n_in,
                              void* d_out, int out_size)
{
    const float* x    = (const float*)d_in[0];
    const float* Wqkv = (const float*)d_in[1];
    const float* bqkv = (const float*)d_in[2];
    const float* Wout = (const float*)d_in[3];
    const float* bout = (const float*)d_in[4];
    float* out = (float*)d_out;

    float *qkv = nullptr;
    __half *x16 = nullptr, *qb = nullptr, *kb = nullptr, *vb = nullptr;
    __half *Asp = nullptr, *W1 = nullptr, *W2 = nullptr;
    cudaGetSymbolAddress((void**)&qkv,  g_qkv);
    cudaGetSymbolAddress((void**)&x16, g_x16);
    cudaGetSymbolAddress((void**)&qb, g_qb);
    cudaGetSymbolAddress((void**)&kb, g_kb);
    cudaGetSymbolAddress((void**)&vb, g_vb);
    cudaGetSymbolAddress((void**)&Asp, g_Asp);
    cudaGetSymbolAddress((void**)&W1,  g_W1);
    cudaGetSymbolAddress((void**)&W2,  g_W2);

    cudaFuncSetAttribute(hgemm_bias_kernel,
                         cudaFuncAttributeMaxDynamicSharedMemorySize, 65536);

    const int castBlocks = (MROWS * (CDIM / 2) + 255) / 256;

    // 1) cast x -> x16 [4096][1024]; transpose Wqkv -> W1 [3072][1024]
    cast_act_kernel<<<castBlocks, 256>>>(x, x16);
    wtrans_kernel<<<dim3(QKVC / 32, CDIM / 32), dim3(32, 8)>>>(Wqkv, W1, CDIM, QKVC);

    // 2) qkv = x @ Wqkv + bqkv   (plain fp16 GEMM, K=1024)
    hgemm_bias_kernel<<<dim3(QKVC / 128, MROWS / 128), 256, 65536>>>(
        x16, W1, bqkv, qkv, MROWS, QKVC, CDIM, CDIM, (CDIM / GM_BK) - 1);

    // 3) RoPE + fp16 cast + [b,h,t,d] relayout
    {
        const int total = MROWS * NHEAD * 32;
        rope_cast_kernel<<<(total + 255) / 256, 256>>>(qkv, qb, kb, vb);
    }

    // 4) flash attention; epilogue writes split activations into Asp
    fa_kernel<<<dim3(SEQ / FA_BM, BATCH * NHEAD), 256>>>(qb, kb, vb, Asp);

    // 5) transpose Wout -> W2 [1024][1024]
    wtrans_kernel<<<dim3(CDIM / 32, CDIM / 32), dim3(32, 8)>>>(Wout, W2, CDIM, CDIM);

    // 6) out = attn @ Wout + bout   (fp16 2-term split GEMM, Ka=2048, B wraps)
    hgemm_bias_kernel<<<dim3(CDIM / 128, MROWS / 128), 256, 65536>>>(
        Asp, W2, bout, out, MROWS, CDIM, KA, CDIM, (CDIM / GM_BK) - 1);
}

// round 8
// speedup vs baseline: 8.6456x; 1.1148x over previous
#include <cuda_runtime.h>
#include <cuda_fp16.h>
#include <cstdint>
#include <cstddef>

// Problem constants (fixed shapes from setup_inputs)
#define BATCH 2
#define SEQ   2048
#define CDIM  1024
#define NHEAD 16
#define HDIM  64
#define MROWS (BATCH * SEQ)          // 4096
#define QKVC  (3 * CDIM)             // 3072

// Scratch (allocation-free rule: __device__ globals)
__device__ __half g_qkv[(size_t)MROWS * QKVC];       // 24 MB fp16 qkv
__device__ __half g_x16[(size_t)MROWS * CDIM];       //  8 MB fp16 cast of x
__device__ __half g_qb[(size_t)MROWS * CDIM];        //  8 MB [b][h][t][d]
__device__ __half g_kb[(size_t)MROWS * CDIM];
__device__ __half g_vb[(size_t)MROWS * CDIM];
__device__ __half g_attn[(size_t)MROWS * CDIM];      //  8 MB attn output fp16
__device__ __half g_W1 [(size_t)QKVC * CDIM];        //  6 MB [N=3072][K=1024] Wqkv^T fp16
__device__ __half g_W2 [(size_t)CDIM * CDIM];        //  2 MB [N=1024][K=1024] Wout^T fp16

// ---------------------------------------------------------------------------
// Common PTX helpers
// ---------------------------------------------------------------------------
__device__ __forceinline__ uint32_t sw_off(int row, int col) {
    // XOR swizzle on 16B chunks within a 64-elt (128B) 16-bit row
    return (uint32_t)(row * 64 + ((((col >> 3) ^ (row & 7)) << 3) | (col & 7)));
}
__device__ __forceinline__ void ldm_x4(uint32_t& r0, uint32_t& r1,
                                       uint32_t& r2, uint32_t& r3, uint32_t a) {
    asm volatile("ldmatrix.sync.aligned.m8n8.x4.shared.b16 {%0,%1,%2,%3}, [%4];"
                 : "=r"(r0), "=r"(r1), "=r"(r2), "=r"(r3) : "r"(a));
}
__device__ __forceinline__ void ldm_x4_t(uint32_t& r0, uint32_t& r1,
                                         uint32_t& r2, uint32_t& r3, uint32_t a) {
    asm volatile("ldmatrix.sync.aligned.m8n8.x4.trans.shared.b16 {%0,%1,%2,%3}, [%4];"
                 : "=r"(r0), "=r"(r1), "=r"(r2), "=r"(r3) : "r"(a));
}
__device__ __forceinline__ void mma16816_f16(float* c, const uint32_t* a,
                                             uint32_t b0, uint32_t b1) {
    asm volatile(
        "mma.sync.aligned.m16n8k16.row.col.f32.f16.f16.f32 "
        "{%0,%1,%2,%3}, {%4,%5,%6,%7}, {%8,%9}, {%0,%1,%2,%3};"
        : "+f"(c[0]), "+f"(c[1]), "+f"(c[2]), "+f"(c[3])
        : "r"(a[0]), "r"(a[1]), "r"(a[2]), "r"(a[3]), "r"(b0), "r"(b1));
}
__device__ __forceinline__ float ex2f(float x) {
    float r;
    asm("ex2.approx.ftz.f32 %0, %1;" : "=f"(r) : "f"(x));
    return r;
}
__device__ __forceinline__ void cp16(uint32_t dst, const void* src) {
    asm volatile("cp.async.cg.shared.global [%0], [%1], 16;" :: "r"(dst), "l"(src));
}

// ---------------------------------------------------------------------------
// Cast activations: in [M][CDIM] fp32 -> out [M][CDIM] fp16
// ---------------------------------------------------------------------------
__global__ void cast_act_kernel(const float* __restrict__ in,
                                __half* __restrict__ out)
{
    const int total = MROWS * (CDIM / 2);
    int idx = blockIdx.x * blockDim.x + threadIdx.x;
    if (idx >= total) return;
    const float2 v = *(const float2*)(in + (size_t)idx * 2);
    __half2 hh;
    hh.x = __float2half_rn(v.x);
    hh.y = __float2half_rn(v.y);
    *(__half2*)(out + (size_t)idx * 2) = hh;
}

// ---------------------------------------------------------------------------
// Transpose weights: W [K][N] fp32 -> Wt [N][K] fp16 (single rounding)
// ---------------------------------------------------------------------------
__global__ void wtrans_kernel(const float* __restrict__ W,
                              __half* __restrict__ Wt, int K, int N)
{
    __shared__ float s[32][33];
    const int k0 = blockIdx.y * 32, n0 = blockIdx.x * 32;
    const int tx = threadIdx.x, ty = threadIdx.y;   // (32, 8)
    #pragma unroll
    for (int i = 0; i < 4; ++i)
        s[ty + i * 8][tx] = W[(size_t)(k0 + ty + i * 8) * N + n0 + tx];
    __syncthreads();
    #pragma unroll
    for (int i = 0; i < 4; ++i) {
        const int n = n0 + ty + i * 8, k = k0 + tx;
        Wt[(size_t)n * K + k] = __float2half_rn(s[tx][ty + i * 8]);
    }
}

// ---------------------------------------------------------------------------
// Tensor-core GEMM (fp16 in, OutT out): C[M][N] = A[M][K] @ Bt[N][K]^T + bias
// 128x128x64 tiles, cp.async double-buffer, 8 warps (2M x 4N), warp 64x32.
// Dyn smem: 64 KB.
// ---------------------------------------------------------------------------
#define GM_BK 64

extern __shared__ __half smem_dyn[];

template <typename OutT>
__global__ __launch_bounds__(256) void hgemm_bias_kernel(
    const __half* __restrict__ A,   // [M][K]
    const __half* __restrict__ Bt,  // [N][K]
    const float* __restrict__ bias, OutT* __restrict__ C,
    int M, int N, int K)
{
    const int tid = threadIdx.x, lane = tid & 31, wid = tid >> 5;
    const int m0 = blockIdx.y * 128, n0 = blockIdx.x * 128;
    const int wm = (wid >> 2) * 64, wn = (wid & 3) * 32;
    const int lrow = lane & 15, lcol8 = (lane >> 4) * 8;

    const uint32_t sAb = (uint32_t)__cvta_generic_to_shared(smem_dyn);
    const uint32_t sBb = sAb + 2 * 16384;   // after the two A buffers

    const __half* Ag = A  + (size_t)m0 * K;
    const __half* Bg = Bt + (size_t)n0 * K;

    // tile loader: 128 rows x 64 cols fp16, 16B chunks, swizzled
    auto loadTile = [&](int it, int buf) {
        const __half* ag = Ag + it * GM_BK;
        const __half* bg = Bg + it * GM_BK;
        const uint32_t sa = sAb + buf * 16384;
        const uint32_t sb = sBb + buf * 16384;
        #pragma unroll
        for (int e = tid; e < 1024; e += 256) {
            const int row = e >> 3, ch = e & 7;
            const uint32_t so = 2 * sw_off(row, ch * 8);
            cp16(sa + so, ag + (size_t)row * K + ch * 8);
            cp16(sb + so, bg + (size_t)row * K + ch * 8);
        }
        asm volatile("cp.async.commit_group;" ::: "memory");
    };

    float acc[4][4][4];
    #pragma unroll
    for (int mt = 0; mt < 4; ++mt)
        #pragma unroll
        for (int nb = 0; nb < 4; ++nb)
            #pragma unroll
            for (int r = 0; r < 4; ++r) acc[mt][nb][r] = 0.f;

    const int kIters = K / GM_BK;
    loadTile(0, 0);
    loadTile(1, 1);

    for (int it = 0; it < kIters; ++it) {
        if (it < kIters - 1)
            asm volatile("cp.async.wait_group 1;" ::: "memory");
        else
            asm volatile("cp.async.wait_group 0;" ::: "memory");
        __syncthreads();

        const int buf = it & 1;
        const uint32_t sa = sAb + buf * 16384;
        const uint32_t sb = sBb + buf * 16384;

        #pragma unroll
        for (int k16 = 0; k16 < 4; ++k16) {
            uint32_t af[4][4];
            #pragma unroll
            for (int mt = 0; mt < 4; ++mt)
                ldm_x4(af[mt][0], af[mt][1], af[mt][2], af[mt][3],
                       sa + 2 * sw_off(wm + mt * 16 + lrow, k16 * 16 + lcol8));
            uint32_t bfr[4][2];
            #pragma unroll
            for (int nt = 0; nt < 2; ++nt) {
                uint32_t r0, r1, r2, r3;
                ldm_x4(r0, r1, r2, r3,
                       sb + 2 * sw_off(wn + nt * 16 + lrow, k16 * 16 + lcol8));
                bfr[2 * nt][0] = r0; bfr[2 * nt][1] = r2;
                bfr[2 * nt + 1][0] = r1; bfr[2 * nt + 1][1] = r3;
            }
            #pragma unroll
            for (int mt = 0; mt < 4; ++mt)
                #pragma unroll
                for (int nb = 0; nb < 4; ++nb)
                    mma16816_f16(acc[mt][nb], af[mt], bfr[nb][0], bfr[nb][1]);
        }

        __syncthreads();
        if (it + 2 < kIters)
            loadTile(it + 2, buf);
        else
            asm volatile("cp.async.commit_group;" ::: "memory");
    }

    // epilogue: bias + store (fp32 or fp16)
    #pragma unroll
    for (int mt = 0; mt < 4; ++mt) {
        const int r0 = m0 + wm + mt * 16 + (lane >> 2);
        #pragma unroll
        for (int nb = 0; nb < 4; ++nb) {
            const int cidx = n0 + wn + nb * 8 + (lane & 3) * 2;
            const float b0 = bias[cidx], b1 = bias[cidx + 1];
            if constexpr (sizeof(OutT) == 4) {
                *(float2*)((float*)C + (size_t)r0 * N + cidx) =
                    make_float2(acc[mt][nb][0] + b0, acc[mt][nb][1] + b1);
                *(float2*)((float*)C + (size_t)(r0 + 8) * N + cidx) =
                    make_float2(acc[mt][nb][2] + b0, acc[mt][nb][3] + b1);
            } else {
                *(__half2*)((__half*)C + (size_t)r0 * N + cidx) =
                    __floats2half2_rn(acc[mt][nb][0] + b0, acc[mt][nb][1] + b1);
                *(__half2*)((__half*)C + (size_t)(r0 + 8) * N + cidx) =
                    __floats2half2_rn(acc[mt][nb][2] + b0, acc[mt][nb][3] + b1);
            }
        }
    }
}

// ---------------------------------------------------------------------------
// RoPE + fp16 relayout into [b][h][t][d]; reads fp16 qkv.
// ---------------------------------------------------------------------------
__global__ void rope_cast_kernel(const __half* __restrict__ qkv,
                                 __half* __restrict__ qb,
                                 __half* __restrict__ kb,
                                 __half* __restrict__ vb)
{
    const int total = MROWS * NHEAD * 32;
    int idx = blockIdx.x * blockDim.x + threadIdx.x;
    if (idx >= total) return;
    const int d = idx & 31;
    const int h = (idx >> 5) & (NHEAD - 1);
    const int m = idx >> 9;
    const int t = m & (SEQ - 1);
    const int b = m >> 11;

    const float inv_freq = exp2f((float)d * (-13.2877123795494493f / 32.0f));
    const float ang = (float)t * inv_freq;
    float s, c;
    sincosf(ang, &s, &c);

    const float QS = 0.125f * 1.4426950408889634f;  // 1/sqrt(64) * log2(e)

    const __half* base = qkv + (size_t)m * QKVC + h * HDIM + d;
    const float q1 = __half2float(base[0]);
    const float q2 = __half2float(base[32]);
    const float k1 = __half2float(base[CDIM]);
    const float k2 = __half2float(base[CDIM + 32]);

    const size_t ob = ((size_t)(b * NHEAD + h) * SEQ + t) * HDIM + d;
    qb[ob]      = __float2half((q1 * c - q2 * s) * QS);
    qb[ob + 32] = __float2half((q2 * c + q1 * s) * QS);
    kb[ob]      = __float2half(k1 * c - k2 * s);
    kb[ob + 32] = __float2half(k2 * c + k1 * s);
    vb[ob]      = base[2 * CDIM];
    vb[ob + 32] = base[2 * CDIM + 32];
}

// ---------------------------------------------------------------------------
// fp16 flash attention; epilogue writes plain fp16 into attn [M][CDIM].
// ---------------------------------------------------------------------------
#define FA_BM 128
#define FA_BN 64
#define FA_TILES (SEQ / FA_BN)   // 32

__global__ __launch_bounds__(256) void fa_kernel(
    const __half* __restrict__ Q, const __half* __restrict__ K,
    const __half* __restrict__ V, __half* __restrict__ attn)
{
    const int bh = blockIdx.y;
    const int b  = bh >> 4;
    const int h  = bh & 15;
    const int q0 = blockIdx.x * FA_BM;
    const int tid  = threadIdx.x;
    const int lane = tid & 31;
    const int wid  = tid >> 5;

    __shared__ __half sQ[FA_BM * HDIM];
    __shared__ __half sK[2][FA_BN * HDIM];
    __shared__ __half sV[2][FA_BN * HDIM];

    const __half* qg = Q + ((size_t)bh * SEQ + q0) * HDIM;
    const __half* kg = K + (size_t)bh * SEQ * HDIM;
    const __half* vg = V + (size_t)bh * SEQ * HDIM;

    const uint32_t sQb  = (uint32_t)__cvta_generic_to_shared(sQ);
    const uint32_t sKb0 = (uint32_t)__cvta_generic_to_shared(sK[0]);
    const uint32_t sKb1 = (uint32_t)__cvta_generic_to_shared(sK[1]);
    const uint32_t sVb0 = (uint32_t)__cvta_generic_to_shared(sV[0]);
    const uint32_t sVb1 = (uint32_t)__cvta_generic_to_shared(sV[1]);

    #pragma unroll
    for (int e = tid; e < FA_BM * 8; e += 256) {
        const int row = e >> 3, ch = e & 7;
        *(uint4*)&sQ[sw_off(row, ch * 8)] = *(const uint4*)(qg + row * 64 + ch * 8);
    }

    #pragma unroll
    for (int pt = 0; pt < 2; ++pt) {
        const __half* kt = kg + pt * FA_BN * HDIM;
        const __half* vt = vg + pt * FA_BN * HDIM;
        const uint32_t kb = pt ? sKb1 : sKb0;
        const uint32_t vb = pt ? sVb1 : sVb0;
        #pragma unroll
        for (int e = tid; e < FA_BN * 8; e += 256) {
            const int row = e >> 3, ch = e & 7;
            const uint32_t so = 2 * sw_off(row, ch * 8);
            cp16(kb + so, kt + row * 64 + ch * 8);
            cp16(vb + so, vt + row * 64 + ch * 8);
        }
        asm volatile("cp.async.commit_group;" ::: "memory");
    }

    __syncthreads();

    uint32_t aq[4][4];
    {
        const int qr = wid * 16 + (lane & 15);
        const int qc = (lane >> 4) * 8;
        #pragma unroll
        for (int c4 = 0; c4 < 4; ++c4)
            ldm_x4(aq[c4][0], aq[c4][1], aq[c4][2], aq[c4][3],
                   sQb + 2 * sw_off(qr, c4 * 16 + qc));
    }

    float o[8][4];
    #pragma unroll
    for (int j = 0; j < 8; ++j)
        #pragma unroll
        for (int r = 0; r < 4; ++r) o[j][r] = 0.f;
    float m0 = -1e30f, m1 = -1e30f, l0 = 0.f, l1 = 0.f;

    const int lrow = lane & 15;
    const int lcol8 = (lane >> 4) * 8;

    for (int t = 0; t < FA_TILES; ++t) {
        if (t < FA_TILES - 1)
            asm volatile("cp.async.wait_group 1;" ::: "memory");
        else
            asm volatile("cp.async.wait_group 0;" ::: "memory");
        __syncthreads();

        const uint32_t kb = (t & 1) ? sKb1 : sKb0;
        const uint32_t vb = (t & 1) ? sVb1 : sVb0;

        float c[8][4];
        #pragma unroll
        for (int j = 0; j < 8; ++j)
            #pragma unroll
            for (int r = 0; r < 4; ++r) c[j][r] = 0.f;

        #pragma unroll
        for (int n16 = 0; n16 < 4; ++n16) {
            #pragma unroll
            for (int dc = 0; dc < 4; ++dc) {
                uint32_t r0, r1, r2, r3;
                ldm_x4(r0, r1, r2, r3,
                       kb + 2 * sw_off(n16 * 16 + lrow, dc * 16 + lcol8));
                mma16816_f16(c[2 * n16 + 0], aq[dc], r0, r2);
                mma16816_f16(c[2 * n16 + 1], aq[dc], r1, r3);
            }
        }

        float t0 = -1e30f, t1 = -1e30f;
        #pragma unroll
        for (int j = 0; j < 8; ++j) {
            t0 = fmaxf(t0, fmaxf(c[j][0], c[j][1]));
            t1 = fmaxf(t1, fmaxf(c[j][2], c[j][3]));
        }
        t0 = fmaxf(t0, __shfl_xor_sync(0xffffffffu, t0, 1));
        t0 = fmaxf(t0, __shfl_xor_sync(0xffffffffu, t0, 2));
        t1 = fmaxf(t1, __shfl_xor_sync(0xffffffffu, t1, 1));
        t1 = fmaxf(t1, __shfl_xor_sync(0xffffffffu, t1, 2));

        const float m0n = fmaxf(m0, t0);
        const float m1n = fmaxf(m1, t1);
        const float a0 = ex2f(m0 - m0n);
        const float a1 = ex2f(m1 - m1n);
        m0 = m0n; m1 = m1n;

        float s0 = 0.f, s1 = 0.f;
        uint32_t ap[4][4];
        #pragma unroll
        for (int j = 0; j < 8; ++j) {
            const float p0 = ex2f(c[j][0] - m0);
            const float p1 = ex2f(c[j][1] - m0);
            const float p2 = ex2f(c[j][2] - m1);
            const float p3 = ex2f(c[j][3] - m1);
            s0 += p0 + p1;
            s1 += p2 + p3;
            const int kc = j >> 1, hi = (j & 1) << 1;
            __half2 u = __floats2half2_rn(p0, p1);
            __half2 w = __floats2half2_rn(p2, p3);
            ap[kc][hi + 0] = *(uint32_t*)&u;
            ap[kc][hi + 1] = *(uint32_t*)&w;
        }
        s0 += __shfl_xor_sync(0xffffffffu, s0, 1);
        s0 += __shfl_xor_sync(0xffffffffu, s0, 2);
        s1 += __shfl_xor_sync(0xffffffffu, s1, 1);
        s1 += __shfl_xor_sync(0xffffffffu, s1, 2);
        l0 = l0 * a0 + s0;
        l1 = l1 * a1 + s1;

        #pragma unroll
        for (int j = 0; j < 8; ++j) {
            o[j][0] *= a0; o[j][1] *= a0;
            o[j][2] *= a1; o[j][3] *= a1;
        }

        #pragma unroll
        for (int kc = 0; kc < 4; ++kc) {
            #pragma unroll
            for (int dc = 0; dc < 4; ++dc) {
                uint32_t r0, r1, r2, r3;
                ldm_x4_t(r0, r1, r2, r3,
                         vb + 2 * sw_off(kc * 16 + lrow, dc * 16 + lcol8));
                mma16816_f16(o[2 * dc + 0], ap[kc], r0, r1);
                mma16816_f16(o[2 * dc + 1], ap[kc], r2, r3);
            }
        }

        __syncthreads();

        if (t + 2 < FA_TILES) {
            const __half* kt = kg + (t + 2) * FA_BN * HDIM;
            const __half* vt = vg + (t + 2) * FA_BN * HDIM;
            const uint32_t kbn = (t & 1) ? sKb1 : sKb0;
            const uint32_t vbn = (t & 1) ? sVb1 : sVb0;
            #pragma unroll
            for (int e = tid; e < FA_BN * 8; e += 256) {
                const int row = e >> 3, ch = e & 7;
                const uint32_t so = 2 * sw_off(row, ch * 8);
                cp16(kbn + so, kt + row * 64 + ch * 8);
                cp16(vbn + so, vt + row * 64 + ch * 8);
            }
        }
        asm volatile("cp.async.commit_group;" ::: "memory");
    }

    // epilogue: normalize + plain fp16 store
    const float inv0 = 1.0f / l0;
    const float inv1 = 1.0f / l1;
    const int g = lane >> 2;
    const int cq = (lane & 3) * 2;
    const int row0 = q0 + wid * 16 + g;
    const int row1 = row0 + 8;
    __half* ab0 = attn + (size_t)(b * SEQ + row0) * CDIM + h * HDIM + cq;
    __half* ab1 = attn + (size_t)(b * SEQ + row1) * CDIM + h * HDIM + cq;
    #pragma unroll
    for (int j = 0; j < 8; ++j) {
        *(__half2*)(ab0 + j * 8) = __floats2half2_rn(o[j][0] * inv0, o[j][1] * inv0);
        *(__half2*)(ab1 + j * 8) = __floats2half2_rn(o[j][2] * inv1, o[j][3] * inv1);
    }
}

// ---------------------------------------------------------------------------
// Launch
// ---------------------------------------------------------------------------
extern "C" void kernel_launch(void* const* d_in, const int* in_sizes, int n_in,
                              void* d_out, int out_size)
{
    const float* x    = (const float*)d_in[0];
    const float* Wqkv = (const float*)d_in[1];
    const float* bqkv = (const float*)d_in[2];
    const float* Wout = (const float*)d_in[3];
    const float* bout = (const float*)d_in[4];
    float* out = (float*)d_out;

    __half *qkv = nullptr, *x16 = nullptr, *qb = nullptr, *kb = nullptr, *vb = nullptr;
    __half *attn = nullptr, *W1 = nullptr, *W2 = nullptr;
    cudaGetSymbolAddress((void**)&qkv, g_qkv);
    cudaGetSymbolAddress((void**)&x16, g_x16);
    cudaGetSymbolAddress((void**)&qb, g_qb);
    cudaGetSymbolAddress((void**)&kb, g_kb);
    cudaGetSymbolAddress((void**)&vb, g_vb);
    cudaGetSymbolAddress((void**)&attn, g_attn);
    cudaGetSymbolAddress((void**)&W1,  g_W1);
    cudaGetSymbolAddress((void**)&W2,  g_W2);

    cudaFuncSetAttribute(hgemm_bias_kernel<__half>,
                         cudaFuncAttributeMaxDynamicSharedMemorySize, 65536);
    cudaFuncSetAttribute(hgemm_bias_kernel<float>,
                         cudaFuncAttributeMaxDynamicSharedMemorySize, 65536);

    const int castBlocks = (MROWS * (CDIM / 2) + 255) / 256;

    // 1) cast x -> x16; transpose Wqkv -> W1, Wout -> W2
    cast_act_kernel<<<castBlocks, 256>>>(x, x16);
    wtrans_kernel<<<dim3(QKVC / 32, CDIM / 32), dim3(32, 8)>>>(Wqkv, W1, CDIM, QKVC);
    wtrans_kernel<<<dim3(CDIM / 32, CDIM / 32), dim3(32, 8)>>>(Wout, W2, CDIM, CDIM);

    // 2) qkv = x @ Wqkv + bqkv   (fp16 GEMM, fp16 output)
    hgemm_bias_kernel<__half><<<dim3(QKVC / 128, MROWS / 128), 256, 65536>>>(
        x16, W1, bqkv, qkv, MROWS, QKVC, CDIM);

    // 3) RoPE + [b,h,t,d] relayout (fp16 in/out)
    {
        const int total = MROWS * NHEAD * 32;
        rope_cast_kernel<<<(total + 255) / 256, 256>>>(qkv, qb, kb, vb);
    }

    // 4) flash attention -> attn fp16
    fa_kernel<<<dim3(SEQ / FA_BM, BATCH * NHEAD), 256>>>(qb, kb, vb, attn);

    // 5) out = attn @ Wout + bout   (fp16 GEMM, fp32 output)
    hgemm_bias_kernel<float><<<dim3(CDIM / 128, MROWS / 128), 256, 65536>>>(
        attn, W2, bout, out, MROWS, CDIM, CDIM);
}

// round 9
// speedup vs baseline: 8.7125x; 1.0077x over previous
#include <cuda_runtime.h>
#include <cuda_fp16.h>
#include <cstdint>
#include <cstddef>

// Problem constants (fixed shapes from setup_inputs)
#define BATCH 2
#define SEQ   2048
#define CDIM  1024
#define NHEAD 16
#define HDIM  64
#define MROWS (BATCH * SEQ)          // 4096
#define QKVC  (3 * CDIM)             // 3072

// Scratch (allocation-free rule: __device__ globals)
__device__ __half g_qkv[(size_t)MROWS * QKVC];       // 24 MB fp16 qkv
__device__ __half g_x16[(size_t)MROWS * CDIM];       //  8 MB fp16 cast of x
__device__ __half g_qb[(size_t)MROWS * CDIM];        //  8 MB [b][h][t][d]
__device__ __half g_kb[(size_t)MROWS * CDIM];
__device__ __half g_vb[(size_t)MROWS * CDIM];
__device__ __half g_attn[(size_t)MROWS * CDIM];      //  8 MB attn output fp16
__device__ __half g_W1 [(size_t)QKVC * CDIM];        //  6 MB [N=3072][K=1024] Wqkv^T fp16
__device__ __half g_W2 [(size_t)CDIM * CDIM];        //  2 MB [N=1024][K=1024] Wout^T fp16

// ---------------------------------------------------------------------------
// Common PTX helpers
// ---------------------------------------------------------------------------
__device__ __forceinline__ uint32_t sw_off(int row, int col) {
    // XOR swizzle on 16B chunks within a 64-elt (128B) 16-bit row
    return (uint32_t)(row * 64 + ((((col >> 3) ^ (row & 7)) << 3) | (col & 7)));
}
__device__ __forceinline__ void ldm_x4(uint32_t& r0, uint32_t& r1,
                                       uint32_t& r2, uint32_t& r3, uint32_t a) {
    asm volatile("ldmatrix.sync.aligned.m8n8.x4.shared.b16 {%0,%1,%2,%3}, [%4];"
                 : "=r"(r0), "=r"(r1), "=r"(r2), "=r"(r3) : "r"(a));
}
__device__ __forceinline__ void ldm_x4_t(uint32_t& r0, uint32_t& r1,
                                         uint32_t& r2, uint32_t& r3, uint32_t a) {
    asm volatile("ldmatrix.sync.aligned.m8n8.x4.trans.shared.b16 {%0,%1,%2,%3}, [%4];"
                 : "=r"(r0), "=r"(r1), "=r"(r2), "=r"(r3) : "r"(a));
}
__device__ __forceinline__ void mma16816_f16(float* c, const uint32_t* a,
                                             uint32_t b0, uint32_t b1) {
    asm volatile(
        "mma.sync.aligned.m16n8k16.row.col.f32.f16.f16.f32 "
        "{%0,%1,%2,%3}, {%4,%5,%6,%7}, {%8,%9}, {%0,%1,%2,%3};"
        : "+f"(c[0]), "+f"(c[1]), "+f"(c[2]), "+f"(c[3])
        : "r"(a[0]), "r"(a[1]), "r"(a[2]), "r"(a[3]), "r"(b0), "r"(b1));
}
__device__ __forceinline__ float ex2f(float x) {
    float r;
    asm("ex2.approx.ftz.f32 %0, %1;" : "=f"(r) : "f"(x));
    return r;
}
__device__ __forceinline__ void cp16(uint32_t dst, const void* src) {
    asm volatile("cp.async.cg.shared.global [%0], [%1], 16;" :: "r"(dst), "l"(src));
}

// ---------------------------------------------------------------------------
// Cast activations: in [M][CDIM] fp32 -> out [M][CDIM] fp16
// ---------------------------------------------------------------------------
__global__ void cast_act_kernel(const float* __restrict__ in,
                                __half* __restrict__ out)
{
    const int total = MROWS * (CDIM / 2);
    int idx = blockIdx.x * blockDim.x + threadIdx.x;
    if (idx >= total) return;
    const float2 v = *(const float2*)(in + (size_t)idx * 2);
    __half2 hh;
    hh.x = __float2half_rn(v.x);
    hh.y = __float2half_rn(v.y);
    *(__half2*)(out + (size_t)idx * 2) = hh;
}

// ---------------------------------------------------------------------------
// Transpose weights: W [K][N] fp32 -> Wt [N][K] fp16 (single rounding)
// ---------------------------------------------------------------------------
__global__ void wtrans_kernel(const float* __restrict__ W,
                              __half* __restrict__ Wt, int K, int N)
{
    __shared__ float s[32][33];
    const int k0 = blockIdx.y * 32, n0 = blockIdx.x * 32;
    const int tx = threadIdx.x, ty = threadIdx.y;   // (32, 8)
    #pragma unroll
    for (int i = 0; i < 4; ++i)
        s[ty + i * 8][tx] = W[(size_t)(k0 + ty + i * 8) * N + n0 + tx];
    __syncthreads();
    #pragma unroll
    for (int i = 0; i < 4; ++i) {
        const int n = n0 + ty + i * 8, k = k0 + tx;
        Wt[(size_t)n * K + k] = __float2half_rn(s[tx][ty + i * 8]);
    }
}

// ---------------------------------------------------------------------------
// Tensor-core GEMM (fp16 in, OutT out): C[M][N] = A[M][K] @ Bt[N][K]^T + bias
// 128x128x64 tiles, 3-stage cp.async circular pipeline, ONE sync per k-iter,
// loads issued before compute. 8 warps (2M x 4N), warp 64x32. Dyn smem 96 KB.
// ---------------------------------------------------------------------------
#define GM_BK 64
#define GM_NSTG 3
#define GM_STG_BYTES 32768   // 16KB A + 16KB B

extern __shared__ __half smem_dyn[];

template <typename OutT>
__global__ __launch_bounds__(256) void hgemm_bias_kernel(
    const __half* __restrict__ A,   // [M][K]
    const __half* __restrict__ Bt,  // [N][K]
    const float* __restrict__ bias, OutT* __restrict__ C,
    int M, int N, int K)
{
    const int tid = threadIdx.x, lane = tid & 31, wid = tid >> 5;
    const int m0 = blockIdx.y * 128, n0 = blockIdx.x * 128;
    const int wm = (wid >> 2) * 64, wn = (wid & 3) * 32;
    const int lrow = lane & 15, lcol8 = (lane >> 4) * 8;

    const uint32_t sBase = (uint32_t)__cvta_generic_to_shared(smem_dyn);

    const __half* Ag = A  + (size_t)m0 * K;
    const __half* Bg = Bt + (size_t)n0 * K;

    // tile loader: 128 rows x 64 cols fp16, 16B chunks, swizzled
    auto loadTile = [&](int it, int stg) {
        const __half* ag = Ag + it * GM_BK;
        const __half* bg = Bg + it * GM_BK;
        const uint32_t sa = sBase + stg * GM_STG_BYTES;
        const uint32_t sb = sa + 16384;
        #pragma unroll
        for (int e = tid; e < 1024; e += 256) {
            const int row = e >> 3, ch = e & 7;
            const uint32_t so = 2 * sw_off(row, ch * 8);
            cp16(sa + so, ag + (size_t)row * K + ch * 8);
            cp16(sb + so, bg + (size_t)row * K + ch * 8);
        }
        asm volatile("cp.async.commit_group;" ::: "memory");
    };

    float acc[4][4][4];
    #pragma unroll
    for (int mt = 0; mt < 4; ++mt)
        #pragma unroll
        for (int nb = 0; nb < 4; ++nb)
            #pragma unroll
            for (int r = 0; r < 4; ++r) acc[mt][nb][r] = 0.f;

    const int kIters = K / GM_BK;
    loadTile(0, 0);
    loadTile(1, 1);

    for (int it = 0; it < kIters; ++it) {
        // wait for tile `it` (pending groups: it, it+1 -> keep <=1 pending)
        asm volatile("cp.async.wait_group 1;" ::: "memory");
        __syncthreads();   // also proves all warps finished reading slot (it-1)%3

        // refill the slot freed by tile it-1 with tile it+2, BEFORE compute
        if (it + 2 < kIters) loadTile(it + 2, (it + 2) % GM_NSTG);
        else asm volatile("cp.async.commit_group;" ::: "memory");

        const uint32_t sa = sBase + (it % GM_NSTG) * GM_STG_BYTES;
        const uint32_t sb = sa + 16384;

        #pragma unroll
        for (int k16 = 0; k16 < 4; ++k16) {
            uint32_t af[4][4];
            #pragma unroll
            for (int mt = 0; mt < 4; ++mt)
                ldm_x4(af[mt][0], af[mt][1], af[mt][2], af[mt][3],
                       sa + 2 * sw_off(wm + mt * 16 + lrow, k16 * 16 + lcol8));
            uint32_t bfr[4][2];
            #pragma unroll
            for (int nt = 0; nt < 2; ++nt) {
                uint32_t r0, r1, r2, r3;
                ldm_x4(r0, r1, r2, r3,
                       sb + 2 * sw_off(wn + nt * 16 + lrow, k16 * 16 + lcol8));
                bfr[2 * nt][0] = r0; bfr[2 * nt][1] = r2;
                bfr[2 * nt + 1][0] = r1; bfr[2 * nt + 1][1] = r3;
            }
            #pragma unroll
            for (int mt = 0; mt < 4; ++mt)
                #pragma unroll
                for (int nb = 0; nb < 4; ++nb)
                    mma16816_f16(acc[mt][nb], af[mt], bfr[nb][0], bfr[nb][1]);
        }
    }

    // epilogue: bias + store (fp32 or fp16)
    #pragma unroll
    for (int mt = 0; mt < 4; ++mt) {
        const int r0 = m0 + wm + mt * 16 + (lane >> 2);
        #pragma unroll
        for (int nb = 0; nb < 4; ++nb) {
            const int cidx = n0 + wn + nb * 8 + (lane & 3) * 2;
            const float b0 = bias[cidx], b1 = bias[cidx + 1];
            if constexpr (sizeof(OutT) == 4) {
                *(float2*)((float*)C + (size_t)r0 * N + cidx) =
                    make_float2(acc[mt][nb][0] + b0, acc[mt][nb][1] + b1);
                *(float2*)((float*)C + (size_t)(r0 + 8) * N + cidx) =
                    make_float2(acc[mt][nb][2] + b0, acc[mt][nb][3] + b1);
            } else {
                *(__half2*)((__half*)C + (size_t)r0 * N + cidx) =
                    __floats2half2_rn(acc[mt][nb][0] + b0, acc[mt][nb][1] + b1);
                *(__half2*)((__half*)C + (size_t)(r0 + 8) * N + cidx) =
                    __floats2half2_rn(acc[mt][nb][2] + b0, acc[mt][nb][3] + b1);
            }
        }
    }
}

// ---------------------------------------------------------------------------
// RoPE + fp16 relayout into [b][h][t][d]; reads fp16 qkv.
// ---------------------------------------------------------------------------
__global__ void rope_cast_kernel(const __half* __restrict__ qkv,
                                 __half* __restrict__ qb,
                                 __half* __restrict__ kb,
                                 __half* __restrict__ vb)
{
    const int total = MROWS * NHEAD * 32;
    int idx = blockIdx.x * blockDim.x + threadIdx.x;
    if (idx >= total) return;
    const int d = idx & 31;
    const int h = (idx >> 5) & (NHEAD - 1);
    const int m = idx >> 9;
    const int t = m & (SEQ - 1);
    const int b = m >> 11;

    const float inv_freq = exp2f((float)d * (-13.2877123795494493f / 32.0f));
    const float ang = (float)t * inv_freq;
    float s, c;
    sincosf(ang, &s, &c);

    const float QS = 0.125f * 1.4426950408889634f;  // 1/sqrt(64) * log2(e)

    const __half* base = qkv + (size_t)m * QKVC + h * HDIM + d;
    const float q1 = __half2float(base[0]);
    const float q2 = __half2float(base[32]);
    const float k1 = __half2float(base[CDIM]);
    const float k2 = __half2float(base[CDIM + 32]);

    const size_t ob = ((size_t)(b * NHEAD + h) * SEQ + t) * HDIM + d;
    qb[ob]      = __float2half((q1 * c - q2 * s) * QS);
    qb[ob + 32] = __float2half((q2 * c + q1 * s) * QS);
    kb[ob]      = __float2half(k1 * c - k2 * s);
    kb[ob + 32] = __float2half(k2 * c + k1 * s);
    vb[ob]      = base[2 * CDIM];
    vb[ob + 32] = base[2 * CDIM + 32];
}

// ---------------------------------------------------------------------------
// fp16 flash attention; epilogue writes plain fp16 into attn [M][CDIM].
// ---------------------------------------------------------------------------
#define FA_BM 128
#define FA_BN 64
#define FA_TILES (SEQ / FA_BN)   // 32

__global__ __launch_bounds__(256) void fa_kernel(
    const __half* __restrict__ Q, const __half* __restrict__ K,
    const __half* __restrict__ V, __half* __restrict__ attn)
{
    const int bh = blockIdx.y;
    const int b  = bh >> 4;
    const int h  = bh & 15;
    const int q0 = blockIdx.x * FA_BM;
    const int tid  = threadIdx.x;
    const int lane = tid & 31;
    const int wid  = tid >> 5;

    __shared__ __half sQ[FA_BM * HDIM];
    __shared__ __half sK[2][FA_BN * HDIM];
    __shared__ __half sV[2][FA_BN * HDIM];

    const __half* qg = Q + ((size_t)bh * SEQ + q0) * HDIM;
    const __half* kg = K + (size_t)bh * SEQ * HDIM;
    const __half* vg = V + (size_t)bh * SEQ * HDIM;

    const uint32_t sQb  = (uint32_t)__cvta_generic_to_shared(sQ);
    const uint32_t sKb0 = (uint32_t)__cvta_generic_to_shared(sK[0]);
    const uint32_t sKb1 = (uint32_t)__cvta_generic_to_shared(sK[1]);
    const uint32_t sVb0 = (uint32_t)__cvta_generic_to_shared(sV[0]);
    const uint32_t sVb1 = (uint32_t)__cvta_generic_to_shared(sV[1]);

    #pragma unroll
    for (int e = tid; e < FA_BM * 8; e += 256) {
        const int row = e >> 3, ch = e & 7;
        *(uint4*)&sQ[sw_off(row, ch * 8)] = *(const uint4*)(qg + row * 64 + ch * 8);
    }

    #pragma unroll
    for (int pt = 0; pt < 2; ++pt) {
        const __half* kt = kg + pt * FA_BN * HDIM;
        const __half* vt = vg + pt * FA_BN * HDIM;
        const uint32_t kb = pt ? sKb1 : sKb0;
        const uint32_t vb = pt ? sVb1 : sVb0;
        #pragma unroll
        for (int e = tid; e < FA_BN * 8; e += 256) {
            const int row = e >> 3, ch = e & 7;
            const uint32_t so = 2 * sw_off(row, ch * 8);
            cp16(kb + so, kt + row * 64 + ch * 8);
            cp16(vb + so, vt + row * 64 + ch * 8);
        }
        asm volatile("cp.async.commit_group;" ::: "memory");
    }

    __syncthreads();

    uint32_t aq[4][4];
    {
        const int qr = wid * 16 + (lane & 15);
        const int qc = (lane >> 4) * 8;
        #pragma unroll
        for (int c4 = 0; c4 < 4; ++c4)
            ldm_x4(aq[c4][0], aq[c4][1], aq[c4][2], aq[c4][3],
                   sQb + 2 * sw_off(qr, c4 * 16 + qc));
    }

    float o[8][4];
    #pragma unroll
    for (int j = 0; j < 8; ++j)
        #pragma unroll
        for (int r = 0; r < 4; ++r) o[j][r] = 0.f;
    float m0 = -1e30f, m1 = -1e30f, l0 = 0.f, l1 = 0.f;

    const int lrow = lane & 15;
    const int lcol8 = (lane >> 4) * 8;

    for (int t = 0; t < FA_TILES; ++t) {
        if (t < FA_TILES - 1)
            asm volatile("cp.async.wait_group 1;" ::: "memory");
        else
            asm volatile("cp.async.wait_group 0;" ::: "memory");
        __syncthreads();

        const uint32_t kb = (t & 1) ? sKb1 : sKb0;
        const uint32_t vb = (t & 1) ? sVb1 : sVb0;

        float c[8][4];
        #pragma unroll
        for (int j = 0; j < 8; ++j)
            #pragma unroll
            for (int r = 0; r < 4; ++r) c[j][r] = 0.f;

        #pragma unroll
        for (int n16 = 0; n16 < 4; ++n16) {
            #pragma unroll
            for (int dc = 0; dc < 4; ++dc) {
                uint32_t r0, r1, r2, r3;
                ldm_x4(r0, r1, r2, r3,
                       kb + 2 * sw_off(n16 * 16 + lrow, dc * 16 + lcol8));
                mma16816_f16(c[2 * n16 + 0], aq[dc], r0, r2);
                mma16816_f16(c[2 * n16 + 1], aq[dc], r1, r3);
            }
        }

        float t0 = -1e30f, t1 = -1e30f;
        #pragma unroll
        for (int j = 0; j < 8; ++j) {
            t0 = fmaxf(t0, fmaxf(c[j][0], c[j][1]));
            t1 = fmaxf(t1, fmaxf(c[j][2], c[j][3]));
        }
        t0 = fmaxf(t0, __shfl_xor_sync(0xffffffffu, t0, 1));
        t0 = fmaxf(t0, __shfl_xor_sync(0xffffffffu, t0, 2));
        t1 = fmaxf(t1, __shfl_xor_sync(0xffffffffu, t1, 1));
        t1 = fmaxf(t1, __shfl_xor_sync(0xffffffffu, t1, 2));

        const float m0n = fmaxf(m0, t0);
        const float m1n = fmaxf(m1, t1);
        const float a0 = ex2f(m0 - m0n);
        const float a1 = ex2f(m1 - m1n);
        m0 = m0n; m1 = m1n;

        float s0 = 0.f, s1 = 0.f;
        uint32_t ap[4][4];
        #pragma unroll
        for (int j = 0; j < 8; ++j) {
            const float p0 = ex2f(c[j][0] - m0);
            const float p1 = ex2f(c[j][1] - m0);
            const float p2 = ex2f(c[j][2] - m1);
            const float p3 = ex2f(c[j][3] - m1);
            s0 += p0 + p1;
            s1 += p2 + p3;
            const int kc = j >> 1, hi = (j & 1) << 1;
            __half2 u = __floats2half2_rn(p0, p1);
            __half2 w = __floats2half2_rn(p2, p3);
            ap[kc][hi + 0] = *(uint32_t*)&u;
            ap[kc][hi + 1] = *(uint32_t*)&w;
        }
        s0 += __shfl_xor_sync(0xffffffffu, s0, 1);
        s0 += __shfl_xor_sync(0xffffffffu, s0, 2);
        s1 += __shfl_xor_sync(0xffffffffu, s1, 1);
        s1 += __shfl_xor_sync(0xffffffffu, s1, 2);
        l0 = l0 * a0 + s0;
        l1 = l1 * a1 + s1;

        #pragma unroll
        for (int j = 0; j < 8; ++j) {
            o[j][0] *= a0; o[j][1] *= a0;
            o[j][2] *= a1; o[j][3] *= a1;
        }

        #pragma unroll
        for (int kc = 0; kc < 4; ++kc) {
            #pragma unroll
            for (int dc = 0; dc < 4; ++dc) {
                uint32_t r0, r1, r2, r3;
                ldm_x4_t(r0, r1, r2, r3,
                         vb + 2 * sw_off(kc * 16 + lrow, dc * 16 + lcol8));
                mma16816_f16(o[2 * dc + 0], ap[kc], r0, r1);
                mma16816_f16(o[2 * dc + 1], ap[kc], r2, r3);
            }
        }

        __syncthreads();

        if (t + 2 < FA_TILES) {
            const __half* kt = kg + (t + 2) * FA_BN * HDIM;
            const __half* vt = vg + (t + 2) * FA_BN * HDIM;
            const uint32_t kbn = (t & 1) ? sKb1 : sKb0;
            const uint32_t vbn = (t & 1) ? sVb1 : sVb0;
            #pragma unroll
            for (int e = tid; e < FA_BN * 8; e += 256) {
                const int row = e >> 3, ch = e & 7;
                const uint32_t so = 2 * sw_off(row, ch * 8);
                cp16(kbn + so, kt + row * 64 + ch * 8);
                cp16(vbn + so, vt + row * 64 + ch * 8);
            }
        }
        asm volatile("cp.async.commit_group;" ::: "memory");
    }

    // epilogue: normalize + plain fp16 store
    const float inv0 = 1.0f / l0;
    const float inv1 = 1.0f / l1;
    const int g = lane >> 2;
    const int cq = (lane & 3) * 2;
    const int row0 = q0 + wid * 16 + g;
    const int row1 = row0 + 8;
    __half* ab0 = attn + (size_t)(b * SEQ + row0) * CDIM + h * HDIM + cq;
    __half* ab1 = attn + (size_t)(b * SEQ + row1) * CDIM + h * HDIM + cq;
    #pragma unroll
    for (int j = 0; j < 8; ++j) {
        *(__half2*)(ab0 + j * 8) = __floats2half2_rn(o[j][0] * inv0, o[j][1] * inv0);
        *(__half2*)(ab1 + j * 8) = __floats2half2_rn(o[j][2] * inv1, o[j][3] * inv1);
    }
}

// ---------------------------------------------------------------------------
// Launch
// ---------------------------------------------------------------------------
extern "C" void kernel_launch(void* const* d_in, const int* in_sizes, int n_in,
                              void* d_out, int out_size)
{
    const float* x    = (const float*)d_in[0];
    const float* Wqkv = (const float*)d_in[1];
    const float* bqkv = (const float*)d_in[2];
    const float* Wout = (const float*)d_in[3];
    const float* bout = (const float*)d_in[4];
    float* out = (float*)d_out;

    __half *qkv = nullptr, *x16 = nullptr, *qb = nullptr, *kb = nullptr, *vb = nullptr;
    __half *attn = nullptr, *W1 = nullptr, *W2 = nullptr;
    cudaGetSymbolAddress((void**)&qkv, g_qkv);
    cudaGetSymbolAddress((void**)&x16, g_x16);
    cudaGetSymbolAddress((void**)&qb, g_qb);
    cudaGetSymbolAddress((void**)&kb, g_kb);
    cudaGetSymbolAddress((void**)&vb, g_vb);
    cudaGetSymbolAddress((void**)&attn, g_attn);
    cudaGetSymbolAddress((void**)&W1,  g_W1);
    cudaGetSymbolAddress((void**)&W2,  g_W2);

    const int GEMM_SMEM = GM_NSTG * GM_STG_BYTES;   // 98304
    cudaFuncSetAttribute(hgemm_bias_kernel<__half>,
                         cudaFuncAttributeMaxDynamicSharedMemorySize, GEMM_SMEM);
    cudaFuncSetAttribute(hgemm_bias_kernel<float>,
                         cudaFuncAttributeMaxDynamicSharedMemorySize, GEMM_SMEM);

    const int castBlocks = (MROWS * (CDIM / 2) + 255) / 256;

    // 1) cast x -> x16; transpose Wqkv -> W1, Wout -> W2
    cast_act_kernel<<<castBlocks, 256>>>(x, x16);
    wtrans_kernel<<<dim3(QKVC / 32, CDIM / 32), dim3(32, 8)>>>(Wqkv, W1, CDIM, QKVC);
    wtrans_kernel<<<dim3(CDIM / 32, CDIM / 32), dim3(32, 8)>>>(Wout, W2, CDIM, CDIM);

    // 2) qkv = x @ Wqkv + bqkv   (fp16 GEMM, fp16 output)
    hgemm_bias_kernel<__half><<<dim3(QKVC / 128, MROWS / 128), 256, GEMM_SMEM>>>(
        x16, W1, bqkv, qkv, MROWS, QKVC, CDIM);

    // 3) RoPE + [b,h,t,d] relayout (fp16 in/out)
    {
        const int total = MROWS * NHEAD * 32;
        rope_cast_kernel<<<(total + 255) / 256, 256>>>(qkv, qb, kb, vb);
    }

    // 4) flash attention -> attn fp16
    fa_kernel<<<dim3(SEQ / FA_BM, BATCH * NHEAD), 256>>>(qb, kb, vb, attn);

    // 5) out = attn @ Wout + bout   (fp16 GEMM, fp32 output)
    hgemm_bias_kernel<float><<<dim3(CDIM / 128, MROWS / 128), 256, GEMM_SMEM>>>(
        attn, W2, bout, out, MROWS, CDIM, CDIM);
}

// round 10
// speedup vs baseline: 8.9451x; 1.0267x over previous
#include <cuda_runtime.h>
#include <cuda_fp16.h>
#include <cstdint>
#include <cstddef>

// Problem constants (fixed shapes from setup_inputs)
#define BATCH 2
#define SEQ   2048
#define CDIM  1024
#define NHEAD 16
#define HDIM  64
#define MROWS (BATCH * SEQ)          // 4096
#define QKVC  (3 * CDIM)             // 3072

// Scratch (allocation-free rule: __device__ globals)
__device__ __half g_qkv[(size_t)MROWS * QKVC];       // 24 MB fp16 qkv
__device__ __half g_x16[(size_t)MROWS * CDIM];       //  8 MB fp16 cast of x
__device__ __half g_qb[(size_t)MROWS * CDIM];        //  8 MB [b][h][t][d]
__device__ __half g_kb[(size_t)MROWS * CDIM];
__device__ __half g_vb[(size_t)MROWS * CDIM];
__device__ __half g_attn[(size_t)MROWS * CDIM];      //  8 MB attn output fp16
__device__ __half g_W1 [(size_t)QKVC * CDIM];        //  6 MB [N=3072][K=1024] Wqkv^T fp16
__device__ __half g_W2 [(size_t)CDIM * CDIM];        //  2 MB [N=1024][K=1024] Wout^T fp16

// ---------------------------------------------------------------------------
// Common PTX helpers
// ---------------------------------------------------------------------------
__device__ __forceinline__ uint32_t sw_off(int row, int col) {
    // XOR swizzle on 16B chunks within a 64-elt (128B) 16-bit row
    return (uint32_t)(row * 64 + ((((col >> 3) ^ (row & 7)) << 3) | (col & 7)));
}
__device__ __forceinline__ void ldm_x4(uint32_t& r0, uint32_t& r1,
                                       uint32_t& r2, uint32_t& r3, uint32_t a) {
    asm volatile("ldmatrix.sync.aligned.m8n8.x4.shared.b16 {%0,%1,%2,%3}, [%4];"
                 : "=r"(r0), "=r"(r1), "=r"(r2), "=r"(r3) : "r"(a));
}
__device__ __forceinline__ void ldm_x4_t(uint32_t& r0, uint32_t& r1,
                                         uint32_t& r2, uint32_t& r3, uint32_t a) {
    asm volatile("ldmatrix.sync.aligned.m8n8.x4.trans.shared.b16 {%0,%1,%2,%3}, [%4];"
                 : "=r"(r0), "=r"(r1), "=r"(r2), "=r"(r3) : "r"(a));
}
__device__ __forceinline__ void mma16816_f16(float* c, const uint32_t* a,
                                             uint32_t b0, uint32_t b1) {
    asm volatile(
        "mma.sync.aligned.m16n8k16.row.col.f32.f16.f16.f32 "
        "{%0,%1,%2,%3}, {%4,%5,%6,%7}, {%8,%9}, {%0,%1,%2,%3};"
        : "+f"(c[0]), "+f"(c[1]), "+f"(c[2]), "+f"(c[3])
        : "r"(a[0]), "r"(a[1]), "r"(a[2]), "r"(a[3]), "r"(b0), "r"(b1));
}
__device__ __forceinline__ float ex2f(float x) {
    float r;
    asm("ex2.approx.ftz.f32 %0, %1;" : "=f"(r) : "f"(x));
    return r;
}
__device__ __forceinline__ void cp16(uint32_t dst, const void* src) {
    asm volatile("cp.async.cg.shared.global [%0], [%1], 16;" :: "r"(dst), "l"(src));
}

// ---------------------------------------------------------------------------
// Fused prep: block ranges do (a) x -> fp16 cast, (b) Wqkv transpose+cast,
// (c) Wout transpose+cast. 256 threads flat.
// ---------------------------------------------------------------------------
__device__ __forceinline__ void trans_tile(const float* __restrict__ W,
                                           __half* __restrict__ Wt,
                                           int K, int N, int bx, int by,
                                           int tx, int ty, float (*s)[33])
{
    const int k0 = by * 32, n0 = bx * 32;
    #pragma unroll
    for (int i = 0; i < 4; ++i)
        s[ty + i * 8][tx] = W[(size_t)(k0 + ty + i * 8) * N + n0 + tx];
    __syncthreads();
    #pragma unroll
    for (int i = 0; i < 4; ++i) {
        const int n = n0 + ty + i * 8, k = k0 + tx;
        Wt[(size_t)n * K + k] = __float2half_rn(s[tx][ty + i * 8]);
    }
}

#define PREP_CAST_BLKS  (MROWS * CDIM / 2 / 256)          // 8192
#define PREP_W1_BLKS    ((QKVC / 32) * (CDIM / 32))       // 3072
#define PREP_W2_BLKS    ((CDIM / 32) * (CDIM / 32))       // 1024

__global__ void prep_kernel(const float* __restrict__ x, __half* __restrict__ x16,
                            const float* __restrict__ Wqkv, __half* __restrict__ W1,
                            const float* __restrict__ Wout, __half* __restrict__ W2)
{
    __shared__ float s[32][33];
    const int bid = blockIdx.x;
    const int tid = threadIdx.x;
    if (bid < PREP_CAST_BLKS) {
        const int idx = bid * 256 + tid;
        const float2 v = *(const float2*)(x + (size_t)idx * 2);
        __half2 hh;
        hh.x = __float2half_rn(v.x);
        hh.y = __float2half_rn(v.y);
        *(__half2*)(x16 + (size_t)idx * 2) = hh;
    } else if (bid < PREP_CAST_BLKS + PREP_W1_BLKS) {
        const int j = bid - PREP_CAST_BLKS;
        trans_tile(Wqkv, W1, CDIM, QKVC, j % (QKVC / 32), j / (QKVC / 32),
                   tid & 31, tid >> 5, s);
    } else {
        const int j = bid - PREP_CAST_BLKS - PREP_W1_BLKS;
        trans_tile(Wout, W2, CDIM, CDIM, j % (CDIM / 32), j / (CDIM / 32),
                   tid & 31, tid >> 5, s);
    }
}

// ---------------------------------------------------------------------------
// GEMM1: fp16 in/out, 128x64 tiles, 128 threads (4 warps, 2M x 2N, warp 64x32),
// 3-stage cp.async pipeline + register double-buffered ldmatrix fragments.
// 3 CTAs/SM (72 KB smem, <=170 regs).
// ---------------------------------------------------------------------------
#define GM_BK 64
#define G1_NSTG 3
#define G1_STG_BYTES 24576   // 16 KB A + 8 KB B

extern __shared__ __half smem_dyn[];

__global__ __launch_bounds__(128, 3) void hgemm_n64_kernel(
    const __half* __restrict__ A,   // [M][K]
    const __half* __restrict__ Bt,  // [N][K]
    const float* __restrict__ bias, __half* __restrict__ C,
    int M, int N, int K)
{
    const int tid = threadIdx.x, lane = tid & 31, wid = tid >> 5;
    const int m0 = blockIdx.y * 128, n0 = blockIdx.x * 64;
    const int wm = (wid >> 1) * 64, wn = (wid & 1) * 32;
    const int lrow = lane & 15, lcol8 = (lane >> 4) * 8;

    const uint32_t sBase = (uint32_t)__cvta_generic_to_shared(smem_dyn);

    const __half* Ag = A  + (size_t)m0 * K;
    const __half* Bg = Bt + (size_t)n0 * K;

    auto loadTile = [&](int it, int stg) {
        const __half* ag = Ag + it * GM_BK;
        const __half* bg = Bg + it * GM_BK;
        const uint32_t sa = sBase + stg * G1_STG_BYTES;
        const uint32_t sb = sa + 16384;
        #pragma unroll
        for (int e = tid; e < 1024; e += 128) {         // A: 128 rows x 8 chunks
            const int row = e >> 3, ch = e & 7;
            cp16(sa + 2 * sw_off(row, ch * 8), ag + (size_t)row * K + ch * 8);
        }
        #pragma unroll
        for (int e = tid; e < 512; e += 128) {          // B: 64 rows x 8 chunks
            const int row = e >> 3, ch = e & 7;
            cp16(sb + 2 * sw_off(row, ch * 8), bg + (size_t)row * K + ch * 8);
        }
        asm volatile("cp.async.commit_group;" ::: "memory");
    };

    float acc[4][4][4];
    #pragma unroll
    for (int mt = 0; mt < 4; ++mt)
        #pragma unroll
        for (int nb = 0; nb < 4; ++nb)
            #pragma unroll
            for (int r = 0; r < 4; ++r) acc[mt][nb][r] = 0.f;

    const int kIters = K / GM_BK;
    loadTile(0, 0);
    loadTile(1, 1);

    uint32_t af[2][4][4];   // ping-pong A fragments
    uint32_t bf[2][4][2];   // ping-pong B fragments

    for (int it = 0; it < kIters; ++it) {
        asm volatile("cp.async.wait_group 1;" ::: "memory");
        __syncthreads();

        if (it + 2 < kIters) loadTile(it + 2, (it + 2) % G1_NSTG);
        else asm volatile("cp.async.commit_group;" ::: "memory");

        const uint32_t sa = sBase + (it % G1_NSTG) * G1_STG_BYTES;
        const uint32_t sb = sa + 16384;

        // prologue: fragments for k16 = 0 into buffer 0
        #pragma unroll
        for (int mt = 0; mt < 4; ++mt)
            ldm_x4(af[0][mt][0], af[0][mt][1], af[0][mt][2], af[0][mt][3],
                   sa + 2 * sw_off(wm + mt * 16 + lrow, lcol8));
        #pragma unroll
        for (int nt = 0; nt < 2; ++nt) {
            uint32_t r0, r1, r2, r3;
            ldm_x4(r0, r1, r2, r3, sb + 2 * sw_off(wn + nt * 16 + lrow, lcol8));
            bf[0][2 * nt][0] = r0;     bf[0][2 * nt][1] = r2;
            bf[0][2 * nt + 1][0] = r1; bf[0][2 * nt + 1][1] = r3;
        }

        #pragma unroll
        for (int k16 = 0; k16 < 4; ++k16) {
            const int cur = k16 & 1, nxt = cur ^ 1;
            if (k16 < 3) {   // prefetch next k16's fragments before MMAs
                #pragma unroll
                for (int mt = 0; mt < 4; ++mt)
                    ldm_x4(af[nxt][mt][0], af[nxt][mt][1],
                           af[nxt][mt][2], af[nxt][mt][3],
                           sa + 2 * sw_off(wm + mt * 16 + lrow,
                                           (k16 + 1) * 16 + lcol8));
                #pragma unroll
                for (int nt = 0; nt < 2; ++nt) {
                    uint32_t r0, r1, r2, r3;
                    ldm_x4(r0, r1, r2, r3,
                           sb + 2 * sw_off(wn + nt * 16 + lrow,
                                           (k16 + 1) * 16 + lcol8));
                    bf[nxt][2 * nt][0] = r0;     bf[nxt][2 * nt][1] = r2;
                    bf[nxt][2 * nt + 1][0] = r1; bf[nxt][2 * nt + 1][1] = r3;
                }
            }
            #pragma unroll
            for (int mt = 0; mt < 4; ++mt)
                #pragma unroll
                for (int nb = 0; nb < 4; ++nb)
                    mma16816_f16(acc[mt][nb], af[cur][mt],
                                 bf[cur][nb][0], bf[cur][nb][1]);
        }
    }

    // epilogue: bias + fp16 store
    #pragma unroll
    for (int mt = 0; mt < 4; ++mt) {
        const int r0 = m0 + wm + mt * 16 + (lane >> 2);
        #pragma unroll
        for (int nb = 0; nb < 4; ++nb) {
            const int cidx = n0 + wn + nb * 8 + (lane & 3) * 2;
            const float b0 = bias[cidx], b1 = bias[cidx + 1];
            *(__half2*)(C + (size_t)r0 * N + cidx) =
                __floats2half2_rn(acc[mt][nb][0] + b0, acc[mt][nb][1] + b1);
            *(__half2*)(C + (size_t)(r0 + 8) * N + cidx) =
                __floats2half2_rn(acc[mt][nb][2] + b0, acc[mt][nb][3] + b1);
        }
    }
}

// ---------------------------------------------------------------------------
// GEMM2 (unchanged R9 structure): fp16 in, fp32 out, 128x128x64, 3-stage,
// 256 threads. grid 256 = single wave.
// ---------------------------------------------------------------------------
#define GM_NSTG 3
#define GM_STG_BYTES 32768   // 16KB A + 16KB B

__global__ __launch_bounds__(256) void hgemm_bias_kernel(
    const __half* __restrict__ A,   // [M][K]
    const __half* __restrict__ Bt,  // [N][K]
    const float* __restrict__ bias, float* __restrict__ C,
    int M, int N, int K)
{
    const int tid = threadIdx.x, lane = tid & 31, wid = tid >> 5;
    const int m0 = blockIdx.y * 128, n0 = blockIdx.x * 128;
    const int wm = (wid >> 2) * 64, wn = (wid & 3) * 32;
    const int lrow = lane & 15, lcol8 = (lane >> 4) * 8;

    const uint32_t sBase = (uint32_t)__cvta_generic_to_shared(smem_dyn);

    const __half* Ag = A  + (size_t)m0 * K;
    const __half* Bg = Bt + (size_t)n0 * K;

    auto loadTile = [&](int it, int stg) {
        const __half* ag = Ag + it * GM_BK;
        const __half* bg = Bg + it * GM_BK;
        const uint32_t sa = sBase + stg * GM_STG_BYTES;
        const uint32_t sb = sa + 16384;
        #pragma unroll
        for (int e = tid; e < 1024; e += 256) {
            const int row = e >> 3, ch = e & 7;
            const uint32_t so = 2 * sw_off(row, ch * 8);
            cp16(sa + so, ag + (size_t)row * K + ch * 8);
            cp16(sb + so, bg + (size_t)row * K + ch * 8);
        }
        asm volatile("cp.async.commit_group;" ::: "memory");
    };

    float acc[4][4][4];
    #pragma unroll
    for (int mt = 0; mt < 4; ++mt)
        #pragma unroll
        for (int nb = 0; nb < 4; ++nb)
            #pragma unroll
            for (int r = 0; r < 4; ++r) acc[mt][nb][r] = 0.f;

    const int kIters = K / GM_BK;
    loadTile(0, 0);
    loadTile(1, 1);

    for (int it = 0; it < kIters; ++it) {
        asm volatile("cp.async.wait_group 1;" ::: "memory");
        __syncthreads();

        if (it + 2 < kIters) loadTile(it + 2, (it + 2) % GM_NSTG);
        else asm volatile("cp.async.commit_group;" ::: "memory");

        const uint32_t sa = sBase + (it % GM_NSTG) * GM_STG_BYTES;
        const uint32_t sb = sa + 16384;

        #pragma unroll
        for (int k16 = 0; k16 < 4; ++k16) {
            uint32_t af[4][4];
            #pragma unroll
            for (int mt = 0; mt < 4; ++mt)
                ldm_x4(af[mt][0], af[mt][1], af[mt][2], af[mt][3],
                       sa + 2 * sw_off(wm + mt * 16 + lrow, k16 * 16 + lcol8));
            uint32_t bfr[4][2];
            #pragma unroll
            for (int nt = 0; nt < 2; ++nt) {
                uint32_t r0, r1, r2, r3;
                ldm_x4(r0, r1, r2, r3,
                       sb + 2 * sw_off(wn + nt * 16 + lrow, k16 * 16 + lcol8));
                bfr[2 * nt][0] = r0; bfr[2 * nt][1] = r2;
                bfr[2 * nt + 1][0] = r1; bfr[2 * nt + 1][1] = r3;
            }
            #pragma unroll
            for (int mt = 0; mt < 4; ++mt)
                #pragma unroll
                for (int nb = 0; nb < 4; ++nb)
                    mma16816_f16(acc[mt][nb], af[mt], bfr[nb][0], bfr[nb][1]);
        }
    }

    #pragma unroll
    for (int mt = 0; mt < 4; ++mt) {
        const int r0 = m0 + wm + mt * 16 + (lane >> 2);
        #pragma unroll
        for (int nb = 0; nb < 4; ++nb) {
            const int cidx = n0 + wn + nb * 8 + (lane & 3) * 2;
            const float b0 = bias[cidx], b1 = bias[cidx + 1];
            *(float2*)(C + (size_t)r0 * N + cidx) =
                make_float2(acc[mt][nb][0] + b0, acc[mt][nb][1] + b1);
            *(float2*)(C + (size_t)(r0 + 8) * N + cidx) =
                make_float2(acc[mt][nb][2] + b0, acc[mt][nb][3] + b1);
        }
    }
}

// ---------------------------------------------------------------------------
// RoPE + fp16 relayout into [b][h][t][d]; reads fp16 qkv. (unchanged)
// ---------------------------------------------------------------------------
__global__ void rope_cast_kernel(const __half* __restrict__ qkv,
                                 __half* __restrict__ qb,
                                 __half* __restrict__ kb,
                                 __half* __restrict__ vb)
{
    const int total = MROWS * NHEAD * 32;
    int idx = blockIdx.x * blockDim.x + threadIdx.x;
    if (idx >= total) return;
    const int d = idx & 31;
    const int h = (idx >> 5) & (NHEAD - 1);
    const int m = idx >> 9;
    const int t = m & (SEQ - 1);
    const int b = m >> 11;

    const float inv_freq = exp2f((float)d * (-13.2877123795494493f / 32.0f));
    const float ang = (float)t * inv_freq;
    float s, c;
    sincosf(ang, &s, &c);

    const float QS = 0.125f * 1.4426950408889634f;  // 1/sqrt(64) * log2(e)

    const __half* base = qkv + (size_t)m * QKVC + h * HDIM + d;
    const float q1 = __half2float(base[0]);
    const float q2 = __half2float(base[32]);
    const float k1 = __half2float(base[CDIM]);
    const float k2 = __half2float(base[CDIM + 32]);

    const size_t ob = ((size_t)(b * NHEAD + h) * SEQ + t) * HDIM + d;
    qb[ob]      = __float2half((q1 * c - q2 * s) * QS);
    qb[ob + 32] = __float2half((q2 * c + q1 * s) * QS);
    kb[ob]      = __float2half(k1 * c - k2 * s);
    kb[ob + 32] = __float2half(k2 * c + k1 * s);
    vb[ob]      = base[2 * CDIM];
    vb[ob + 32] = base[2 * CDIM + 32];
}

// ---------------------------------------------------------------------------
// fp16 flash attention (unchanged); epilogue writes fp16 into attn [M][CDIM].
// ---------------------------------------------------------------------------
#define FA_BM 128
#define FA_BN 64
#define FA_TILES (SEQ / FA_BN)   // 32

__global__ __launch_bounds__(256) void fa_kernel(
    const __half* __restrict__ Q, const __half* __restrict__ K,
    const __half* __restrict__ V, __half* __restrict__ attn)
{
    const int bh = blockIdx.y;
    const int b  = bh >> 4;
    const int h  = bh & 15;
    const int q0 = blockIdx.x * FA_BM;
    const int tid  = threadIdx.x;
    const int lane = tid & 31;
    const int wid  = tid >> 5;

    __shared__ __half sQ[FA_BM * HDIM];
    __shared__ __half sK[2][FA_BN * HDIM];
    __shared__ __half sV[2][FA_BN * HDIM];

    const __half* qg = Q + ((size_t)bh * SEQ + q0) * HDIM;
    const __half* kg = K + (size_t)bh * SEQ * HDIM;
    const __half* vg = V + (size_t)bh * SEQ * HDIM;

    const uint32_t sQb  = (uint32_t)__cvta_generic_to_shared(sQ);
    const uint32_t sKb0 = (uint32_t)__cvta_generic_to_shared(sK[0]);
    const uint32_t sKb1 = (uint32_t)__cvta_generic_to_shared(sK[1]);
    const uint32_t sVb0 = (uint32_t)__cvta_generic_to_shared(sV[0]);
    const uint32_t sVb1 = (uint32_t)__cvta_generic_to_shared(sV[1]);

    #pragma unroll
    for (int e = tid; e < FA_BM * 8; e += 256) {
        const int row = e >> 3, ch = e & 7;
        *(uint4*)&sQ[sw_off(row, ch * 8)] = *(const uint4*)(qg + row * 64 + ch * 8);
    }

    #pragma unroll
    for (int pt = 0; pt < 2; ++pt) {
        const __half* kt = kg + pt * FA_BN * HDIM;
        const __half* vt = vg + pt * FA_BN * HDIM;
        const uint32_t kb = pt ? sKb1 : sKb0;
        const uint32_t vb = pt ? sVb1 : sVb0;
        #pragma unroll
        for (int e = tid; e < FA_BN * 8; e += 256) {
            const int row = e >> 3, ch = e & 7;
            const uint32_t so = 2 * sw_off(row, ch * 8);
            cp16(kb + so, kt + row * 64 + ch * 8);
            cp16(vb + so, vt + row * 64 + ch * 8);
        }
        asm volatile("cp.async.commit_group;" ::: "memory");
    }

    __syncthreads();

    uint32_t aq[4][4];
    {
        const int qr = wid * 16 + (lane & 15);
        const int qc = (lane >> 4) * 8;
        #pragma unroll
        for (int c4 = 0; c4 < 4; ++c4)
            ldm_x4(aq[c4][0], aq[c4][1], aq[c4][2], aq[c4][3],
                   sQb + 2 * sw_off(qr, c4 * 16 + qc));
    }

    float o[8][4];
    #pragma unroll
    for (int j = 0; j < 8; ++j)
        #pragma unroll
        for (int r = 0; r < 4; ++r) o[j][r] = 0.f;
    float m0 = -1e30f, m1 = -1e30f, l0 = 0.f, l1 = 0.f;

    const int lrow = lane & 15;
    const int lcol8 = (lane >> 4) * 8;

    for (int t = 0; t < FA_TILES; ++t) {
        if (t < FA_TILES - 1)
            asm volatile("cp.async.wait_group 1;" ::: "memory");
        else
            asm volatile("cp.async.wait_group 0;" ::: "memory");
        __syncthreads();

        const uint32_t kb = (t & 1) ? sKb1 : sKb0;
        const uint32_t vb = (t & 1) ? sVb1 : sVb0;

        float c[8][4];
        #pragma unroll
        for (int j = 0; j < 8; ++j)
            #pragma unroll
            for (int r = 0; r < 4; ++r) c[j][r] = 0.f;

        #pragma unroll
        for (int n16 = 0; n16 < 4; ++n16) {
            #pragma unroll
            for (int dc = 0; dc < 4; ++dc) {
                uint32_t r0, r1, r2, r3;
                ldm_x4(r0, r1, r2, r3,
                       kb + 2 * sw_off(n16 * 16 + lrow, dc * 16 + lcol8));
                mma16816_f16(c[2 * n16 + 0], aq[dc], r0, r2);
                mma16816_f16(c[2 * n16 + 1], aq[dc], r1, r3);
            }
        }

        float t0 = -1e30f, t1 = -1e30f;
        #pragma unroll
        for (int j = 0; j < 8; ++j) {
            t0 = fmaxf(t0, fmaxf(c[j][0], c[j][1]));
            t1 = fmaxf(t1, fmaxf(c[j][2], c[j][3]));
        }
        t0 = fmaxf(t0, __shfl_xor_sync(0xffffffffu, t0, 1));
        t0 = fmaxf(t0, __shfl_xor_sync(0xffffffffu, t0, 2));
        t1 = fmaxf(t1, __shfl_xor_sync(0xffffffffu, t1, 1));
        t1 = fmaxf(t1, __shfl_xor_sync(0xffffffffu, t1, 2));

        const float m0n = fmaxf(m0, t0);
        const float m1n = fmaxf(m1, t1);
        const float a0 = ex2f(m0 - m0n);
        const float a1 = ex2f(m1 - m1n);
        m0 = m0n; m1 = m1n;

        float s0 = 0.f, s1 = 0.f;
        uint32_t ap[4][4];
        #pragma unroll
        for (int j = 0; j < 8; ++j) {
            const float p0 = ex2f(c[j][0] - m0);
            const float p1 = ex2f(c[j][1] - m0);
            const float p2 = ex2f(c[j][2] - m1);
            const float p3 = ex2f(c[j][3] - m1);
            s0 += p0 + p1;
            s1 += p2 + p3;
            const int kc = j >> 1, hi = (j & 1) << 1;
            __half2 u = __floats2half2_rn(p0, p1);
            __half2 w = __floats2half2_rn(p2, p3);
            ap[kc][hi + 0] = *(uint32_t*)&u;
            ap[kc][hi + 1] = *(uint32_t*)&w;
        }
        s0 += __shfl_xor_sync(0xffffffffu, s0, 1);
        s0 += __shfl_xor_sync(0xffffffffu, s0, 2);
        s1 += __shfl_xor_sync(0xffffffffu, s1, 1);
        s1 += __shfl_xor_sync(0xffffffffu, s1, 2);
        l0 = l0 * a0 + s0;
        l1 = l1 * a1 + s1;

        #pragma unroll
        for (int j = 0; j < 8; ++j) {
            o[j][0] *= a0; o[j][1] *= a0;
            o[j][2] *= a1; o[j][3] *= a1;
        }

        #pragma unroll
        for (int kc = 0; kc < 4; ++kc) {
            #pragma unroll
            for (int dc = 0; dc < 4; ++dc) {
                uint32_t r0, r1, r2, r3;
                ldm_x4_t(r0, r1, r2, r3,
                         vb + 2 * sw_off(kc * 16 + lrow, dc * 16 + lcol8));
                mma16816_f16(o[2 * dc + 0], ap[kc], r0, r1);
                mma16816_f16(o[2 * dc + 1], ap[kc], r2, r3);
            }
        }

        __syncthreads();

        if (t + 2 < FA_TILES) {
            const __half* kt = kg + (t + 2) * FA_BN * HDIM;
            const __half* vt = vg + (t + 2) * FA_BN * HDIM;
            const uint32_t kbn = (t & 1) ? sKb1 : sKb0;
            const uint32_t vbn = (t & 1) ? sVb1 : sVb0;
            #pragma unroll
            for (int e = tid; e < FA_BN * 8; e += 256) {
                const int row = e >> 3, ch = e & 7;
                const uint32_t so = 2 * sw_off(row, ch * 8);
                cp16(kbn + so, kt + row * 64 + ch * 8);
                cp16(vbn + so, vt + row * 64 + ch * 8);
            }
        }
        asm volatile("cp.async.commit_group;" ::: "memory");
    }

    const float inv0 = 1.0f / l0;
    const float inv1 = 1.0f / l1;
    const int g = lane >> 2;
    const int cq = (lane & 3) * 2;
    const int row0 = q0 + wid * 16 + g;
    const int row1 = row0 + 8;
    __half* ab0 = attn + (size_t)(b * SEQ + row0) * CDIM + h * HDIM + cq;
    __half* ab1 = attn + (size_t)(b * SEQ + row1) * CDIM + h * HDIM + cq;
    #pragma unroll
    for (int j = 0; j < 8; ++j) {
        *(__half2*)(ab0 + j * 8) = __floats2half2_rn(o[j][0] * inv0, o[j][1] * inv0);
        *(__half2*)(ab1 + j * 8) = __floats2half2_rn(o[j][2] * inv1, o[j][3] * inv1);
    }
}

// ---------------------------------------------------------------------------
// Launch
// ---------------------------------------------------------------------------
extern "C" void kernel_launch(void* const* d_in, const int* in_sizes, int n_in,
                              void* d_out, int out_size)
{
    const float* x    = (const float*)d_in[0];
    const float* Wqkv = (const float*)d_in[1];
    const float* bqkv = (const float*)d_in[2];
    const float* Wout = (const float*)d_in[3];
    const float* bout = (const float*)d_in[4];
    float* out = (float*)d_out;

    __half *qkv = nullptr, *x16 = nullptr, *qb = nullptr, *kb = nullptr, *vb = nullptr;
    __half *attn = nullptr, *W1 = nullptr, *W2 = nullptr;
    cudaGetSymbolAddress((void**)&qkv, g_qkv);
    cudaGetSymbolAddress((void**)&x16, g_x16);
    cudaGetSymbolAddress((void**)&qb, g_qb);
    cudaGetSymbolAddress((void**)&kb, g_kb);
    cudaGetSymbolAddress((void**)&vb, g_vb);
    cudaGetSymbolAddress((void**)&attn, g_attn);
    cudaGetSymbolAddress((void**)&W1,  g_W1);
    cudaGetSymbolAddress((void**)&W2,  g_W2);

    const int G1_SMEM = G1_NSTG * G1_STG_BYTES;     // 73728
    const int G2_SMEM = GM_NSTG * GM_STG_BYTES;     // 98304
    cudaFuncSetAttribute(hgemm_n64_kernel,
                         cudaFuncAttributeMaxDynamicSharedMemorySize, G1_SMEM);
    cudaFuncSetAttribute(hgemm_bias_kernel,
                         cudaFuncAttributeMaxDynamicSharedMemorySize, G2_SMEM);

    // 1) fused prep: cast x -> x16, transpose Wqkv -> W1, Wout -> W2
    prep_kernel<<<PREP_CAST_BLKS + PREP_W1_BLKS + PREP_W2_BLKS, 256>>>(
        x, x16, Wqkv, W1, Wout, W2);

    // 2) qkv = x @ Wqkv + bqkv   (fp16 GEMM, 128x64 tiles, 3 CTA/SM)
    hgemm_n64_kernel<<<dim3(QKVC / 64, MROWS / 128), 128, G1_SMEM>>>(
        x16, W1, bqkv, qkv, MROWS, QKVC, CDIM);

    // 3) RoPE + [b,h,t,d] relayout (fp16 in/out)
    {
        const int total = MROWS * NHEAD * 32;
        rope_cast_kernel<<<(total + 255) / 256, 256>>>(qkv, qb, kb, vb);
    }

    // 4) flash attention -> attn fp16
    fa_kernel<<<dim3(SEQ / FA_BM, BATCH * NHEAD), 256>>>(qb, kb, vb, attn);

    // 5) out = attn @ Wout + bout   (fp16 GEMM, fp32 output, single wave)
    hgemm_bias_kernel<<<dim3(CDIM / 128, MROWS / 128), 256, G2_SMEM>>>(
        attn, W2, bout, out, MROWS, CDIM, CDIM);
}

// round 11
// speedup vs baseline: 8.9836x; 1.0043x over previous
#include <cuda_runtime.h>
#include <cuda_fp16.h>
#include <cstdint>
#include <cstddef>

// Problem constants (fixed shapes from setup_inputs)
#define BATCH 2
#define SEQ   2048
#define CDIM  1024
#define NHEAD 16
#define HDIM  64
#define MROWS (BATCH * SEQ)          // 4096
#define QKVC  (3 * CDIM)             // 3072

// Scratch (allocation-free rule: __device__ globals)
__device__ __half g_qkv[(size_t)MROWS * QKVC];       // 24 MB fp16 qkv
__device__ __half g_x16[(size_t)MROWS * CDIM];       //  8 MB fp16 cast of x
__device__ __half g_qb[(size_t)MROWS * CDIM];        //  8 MB [b][h][t][d]
__device__ __half g_kb[(size_t)MROWS * CDIM];
__device__ __half g_vb[(size_t)MROWS * CDIM];
__device__ __half g_attn[(size_t)MROWS * CDIM];      //  8 MB attn output fp16
__device__ __half g_W1 [(size_t)QKVC * CDIM];        //  6 MB [N=3072][K=1024] Wqkv^T fp16
__device__ __half g_W2 [(size_t)CDIM * CDIM];        //  2 MB [N=1024][K=1024] Wout^T fp16

// ---------------------------------------------------------------------------
// Common PTX helpers
// ---------------------------------------------------------------------------
__device__ __forceinline__ uint32_t sw_off(int row, int col) {
    // XOR swizzle on 16B chunks within a 64-elt (128B) 16-bit row
    return (uint32_t)(row * 64 + ((((col >> 3) ^ (row & 7)) << 3) | (col & 7)));
}
__device__ __forceinline__ void ldm_x4(uint32_t& r0, uint32_t& r1,
                                       uint32_t& r2, uint32_t& r3, uint32_t a) {
    asm volatile("ldmatrix.sync.aligned.m8n8.x4.shared.b16 {%0,%1,%2,%3}, [%4];"
                 : "=r"(r0), "=r"(r1), "=r"(r2), "=r"(r3) : "r"(a));
}
__device__ __forceinline__ void ldm_x4_t(uint32_t& r0, uint32_t& r1,
                                         uint32_t& r2, uint32_t& r3, uint32_t a) {
    asm volatile("ldmatrix.sync.aligned.m8n8.x4.trans.shared.b16 {%0,%1,%2,%3}, [%4];"
                 : "=r"(r0), "=r"(r1), "=r"(r2), "=r"(r3) : "r"(a));
}
__device__ __forceinline__ void mma16816_f16(float* c, const uint32_t* a,
                                             uint32_t b0, uint32_t b1) {
    asm volatile(
        "mma.sync.aligned.m16n8k16.row.col.f32.f16.f16.f32 "
        "{%0,%1,%2,%3}, {%4,%5,%6,%7}, {%8,%9}, {%0,%1,%2,%3};"
        : "+f"(c[0]), "+f"(c[1]), "+f"(c[2]), "+f"(c[3])
        : "r"(a[0]), "r"(a[1]), "r"(a[2]), "r"(a[3]), "r"(b0), "r"(b1));
}
__device__ __forceinline__ float ex2f(float x) {
    float r;
    asm("ex2.approx.ftz.f32 %0, %1;" : "=f"(r) : "f"(x));
    return r;
}
__device__ __forceinline__ void cp16(uint32_t dst, const void* src) {
    asm volatile("cp.async.cg.shared.global [%0], [%1], 16;" :: "r"(dst), "l"(src));
}

// ---------------------------------------------------------------------------
// Fused prep: block ranges do (a) x -> fp16 cast, (b) Wqkv transpose+cast,
// (c) Wout transpose+cast. 256 threads flat.
// ---------------------------------------------------------------------------
__device__ __forceinline__ void trans_tile(const float* __restrict__ W,
                                           __half* __restrict__ Wt,
                                           int K, int N, int bx, int by,
                                           int tx, int ty, float (*s)[33])
{
    const int k0 = by * 32, n0 = bx * 32;
    #pragma unroll
    for (int i = 0; i < 4; ++i)
        s[ty + i * 8][tx] = W[(size_t)(k0 + ty + i * 8) * N + n0 + tx];
    __syncthreads();
    #pragma unroll
    for (int i = 0; i < 4; ++i) {
        const int n = n0 + ty + i * 8, k = k0 + tx;
        Wt[(size_t)n * K + k] = __float2half_rn(s[tx][ty + i * 8]);
    }
}

#define PREP_CAST_BLKS  (MROWS * CDIM / 2 / 256)          // 8192
#define PREP_W1_BLKS    ((QKVC / 32) * (CDIM / 32))       // 3072
#define PREP_W2_BLKS    ((CDIM / 32) * (CDIM / 32))       // 1024

__global__ void prep_kernel(const float* __restrict__ x, __half* __restrict__ x16,
                            const float* __restrict__ Wqkv, __half* __restrict__ W1,
                            const float* __restrict__ Wout, __half* __restrict__ W2)
{
    __shared__ float s[32][33];
    const int bid = blockIdx.x;
    const int tid = threadIdx.x;
    if (bid < PREP_CAST_BLKS) {
        const int idx = bid * 256 + tid;
        const float2 v = *(const float2*)(x + (size_t)idx * 2);
        __half2 hh;
        hh.x = __float2half_rn(v.x);
        hh.y = __float2half_rn(v.y);
        *(__half2*)(x16 + (size_t)idx * 2) = hh;
    } else if (bid < PREP_CAST_BLKS + PREP_W1_BLKS) {
        const int j = bid - PREP_CAST_BLKS;
        trans_tile(Wqkv, W1, CDIM, QKVC, j % (QKVC / 32), j / (QKVC / 32),
                   tid & 31, tid >> 5, s);
    } else {
        const int j = bid - PREP_CAST_BLKS - PREP_W1_BLKS;
        trans_tile(Wout, W2, CDIM, CDIM, j % (CDIM / 32), j / (CDIM / 32),
                   tid & 31, tid >> 5, s);
    }
}

// ---------------------------------------------------------------------------
// GEMM1: fp16 in/out, 128x64 tiles, 128 threads (4 warps, 2M x 2N, warp 64x32),
// 3-stage cp.async pipeline + register double-buffered ldmatrix fragments.
// ---------------------------------------------------------------------------
#define GM_BK 64
#define G1_NSTG 3
#define G1_STG_BYTES 24576   // 16 KB A + 8 KB B

extern __shared__ __half smem_dyn[];

__global__ __launch_bounds__(128, 3) void hgemm_n64_kernel(
    const __half* __restrict__ A,   // [M][K]
    const __half* __restrict__ Bt,  // [N][K]
    const float* __restrict__ bias, __half* __restrict__ C,
    int M, int N, int K)
{
    const int tid = threadIdx.x, lane = tid & 31, wid = tid >> 5;
    const int m0 = blockIdx.y * 128, n0 = blockIdx.x * 64;
    const int wm = (wid >> 1) * 64, wn = (wid & 1) * 32;
    const int lrow = lane & 15, lcol8 = (lane >> 4) * 8;

    const uint32_t sBase = (uint32_t)__cvta_generic_to_shared(smem_dyn);

    const __half* Ag = A  + (size_t)m0 * K;
    const __half* Bg = Bt + (size_t)n0 * K;

    auto loadTile = [&](int it, int stg) {
        const __half* ag = Ag + it * GM_BK;
        const __half* bg = Bg + it * GM_BK;
        const uint32_t sa = sBase + stg * G1_STG_BYTES;
        const uint32_t sb = sa + 16384;
        #pragma unroll
        for (int e = tid; e < 1024; e += 128) {         // A: 128 rows x 8 chunks
            const int row = e >> 3, ch = e & 7;
            cp16(sa + 2 * sw_off(row, ch * 8), ag + (size_t)row * K + ch * 8);
        }
        #pragma unroll
        for (int e = tid; e < 512; e += 128) {          // B: 64 rows x 8 chunks
            const int row = e >> 3, ch = e & 7;
            cp16(sb + 2 * sw_off(row, ch * 8), bg + (size_t)row * K + ch * 8);
        }
        asm volatile("cp.async.commit_group;" ::: "memory");
    };

    float acc[4][4][4];
    #pragma unroll
    for (int mt = 0; mt < 4; ++mt)
        #pragma unroll
        for (int nb = 0; nb < 4; ++nb)
            #pragma unroll
            for (int r = 0; r < 4; ++r) acc[mt][nb][r] = 0.f;

    const int kIters = K / GM_BK;
    loadTile(0, 0);
    loadTile(1, 1);

    uint32_t af[2][4][4];   // ping-pong A fragments
    uint32_t bf[2][4][2];   // ping-pong B fragments

    for (int it = 0; it < kIters; ++it) {
        asm volatile("cp.async.wait_group 1;" ::: "memory");
        __syncthreads();

        if (it + 2 < kIters) loadTile(it + 2, (it + 2) % G1_NSTG);
        else asm volatile("cp.async.commit_group;" ::: "memory");

        const uint32_t sa = sBase + (it % G1_NSTG) * G1_STG_BYTES;
        const uint32_t sb = sa + 16384;

        #pragma unroll
        for (int mt = 0; mt < 4; ++mt)
            ldm_x4(af[0][mt][0], af[0][mt][1], af[0][mt][2], af[0][mt][3],
                   sa + 2 * sw_off(wm + mt * 16 + lrow, lcol8));
        #pragma unroll
        for (int nt = 0; nt < 2; ++nt) {
            uint32_t r0, r1, r2, r3;
            ldm_x4(r0, r1, r2, r3, sb + 2 * sw_off(wn + nt * 16 + lrow, lcol8));
            bf[0][2 * nt][0] = r0;     bf[0][2 * nt][1] = r2;
            bf[0][2 * nt + 1][0] = r1; bf[0][2 * nt + 1][1] = r3;
        }

        #pragma unroll
        for (int k16 = 0; k16 < 4; ++k16) {
            const int cur = k16 & 1, nxt = cur ^ 1;
            if (k16 < 3) {
                #pragma unroll
                for (int mt = 0; mt < 4; ++mt)
                    ldm_x4(af[nxt][mt][0], af[nxt][mt][1],
                           af[nxt][mt][2], af[nxt][mt][3],
                           sa + 2 * sw_off(wm + mt * 16 + lrow,
                                           (k16 + 1) * 16 + lcol8));
                #pragma unroll
                for (int nt = 0; nt < 2; ++nt) {
                    uint32_t r0, r1, r2, r3;
                    ldm_x4(r0, r1, r2, r3,
                           sb + 2 * sw_off(wn + nt * 16 + lrow,
                                           (k16 + 1) * 16 + lcol8));
                    bf[nxt][2 * nt][0] = r0;     bf[nxt][2 * nt][1] = r2;
                    bf[nxt][2 * nt + 1][0] = r1; bf[nxt][2 * nt + 1][1] = r3;
                }
            }
            #pragma unroll
            for (int mt = 0; mt < 4; ++mt)
                #pragma unroll
                for (int nb = 0; nb < 4; ++nb)
                    mma16816_f16(acc[mt][nb], af[cur][mt],
                                 bf[cur][nb][0], bf[cur][nb][1]);
        }
    }

    #pragma unroll
    for (int mt = 0; mt < 4; ++mt) {
        const int r0 = m0 + wm + mt * 16 + (lane >> 2);
        #pragma unroll
        for (int nb = 0; nb < 4; ++nb) {
            const int cidx = n0 + wn + nb * 8 + (lane & 3) * 2;
            const float b0 = bias[cidx], b1 = bias[cidx + 1];
            *(__half2*)(C + (size_t)r0 * N + cidx) =
                __floats2half2_rn(acc[mt][nb][0] + b0, acc[mt][nb][1] + b1);
            *(__half2*)(C + (size_t)(r0 + 8) * N + cidx) =
                __floats2half2_rn(acc[mt][nb][2] + b0, acc[mt][nb][3] + b1);
        }
    }
}

// ---------------------------------------------------------------------------
// GEMM2: fp16 in, fp32 out, 128x128x64, 3-stage, 256 threads.
// ---------------------------------------------------------------------------
#define GM_NSTG 3
#define GM_STG_BYTES 32768   // 16KB A + 16KB B

__global__ __launch_bounds__(256) void hgemm_bias_kernel(
    const __half* __restrict__ A,   // [M][K]
    const __half* __restrict__ Bt,  // [N][K]
    const float* __restrict__ bias, float* __restrict__ C,
    int M, int N, int K)
{
    const int tid = threadIdx.x, lane = tid & 31, wid = tid >> 5;
    const int m0 = blockIdx.y * 128, n0 = blockIdx.x * 128;
    const int wm = (wid >> 2) * 64, wn = (wid & 3) * 32;
    const int lrow = lane & 15, lcol8 = (lane >> 4) * 8;

    const uint32_t sBase = (uint32_t)__cvta_generic_to_shared(smem_dyn);

    const __half* Ag = A  + (size_t)m0 * K;
    const __half* Bg = Bt + (size_t)n0 * K;

    auto loadTile = [&](int it, int stg) {
        const __half* ag = Ag + it * GM_BK;
        const __half* bg = Bg + it * GM_BK;
        const uint32_t sa = sBase + stg * GM_STG_BYTES;
        const uint32_t sb = sa + 16384;
        #pragma unroll
        for (int e = tid; e < 1024; e += 256) {
            const int row = e >> 3, ch = e & 7;
            const uint32_t so = 2 * sw_off(row, ch * 8);
            cp16(sa + so, ag + (size_t)row * K + ch * 8);
            cp16(sb + so, bg + (size_t)row * K + ch * 8);
        }
        asm volatile("cp.async.commit_group;" ::: "memory");
    };

    float acc[4][4][4];
    #pragma unroll
    for (int mt = 0; mt < 4; ++mt)
        #pragma unroll
        for (int nb = 0; nb < 4; ++nb)
            #pragma unroll
            for (int r = 0; r < 4; ++r) acc[mt][nb][r] = 0.f;

    const int kIters = K / GM_BK;
    loadTile(0, 0);
    loadTile(1, 1);

    for (int it = 0; it < kIters; ++it) {
        asm volatile("cp.async.wait_group 1;" ::: "memory");
        __syncthreads();

        if (it + 2 < kIters) loadTile(it + 2, (it + 2) % GM_NSTG);
        else asm volatile("cp.async.commit_group;" ::: "memory");

        const uint32_t sa = sBase + (it % GM_NSTG) * GM_STG_BYTES;
        const uint32_t sb = sa + 16384;

        #pragma unroll
        for (int k16 = 0; k16 < 4; ++k16) {
            uint32_t af[4][4];
            #pragma unroll
            for (int mt = 0; mt < 4; ++mt)
                ldm_x4(af[mt][0], af[mt][1], af[mt][2], af[mt][3],
                       sa + 2 * sw_off(wm + mt * 16 + lrow, k16 * 16 + lcol8));
            uint32_t bfr[4][2];
            #pragma unroll
            for (int nt = 0; nt < 2; ++nt) {
                uint32_t r0, r1, r2, r3;
                ldm_x4(r0, r1, r2, r3,
                       sb + 2 * sw_off(wn + nt * 16 + lrow, k16 * 16 + lcol8));
                bfr[2 * nt][0] = r0; bfr[2 * nt][1] = r2;
                bfr[2 * nt + 1][0] = r1; bfr[2 * nt + 1][1] = r3;
            }
            #pragma unroll
            for (int mt = 0; mt < 4; ++mt)
                #pragma unroll
                for (int nb = 0; nb < 4; ++nb)
                    mma16816_f16(acc[mt][nb], af[mt], bfr[nb][0], bfr[nb][1]);
        }
    }

    #pragma unroll
    for (int mt = 0; mt < 4; ++mt) {
        const int r0 = m0 + wm + mt * 16 + (lane >> 2);
        #pragma unroll
        for (int nb = 0; nb < 4; ++nb) {
            const int cidx = n0 + wn + nb * 8 + (lane & 3) * 2;
            const float b0 = bias[cidx], b1 = bias[cidx + 1];
            *(float2*)(C + (size_t)r0 * N + cidx) =
                make_float2(acc[mt][nb][0] + b0, acc[mt][nb][1] + b1);
            *(float2*)(C + (size_t)(r0 + 8) * N + cidx) =
                make_float2(acc[mt][nb][2] + b0, acc[mt][nb][3] + b1);
        }
    }
}

// ---------------------------------------------------------------------------
// RoPE + fp16 relayout into [b][h][t][d]; reads fp16 qkv. (unchanged)
// ---------------------------------------------------------------------------
__global__ void rope_cast_kernel(const __half* __restrict__ qkv,
                                 __half* __restrict__ qb,
                                 __half* __restrict__ kb,
                                 __half* __restrict__ vb)
{
    const int total = MROWS * NHEAD * 32;
    int idx = blockIdx.x * blockDim.x + threadIdx.x;
    if (idx >= total) return;
    const int d = idx & 31;
    const int h = (idx >> 5) & (NHEAD - 1);
    const int m = idx >> 9;
    const int t = m & (SEQ - 1);
    const int b = m >> 11;

    const float inv_freq = exp2f((float)d * (-13.2877123795494493f / 32.0f));
    const float ang = (float)t * inv_freq;
    float s, c;
    sincosf(ang, &s, &c);

    const float QS = 0.125f * 1.4426950408889634f;  // 1/sqrt(64) * log2(e)

    const __half* base = qkv + (size_t)m * QKVC + h * HDIM + d;
    const float q1 = __half2float(base[0]);
    const float q2 = __half2float(base[32]);
    const float k1 = __half2float(base[CDIM]);
    const float k2 = __half2float(base[CDIM + 32]);

    const size_t ob = ((size_t)(b * NHEAD + h) * SEQ + t) * HDIM + d;
    qb[ob]      = __float2half((q1 * c - q2 * s) * QS);
    qb[ob + 32] = __float2half((q2 * c + q1 * s) * QS);
    kb[ob]      = __float2half(k1 * c - k2 * s);
    kb[ob + 32] = __float2half(k2 * c + k1 * s);
    vb[ob]      = base[2 * CDIM];
    vb[ob + 32] = base[2 * CDIM + 32];
}

// ---------------------------------------------------------------------------
// fp16 flash attention with softmax/PV interleaving (bit-identical math).
// Per key-chunk kc: compute p (ex2+pack) then immediately issue that chunk's
// PV MMAs — MUFU/FMA work overlaps the tensor pipe. s/l shuffle reductions
// deferred until after all PV MMAs (off the critical path).
// ---------------------------------------------------------------------------
#define FA_BM 128
#define FA_BN 64
#define FA_TILES (SEQ / FA_BN)   // 32

__global__ __launch_bounds__(256) void fa_kernel(
    const __half* __restrict__ Q, const __half* __restrict__ K,
    const __half* __restrict__ V, __half* __restrict__ attn)
{
    const int bh = blockIdx.y;
    const int b  = bh >> 4;
    const int h  = bh & 15;
    const int q0 = blockIdx.x * FA_BM;
    const int tid  = threadIdx.x;
    const int lane = tid & 31;
    const int wid  = tid >> 5;

    __shared__ __half sQ[FA_BM * HDIM];
    __shared__ __half sK[2][FA_BN * HDIM];
    __shared__ __half sV[2][FA_BN * HDIM];

    const __half* qg = Q + ((size_t)bh * SEQ + q0) * HDIM;
    const __half* kg = K + (size_t)bh * SEQ * HDIM;
    const __half* vg = V + (size_t)bh * SEQ * HDIM;

    const uint32_t sQb  = (uint32_t)__cvta_generic_to_shared(sQ);
    const uint32_t sKb0 = (uint32_t)__cvta_generic_to_shared(sK[0]);
    const uint32_t sKb1 = (uint32_t)__cvta_generic_to_shared(sK[1]);
    const uint32_t sVb0 = (uint32_t)__cvta_generic_to_shared(sV[0]);
    const uint32_t sVb1 = (uint32_t)__cvta_generic_to_shared(sV[1]);

    #pragma unroll
    for (int e = tid; e < FA_BM * 8; e += 256) {
        const int row = e >> 3, ch = e & 7;
        *(uint4*)&sQ[sw_off(row, ch * 8)] = *(const uint4*)(qg + row * 64 + ch * 8);
    }

    #pragma unroll
    for (int pt = 0; pt < 2; ++pt) {
        const __half* kt = kg + pt * FA_BN * HDIM;
        const __half* vt = vg + pt * FA_BN * HDIM;
        const uint32_t kb = pt ? sKb1 : sKb0;
        const uint32_t vb = pt ? sVb1 : sVb0;
        #pragma unroll
        for (int e = tid; e < FA_BN * 8; e += 256) {
            const int row = e >> 3, ch = e & 7;
            const uint32_t so = 2 * sw_off(row, ch * 8);
            cp16(kb + so, kt + row * 64 + ch * 8);
            cp16(vb + so, vt + row * 64 + ch * 8);
        }
        asm volatile("cp.async.commit_group;" ::: "memory");
    }

    __syncthreads();

    uint32_t aq[4][4];
    {
        const int qr = wid * 16 + (lane & 15);
        const int qc = (lane >> 4) * 8;
        #pragma unroll
        for (int c4 = 0; c4 < 4; ++c4)
            ldm_x4(aq[c4][0], aq[c4][1], aq[c4][2], aq[c4][3],
                   sQb + 2 * sw_off(qr, c4 * 16 + qc));
    }

    float o[8][4];
    #pragma unroll
    for (int j = 0; j < 8; ++j)
        #pragma unroll
        for (int r = 0; r < 4; ++r) o[j][r] = 0.f;
    float m0 = -1e30f, m1 = -1e30f, l0 = 0.f, l1 = 0.f;

    const int lrow = lane & 15;
    const int lcol8 = (lane >> 4) * 8;

    for (int t = 0; t < FA_TILES; ++t) {
        if (t < FA_TILES - 1)
            asm volatile("cp.async.wait_group 1;" ::: "memory");
        else
            asm volatile("cp.async.wait_group 0;" ::: "memory");
        __syncthreads();

        const uint32_t kb = (t & 1) ? sKb1 : sKb0;
        const uint32_t vb = (t & 1) ? sVb1 : sVb0;

        // ---- S = Q K^T ----
        float c[8][4];
        #pragma unroll
        for (int j = 0; j < 8; ++j)
            #pragma unroll
            for (int r = 0; r < 4; ++r) c[j][r] = 0.f;

        #pragma unroll
        for (int n16 = 0; n16 < 4; ++n16) {
            #pragma unroll
            for (int dc = 0; dc < 4; ++dc) {
                uint32_t r0, r1, r2, r3;
                ldm_x4(r0, r1, r2, r3,
                       kb + 2 * sw_off(n16 * 16 + lrow, dc * 16 + lcol8));
                mma16816_f16(c[2 * n16 + 0], aq[dc], r0, r2);
                mma16816_f16(c[2 * n16 + 1], aq[dc], r1, r3);
            }
        }

        // ---- running max + rescale factors (serial, unavoidable) ----
        float t0 = -1e30f, t1 = -1e30f;
        #pragma unroll
        for (int j = 0; j < 8; ++j) {
            t0 = fmaxf(t0, fmaxf(c[j][0], c[j][1]));
            t1 = fmaxf(t1, fmaxf(c[j][2], c[j][3]));
        }
        t0 = fmaxf(t0, __shfl_xor_sync(0xffffffffu, t0, 1));
        t0 = fmaxf(t0, __shfl_xor_sync(0xffffffffu, t0, 2));
        t1 = fmaxf(t1, __shfl_xor_sync(0xffffffffu, t1, 1));
        t1 = fmaxf(t1, __shfl_xor_sync(0xffffffffu, t1, 2));

        const float m0n = fmaxf(m0, t0);
        const float m1n = fmaxf(m1, t1);
        const float a0 = ex2f(m0 - m0n);
        const float a1 = ex2f(m1 - m1n);
        m0 = m0n; m1 = m1n;

        #pragma unroll
        for (int j = 0; j < 8; ++j) {
            o[j][0] *= a0; o[j][1] *= a0;
            o[j][2] *= a1; o[j][3] *= a1;
        }

        // ---- interleaved: per key-chunk, compute p then issue PV MMAs ----
        float s0 = 0.f, s1 = 0.f;
        #pragma unroll
        for (int kc = 0; kc < 4; ++kc) {
            uint32_t ap[4];
            #pragma unroll
            for (int jj = 0; jj < 2; ++jj) {
                const int j = 2 * kc + jj;
                const float p0 = ex2f(c[j][0] - m0);
                const float p1 = ex2f(c[j][1] - m0);
                const float p2 = ex2f(c[j][2] - m1);
                const float p3 = ex2f(c[j][3] - m1);
                s0 += p0 + p1;
                s1 += p2 + p3;
                __half2 u = __floats2half2_rn(p0, p1);
                __half2 w = __floats2half2_rn(p2, p3);
                ap[2 * jj + 0] = *(uint32_t*)&u;
                ap[2 * jj + 1] = *(uint32_t*)&w;
            }
            #pragma unroll
            for (int dc = 0; dc < 4; ++dc) {
                uint32_t r0, r1, r2, r3;
                ldm_x4_t(r0, r1, r2, r3,
                         vb + 2 * sw_off(kc * 16 + lrow, dc * 16 + lcol8));
                mma16816_f16(o[2 * dc + 0], ap, r0, r1);
                mma16816_f16(o[2 * dc + 1], ap, r2, r3);
            }
        }

        // ---- deferred l reduction (off the PV critical path) ----
        s0 += __shfl_xor_sync(0xffffffffu, s0, 1);
        s0 += __shfl_xor_sync(0xffffffffu, s0, 2);
        s1 += __shfl_xor_sync(0xffffffffu, s1, 1);
        s1 += __shfl_xor_sync(0xffffffffu, s1, 2);
        l0 = l0 * a0 + s0;
        l1 = l1 * a1 + s1;

        __syncthreads();

        if (t + 2 < FA_TILES) {
            const __half* kt = kg + (t + 2) * FA_BN * HDIM;
            const __half* vt = vg + (t + 2) * FA_BN * HDIM;
            const uint32_t kbn = (t & 1) ? sKb1 : sKb0;
            const uint32_t vbn = (t & 1) ? sVb1 : sVb0;
            #pragma unroll
            for (int e = tid; e < FA_BN * 8; e += 256) {
                const int row = e >> 3, ch = e & 7;
                const uint32_t so = 2 * sw_off(row, ch * 8);
                cp16(kbn + so, kt + row * 64 + ch * 8);
                cp16(vbn + so, vt + row * 64 + ch * 8);
            }
        }
        asm volatile("cp.async.commit_group;" ::: "memory");
    }

    const float inv0 = 1.0f / l0;
    const float inv1 = 1.0f / l1;
    const int g = lane >> 2;
    const int cq = (lane & 3) * 2;
    const int row0 = q0 + wid * 16 + g;
    const int row1 = row0 + 8;
    __half* ab0 = attn + (size_t)(b * SEQ + row0) * CDIM + h * HDIM + cq;
    __half* ab1 = attn + (size_t)(b * SEQ + row1) * CDIM + h * HDIM + cq;
    #pragma unroll
    for (int j = 0; j < 8; ++j) {
        *(__half2*)(ab0 + j * 8) = __floats2half2_rn(o[j][0] * inv0, o[j][1] * inv0);
        *(__half2*)(ab1 + j * 8) = __floats2half2_rn(o[j][2] * inv1, o[j][3] * inv1);
    }
}

// ---------------------------------------------------------------------------
// Launch
// ---------------------------------------------------------------------------
extern "C" void kernel_launch(void* const* d_in, const int* in_sizes, int n_in,
                              void* d_out, int out_size)
{
    const float* x    = (const float*)d_in[0];
    const float* Wqkv = (const float*)d_in[1];
    const float* bqkv = (const float*)d_in[2];
    const float* Wout = (const float*)d_in[3];
    const float* bout = (const float*)d_in[4];
    float* out = (float*)d_out;

    __half *qkv = nullptr, *x16 = nullptr, *qb = nullptr, *kb = nullptr, *vb = nullptr;
    __half *attn = nullptr, *W1 = nullptr, *W2 = nullptr;
    cudaGetSymbolAddress((void**)&qkv, g_qkv);
    cudaGetSymbolAddress((void**)&x16, g_x16);
    cudaGetSymbolAddress((void**)&qb, g_qb);
    cudaGetSymbolAddress((void**)&kb, g_kb);
    cudaGetSymbolAddress((void**)&vb, g_vb);
    cudaGetSymbolAddress((void**)&attn, g_attn);
    cudaGetSymbolAddress((void**)&W1,  g_W1);
    cudaGetSymbolAddress((void**)&W2,  g_W2);

    const int G1_SMEM = G1_NSTG * G1_STG_BYTES;     // 73728
    const int G2_SMEM = GM_NSTG * GM_STG_BYTES;     // 98304
    cudaFuncSetAttribute(hgemm_n64_kernel,
                         cudaFuncAttributeMaxDynamicSharedMemorySize, G1_SMEM);
    cudaFuncSetAttribute(hgemm_bias_kernel,
                         cudaFuncAttributeMaxDynamicSharedMemorySize, G2_SMEM);

    // 1) fused prep: cast x -> x16, transpose Wqkv -> W1, Wout -> W2
    prep_kernel<<<PREP_CAST_BLKS + PREP_W1_BLKS + PREP_W2_BLKS, 256>>>(
        x, x16, Wqkv, W1, Wout, W2);

    // 2) qkv = x @ Wqkv + bqkv
    hgemm_n64_kernel<<<dim3(QKVC / 64, MROWS / 128), 128, G1_SMEM>>>(
        x16, W1, bqkv, qkv, MROWS, QKVC, CDIM);

    // 3) RoPE + [b,h,t,d] relayout
    {
        const int total = MROWS * NHEAD * 32;
        rope_cast_kernel<<<(total + 255) / 256, 256>>>(qkv, qb, kb, vb);
    }

    // 4) flash attention -> attn fp16
    fa_kernel<<<dim3(SEQ / FA_BM, BATCH * NHEAD), 256>>>(qb, kb, vb, attn);

    // 5) out = attn @ Wout + bout
    hgemm_bias_kernel<<<dim3(CDIM / 128, MROWS / 128), 256, G2_SMEM>>>(
        attn, W2, bout, out, MROWS, CDIM, CDIM);
}